// round 4
// baseline (speedup 1.0000x reference)
#include <cuda_runtime.h>
#include <cuda_fp16.h>
#include <cstdint>

#define SEQ   8192
#define NN    1024
#define DD    64
#define QSZ   256
#define BOT   40
#define INNER 512
#define NTILES 128   // SEQ / 64

// ------------------------- scratch (no allocs allowed) -----------------------
__device__ __half g_q[(size_t)4 * SEQ * DD];    // [b][s][d], pre-scaled by 0.125*log2e
__device__ __half g_k[(size_t)4 * SEQ * DD];    // [b][s][d]
__device__ __half g_vt[(size_t)4 * DD * SEQ];   // [b][d][s]  (V transposed)
__device__ float  g_attn[(size_t)4096 * INNER]; // [b*1024+n][h*64+d]

__device__ __forceinline__ float ex2f(float x) {
    float y;
    asm("ex2.approx.ftz.f32 %0, %1;" : "=f"(y) : "f"(x));
    return y;
}

__device__ __forceinline__ unsigned ex2h2(float a, float b) {
    __half2 h = __floats2half2_rn(a, b);
    unsigned u = *reinterpret_cast<unsigned*>(&h);
    unsigned r;
    asm("ex2.approx.f16x2 %0, %1;" : "=r"(r) : "r"(u));
    return r;
}

__device__ __forceinline__ void mma16816(float (&c)[4], const unsigned (&a)[4],
                                         unsigned b0, unsigned b1) {
    asm volatile(
        "mma.sync.aligned.m16n8k16.row.col.f32.f16.f16.f32 "
        "{%0,%1,%2,%3}, {%4,%5,%6,%7}, {%8,%9}, {%0,%1,%2,%3};\n"
        : "+f"(c[0]), "+f"(c[1]), "+f"(c[2]), "+f"(c[3])
        : "r"(a[0]), "r"(a[1]), "r"(a[2]), "r"(a[3]), "r"(b0), "r"(b1));
}

__device__ __forceinline__ void cp16(void* s, const void* g) {
    unsigned sa = (unsigned)__cvta_generic_to_shared(s);
    asm volatile("cp.async.cg.shared.global [%0], [%1], 16;\n" :: "r"(sa), "l"(g));
}

__device__ __forceinline__ void ldsm_x4(unsigned& r0, unsigned& r1, unsigned& r2,
                                        unsigned& r3, const void* p) {
    unsigned a = (unsigned)__cvta_generic_to_shared(p);
    asm volatile("ldmatrix.sync.aligned.m8n8.x4.shared.b16 {%0,%1,%2,%3}, [%4];"
                 : "=r"(r0), "=r"(r1), "=r"(r2), "=r"(r3) : "r"(a));
}

// ---------------------------------------------------------------------------
// Fused bottleneck projection v2: 64 rows/block, grid (64, 3)
// ---------------------------------------------------------------------------
__global__ __launch_bounds__(256) void proj_kernel(
    const float* __restrict__ x,
    const float* __restrict__ wq1, const float* __restrict__ wq2,
    const float* __restrict__ wk1, const float* __restrict__ wk2,
    const float* __restrict__ wv1, const float* __restrict__ wv2) {
    __shared__ float sW[QSZ * BOT];   // phase A: w1 (256x40); phase B: w2 chunk (40x128)
    __shared__ float sB[64 * 44];     // bottleneck tile (padded)

    const int proj = blockIdx.y;
    const float* w1 = (proj == 0) ? wq1 : (proj == 1 ? wk1 : wv1);
    const float* w2 = (proj == 0) ? wq2 : (proj == 1 ? wk2 : wv2);
    const int row0 = blockIdx.x * 64;
    const int tid = threadIdx.x;

#pragma unroll
    for (int i = 0; i < 40; i++) sW[tid + i * 256] = w1[tid + i * 256];
    __syncthreads();

    // ---- Phase A: bottleneck = x @ w1 (+ silu for k); 2 rows x 5 cols/thread ----
    {
        const int rp = tid >> 3;      // row pair [0,32)
        const int tc = tid & 7;       // col thread [0,8)
        const float4* xr0 = reinterpret_cast<const float4*>(x + (size_t)(row0 + rp * 2) * QSZ);
        const float4* xr1 = reinterpret_cast<const float4*>(x + (size_t)(row0 + rp * 2 + 1) * QSZ);
        float acc[2][5];
#pragma unroll
        for (int r = 0; r < 2; r++)
#pragma unroll
            for (int i = 0; i < 5; i++) acc[r][i] = 0.f;
#pragma unroll 4
        for (int k4 = 0; k4 < 64; k4++) {
            float4 a0 = xr0[k4];
            float4 a1 = xr1[k4];
            float x0[4] = {a0.x, a0.y, a0.z, a0.w};
            float x1[4] = {a1.x, a1.y, a1.z, a1.w};
            const float* wp = sW + k4 * 4 * BOT + tc;
#pragma unroll
            for (int kk = 0; kk < 4; kk++)
#pragma unroll
                for (int i = 0; i < 5; i++) {
                    float wv = wp[kk * BOT + i * 8];
                    acc[0][i] += x0[kk] * wv;
                    acc[1][i] += x1[kk] * wv;
                }
        }
#pragma unroll
        for (int r = 0; r < 2; r++)
#pragma unroll
            for (int i = 0; i < 5; i++) {
                float v = acc[r][i];
                if (proj == 1) v = v / (1.0f + __expf(-v));
                sB[(rp * 2 + r) * 44 + tc + 8 * i] = v;
            }
    }
    __syncthreads();

    // ---- Phase B: out = bottleneck @ w2, 4 chunks of 128 cols; 8 rows x 4 cols ----
    const int rg = tid >> 5;          // row group [0,8) -> rows rg*8..+7
    const int cg = tid & 31;          // col group -> cols cg*4

    for (int ch = 0; ch < 4; ch++) {
        if (ch) __syncthreads();
#pragma unroll
        for (int i = 0; i < 5; i++) {
            int task = tid + i * 256;  // 1280 float4 loads (40x128 floats)
            int kk = task >> 5;
            int c4 = (task & 31) * 4;
            *reinterpret_cast<float4*>(sW + kk * 128 + c4) =
                *reinterpret_cast<const float4*>(w2 + (size_t)kk * INNER + ch * 128 + c4);
        }
        __syncthreads();

        float acc[8][4];
#pragma unroll
        for (int r = 0; r < 8; r++)
#pragma unroll
            for (int j = 0; j < 4; j++) acc[r][j] = 0.f;

#pragma unroll
        for (int k = 0; k < BOT; k++) {
            float4 wv = *reinterpret_cast<const float4*>(sW + k * 128 + cg * 4);
#pragma unroll
            for (int r = 0; r < 8; r++) {
                float bv = sB[(rg * 8 + r) * 44 + k];
                acc[r][0] += bv * wv.x;
                acc[r][1] += bv * wv.y;
                acc[r][2] += bv * wv.z;
                acc[r][3] += bv * wv.w;
            }
        }

        const int col = ch * 128 + cg * 4;
        const int h = col >> 6, d = col & 63;
#pragma unroll
        for (int r = 0; r < 8; r++) {
            int grow = row0 + rg * 8 + r;
            int bidx = grow >> 10, nidx = grow & 1023;
            if (proj == 0) {
                const float s = 0.125f * 1.4426950408889634f;  // d^-0.5 * log2(e)
                __half2* dst = reinterpret_cast<__half2*>(
                    g_q + ((size_t)bidx * SEQ + h * NN + nidx) * DD + d);
                dst[0] = __floats2half2_rn(acc[r][0] * s, acc[r][1] * s);
                dst[1] = __floats2half2_rn(acc[r][2] * s, acc[r][3] * s);
            } else if (proj == 1) {
                __half2* dst = reinterpret_cast<__half2*>(
                    g_k + ((size_t)bidx * SEQ + h * NN + nidx) * DD + d);
                dst[0] = __floats2half2_rn(acc[r][0], acc[r][1]);
                dst[1] = __floats2half2_rn(acc[r][2], acc[r][3]);
            } else {
                size_t base = ((size_t)bidx * DD + d) * SEQ + h * NN + nidx;
                g_vt[base]           = __float2half_rn(acc[r][0]);
                g_vt[base + SEQ]     = __float2half_rn(acc[r][1]);
                g_vt[base + 2 * SEQ] = __float2half_rn(acc[r][2]);
                g_vt[base + 3 * SEQ] = __float2half_rn(acc[r][3]);
            }
        }
    }
}

// ---------------------------------------------------------------------------
// Flash attention: seq 8192, d=64, Br=128 (4 warps x 32 rows), Bc=64.
// ldmatrix fragment loads, f16x2 exp2 softmax, branch-skipped rescale.
// ---------------------------------------------------------------------------
__global__ __launch_bounds__(128) void attn_kernel() {
    __shared__ __half sK[2][64 * 72];
    __shared__ __half sV[2][64 * 72];

    const int b = blockIdx.y;
    const int row0 = blockIdx.x * 128;
    const int tid = threadIdx.x;
    const int warp = tid >> 5, lane = tid & 31;
    const int gi = lane >> 2, tig = lane & 3;
    const int l8 = lane & 7, mrow = lane >> 3;

    const __half* kbase = g_k + (size_t)b * SEQ * DD;
    const __half* vbase = g_vt + (size_t)b * DD * SEQ;

    // prologue: load tile 0 into buf 0
    {
#pragma unroll
        for (int i = 0; i < 4; i++) {
            int t = tid + i * 128;
            int row = t >> 3, seg = t & 7;
            cp16(&sK[0][row * 72 + seg * 8], kbase + (size_t)row * DD + seg * 8);
            cp16(&sV[0][row * 72 + seg * 8], vbase + (size_t)row * SEQ + seg * 8);
        }
        asm volatile("cp.async.commit_group;\n");
    }

    // Q fragments straight from gmem (mma A layout)
    unsigned qf[2][4][4];
    const __half* qb = g_q + ((size_t)b * SEQ + row0 + warp * 32) * DD;
#pragma unroll
    for (int rb = 0; rb < 2; rb++)
#pragma unroll
        for (int kc = 0; kc < 4; kc++) {
            int rr = rb * 16 + gi;
            int cc = kc * 16 + tig * 2;
            qf[rb][kc][0] = *reinterpret_cast<const unsigned*>(qb + rr * DD + cc);
            qf[rb][kc][1] = *reinterpret_cast<const unsigned*>(qb + (rr + 8) * DD + cc);
            qf[rb][kc][2] = *reinterpret_cast<const unsigned*>(qb + rr * DD + cc + 8);
            qf[rb][kc][3] = *reinterpret_cast<const unsigned*>(qb + (rr + 8) * DD + cc + 8);
        }

    float O[2][8][4];
#pragma unroll
    for (int rb = 0; rb < 2; rb++)
#pragma unroll
        for (int dt = 0; dt < 8; dt++)
#pragma unroll
            for (int q = 0; q < 4; q++) O[rb][dt][q] = 0.f;

    float m[2][2] = {{-1e30f, -1e30f}, {-1e30f, -1e30f}};
    float l[2][2] = {{0.f, 0.f}, {0.f, 0.f}};

    int buf = 0;
    for (int jt = 0; jt < NTILES; jt++) {
        if (jt + 1 < NTILES) {
            const __half* kp = kbase + (size_t)(jt + 1) * 64 * DD;
            const __half* vp = vbase + (jt + 1) * 64;
#pragma unroll
            for (int i = 0; i < 4; i++) {
                int t = tid + i * 128;
                int row = t >> 3, seg = t & 7;
                cp16(&sK[buf ^ 1][row * 72 + seg * 8], kp + (size_t)row * DD + seg * 8);
                cp16(&sV[buf ^ 1][row * 72 + seg * 8], vp + (size_t)row * SEQ + seg * 8);
            }
            asm volatile("cp.async.commit_group;\n");
            asm volatile("cp.async.wait_group 1;\n");
        } else {
            asm volatile("cp.async.wait_group 0;\n");
        }
        __syncthreads();

        // ---- S = Q @ K^T (ldmatrix B-fragments) ----
        float S[2][8][4];
#pragma unroll
        for (int rb = 0; rb < 2; rb++)
#pragma unroll
            for (int nt = 0; nt < 8; nt++)
#pragma unroll
                for (int q = 0; q < 4; q++) S[rb][nt][q] = 0.f;

#pragma unroll
        for (int nt = 0; nt < 8; nt++) {
            unsigned kb0[4], kb1[4];
            const __half* ka = &sK[buf][(nt * 8 + l8) * 72 + mrow * 8];
            ldsm_x4(kb0[0], kb1[0], kb0[1], kb1[1], ka);
            ldsm_x4(kb0[2], kb1[2], kb0[3], kb1[3], ka + 32);
#pragma unroll
            for (int rb = 0; rb < 2; rb++)
#pragma unroll
                for (int kc = 0; kc < 4; kc++)
                    mma16816(S[rb][nt], qf[rb][kc], kb0[kc], kb1[kc]);
        }

        // ---- online softmax (log2 domain) ----
        unsigned pa[2][4][4];
#pragma unroll
        for (int rb = 0; rb < 2; rb++) {
#pragma unroll
            for (int h2 = 0; h2 < 2; h2++) {
                float tm = -1e30f;
#pragma unroll
                for (int nt = 0; nt < 8; nt++)
                    tm = fmaxf(tm, fmaxf(S[rb][nt][2 * h2], S[rb][nt][2 * h2 + 1]));
                tm = fmaxf(tm, __shfl_xor_sync(0xffffffffu, tm, 1));
                tm = fmaxf(tm, __shfl_xor_sync(0xffffffffu, tm, 2));
                if (tm > m[rb][h2]) {
                    float al = ex2f(m[rb][h2] - tm);
                    m[rb][h2] = tm;
                    l[rb][h2] *= al;
#pragma unroll
                    for (int dt = 0; dt < 8; dt++) {
                        O[rb][dt][2 * h2]     *= al;
                        O[rb][dt][2 * h2 + 1] *= al;
                    }
                }
            }
            __half2 ls0 = __floats2half2_rn(0.f, 0.f);
            __half2 ls1 = ls0;
            float m0 = m[rb][0], m1 = m[rb][1];
#pragma unroll
            for (int nt = 0; nt < 8; nt++) {
                unsigned p01 = ex2h2(S[rb][nt][0] - m0, S[rb][nt][1] - m0);
                unsigned p23 = ex2h2(S[rb][nt][2] - m1, S[rb][nt][3] - m1);
                ls0 = __hadd2(ls0, *reinterpret_cast<__half2*>(&p01));
                ls1 = __hadd2(ls1, *reinterpret_cast<__half2*>(&p23));
                pa[rb][nt >> 1][(nt & 1) * 2]     = p01;
                pa[rb][nt >> 1][(nt & 1) * 2 + 1] = p23;
            }
            float2 f0 = __half22float2(ls0);
            float2 f1 = __half22float2(ls1);
            l[rb][0] += f0.x + f0.y;
            l[rb][1] += f1.x + f1.y;
        }

        // ---- O += P @ V (ldmatrix B-fragments from transposed V) ----
#pragma unroll
        for (int dt = 0; dt < 8; dt++) {
            unsigned vb0[4], vb1[4];
            const __half* va = &sV[buf][(dt * 8 + l8) * 72 + mrow * 8];
            ldsm_x4(vb0[0], vb1[0], vb0[1], vb1[1], va);
            ldsm_x4(vb0[2], vb1[2], vb0[3], vb1[3], va + 32);
#pragma unroll
            for (int rb = 0; rb < 2; rb++)
#pragma unroll
                for (int kc = 0; kc < 4; kc++)
                    mma16816(O[rb][dt], pa[rb][kc], vb0[kc], vb1[kc]);
        }
        __syncthreads();
        buf ^= 1;
    }

    // ---- epilogue: normalize + store ----
#pragma unroll
    for (int rb = 0; rb < 2; rb++) {
#pragma unroll
        for (int h2 = 0; h2 < 2; h2++) {
            float lt = l[rb][h2];
            lt += __shfl_xor_sync(0xffffffffu, lt, 1);
            lt += __shfl_xor_sync(0xffffffffu, lt, 2);
            float inv = 1.0f / lt;
            int srow = row0 + warp * 32 + rb * 16 + gi + h2 * 8;
            int h = srow >> 10, n = srow & 1023;
            float* orow = g_attn + ((size_t)((b << 10) | n)) * INNER + h * 64;
#pragma unroll
            for (int dt = 0; dt < 8; dt++) {
                float2 o2 = make_float2(O[rb][dt][2 * h2] * inv,
                                        O[rb][dt][2 * h2 + 1] * inv);
                *reinterpret_cast<float2*>(orow + dt * 8 + tig * 2) = o2;
            }
        }
    }
}

// ---------------------------------------------------------------------------
// Output projection: out = g_attn (4096x512) @ wo (512x256) + bo (fp32)
// Transposed-A smem staging: 2x LDS.128 per 16 FMA.
// ---------------------------------------------------------------------------
__global__ __launch_bounds__(256) void out_gemm(
    const float* __restrict__ wo, const float* __restrict__ bo,
    float* __restrict__ out) {
    __shared__ float As[32][68];   // [k][m], padded
    __shared__ float Bs[32][64];

    const int bm0 = blockIdx.x * 64;
    const int bn0 = blockIdx.y * 64;
    const int tid = threadIdx.x;
    const int tx = tid & 15, ty = tid >> 4;

    float acc[4][4];
#pragma unroll
    for (int i = 0; i < 4; i++)
#pragma unroll
        for (int j = 0; j < 4; j++) acc[i][j] = 0.f;

    for (int kb = 0; kb < 16; kb++) {
#pragma unroll
        for (int i = 0; i < 2; i++) {
            int t = tid + i * 256;
            int ra = t >> 3, ca = (t & 7) * 4;
            float4 v = *reinterpret_cast<const float4*>(
                g_attn + (size_t)(bm0 + ra) * 512 + kb * 32 + ca);
            As[ca + 0][ra] = v.x;
            As[ca + 1][ra] = v.y;
            As[ca + 2][ra] = v.z;
            As[ca + 3][ra] = v.w;
            int rb2 = t >> 4, cb2 = (t & 15) * 4;
            *reinterpret_cast<float4*>(&Bs[rb2][cb2]) =
                *reinterpret_cast<const float4*>(wo + (size_t)(kb * 32 + rb2) * 256 + bn0 + cb2);
        }
        __syncthreads();
#pragma unroll
        for (int k = 0; k < 32; k++) {
            float4 av = *reinterpret_cast<const float4*>(&As[k][ty * 4]);
            float4 bv = *reinterpret_cast<const float4*>(&Bs[k][tx * 4]);
            float a[4] = {av.x, av.y, av.z, av.w};
#pragma unroll
            for (int i = 0; i < 4; i++) {
                acc[i][0] += a[i] * bv.x;
                acc[i][1] += a[i] * bv.y;
                acc[i][2] += a[i] * bv.z;
                acc[i][3] += a[i] * bv.w;
            }
        }
        __syncthreads();
    }

    float4 bias = *reinterpret_cast<const float4*>(bo + bn0 + tx * 4);
#pragma unroll
    for (int i = 0; i < 4; i++) {
        float4 o;
        o.x = acc[i][0] + bias.x;
        o.y = acc[i][1] + bias.y;
        o.z = acc[i][2] + bias.z;
        o.w = acc[i][3] + bias.w;
        *reinterpret_cast<float4*>(out + (size_t)(bm0 + ty * 4 + i) * 256 + bn0 + tx * 4) = o;
    }
}

// ---------------------------------------------------------------------------
extern "C" void kernel_launch(void* const* d_in, const int* in_sizes, int n_in,
                              void* d_out, int out_size) {
    const float* x   = (const float*)d_in[0];
    const float* wq1 = (const float*)d_in[1];
    const float* wq2 = (const float*)d_in[2];
    const float* wk1 = (const float*)d_in[3];
    const float* wk2 = (const float*)d_in[4];
    const float* wv1 = (const float*)d_in[5];
    const float* wv2 = (const float*)d_in[6];
    const float* wo  = (const float*)d_in[7];
    const float* bo  = (const float*)d_in[8];
    float* out = (float*)d_out;

    proj_kernel<<<dim3(64, 3), 256>>>(x, wq1, wq2, wk1, wk2, wv1, wv2);
    attn_kernel<<<dim3(64, 4), 128>>>();
    out_gemm<<<dim3(64, 4), 256>>>(wo, bo, out);
}

// round 5
// speedup vs baseline: 1.0412x; 1.0412x over previous
#include <cuda_runtime.h>
#include <cuda_fp16.h>
#include <cstdint>

#define NN    1024
#define QSZ   256
#define BOT   40

// ------------------------- scratch (no allocs allowed) -----------------------
__device__ float  g_a[(size_t)4096 * 40];            // a = x@wq1           [b*1024+n][40]
__device__ __half g_b[(size_t)4096 * 48];            // b = silu(x@wk1)     [b*1024+n][48] (pad 0)
__device__ __half g_ct[(size_t)4 * 40 * 1024];       // c^T (c = x@wv1)     [b][40][n]
__device__ __half g_ah[(size_t)4 * 8 * 8 * 1024 * 48]; // ahat = a@G_{h,h'} [b][h][h'][n][48] (pad 0)
__device__ __half g_wv2t[(size_t)8 * 64 * 48];       // wv2 transposed per head [h][d][40pad48]
__device__ float  g_attn[(size_t)4096 * 512];        // attention out, unsplit

__device__ __forceinline__ float ex2f(float x) {
    float y;
    asm("ex2.approx.ftz.f32 %0, %1;" : "=f"(y) : "f"(x));
    return y;
}

__device__ __forceinline__ unsigned ex2h2(float a, float b) {
    __half2 h = __floats2half2_rn(a, b);
    unsigned u = *reinterpret_cast<unsigned*>(&h);
    unsigned r;
    asm("ex2.approx.f16x2 %0, %1;" : "=r"(r) : "r"(u));
    return r;
}

__device__ __forceinline__ unsigned packh2(float a, float b) {
    __half2 h = __floats2half2_rn(a, b);
    return *reinterpret_cast<unsigned*>(&h);
}

__device__ __forceinline__ void mma16816(float (&c)[4], const unsigned (&a)[4],
                                         unsigned b0, unsigned b1) {
    asm volatile(
        "mma.sync.aligned.m16n8k16.row.col.f32.f16.f16.f32 "
        "{%0,%1,%2,%3}, {%4,%5,%6,%7}, {%8,%9}, {%0,%1,%2,%3};\n"
        : "+f"(c[0]), "+f"(c[1]), "+f"(c[2]), "+f"(c[3])
        : "r"(a[0]), "r"(a[1]), "r"(a[2]), "r"(a[3]), "r"(b0), "r"(b1));
}

__device__ __forceinline__ void cp16(void* s, const void* g) {
    unsigned sa = (unsigned)__cvta_generic_to_shared(s);
    asm volatile("cp.async.cg.shared.global [%0], [%1], 16;\n" :: "r"(sa), "l"(g));
}

__device__ __forceinline__ void ldsm_x4(unsigned& r0, unsigned& r1, unsigned& r2,
                                        unsigned& r3, const void* p) {
    unsigned a = (unsigned)__cvta_generic_to_shared(p);
    asm volatile("ldmatrix.sync.aligned.m8n8.x4.shared.b16 {%0,%1,%2,%3}, [%4];"
                 : "=r"(r0), "=r"(r1), "=r"(r2), "=r"(r3) : "r"(a));
}

__device__ __forceinline__ void ldsm_x2(unsigned& r0, unsigned& r1, const void* p) {
    unsigned a = (unsigned)__cvta_generic_to_shared(p);
    asm volatile("ldmatrix.sync.aligned.m8n8.x2.shared.b16 {%0,%1}, [%2];"
                 : "=r"(r0), "=r"(r1) : "r"(a));
}

// ---------------------------------------------------------------------------
// Bottleneck-only projection: grid (128, 3), 32 rows/block.
//   proj 0: a = x@wq1 (fp32)      proj 1: b = silu(x@wk1) (fp16, 48-pad)
//   proj 2: c^T = (x@wv1)^T (fp16)
// ---------------------------------------------------------------------------
__global__ __launch_bounds__(256) void proj_kernel(
    const float* __restrict__ x,
    const float* __restrict__ wq1, const float* __restrict__ wk1,
    const float* __restrict__ wv1) {
    __shared__ float sWT[40 * 260];   // w1 transposed [c][k], padded stride 260
    __shared__ float sB[32 * 44];

    const int proj = blockIdx.y;
    const float* w1 = (proj == 0) ? wq1 : (proj == 1 ? wk1 : wv1);
    const int row0 = blockIdx.x * 32;
    const int tid = threadIdx.x;

    // transpose w1 into smem: element (k, c) at w1[k*40+c] -> sWT[c*260+k]
#pragma unroll
    for (int i = 0; i < 40; i++) {
        int idx = tid + i * 256;
        int k = idx / 40, c = idx % 40;
        sWT[c * 260 + k] = w1[idx];
    }
    __syncthreads();

    const int r = tid >> 3;       // row [0,32)
    const int tc = tid & 7;       // col thread [0,8): cols tc + 8i
    {
        const float4* xr = reinterpret_cast<const float4*>(x + (size_t)(row0 + r) * QSZ);
        float acc[5] = {0.f, 0.f, 0.f, 0.f, 0.f};
#pragma unroll 8
        for (int k4 = 0; k4 < 64; k4++) {
            float4 xv = xr[k4];
#pragma unroll
            for (int i = 0; i < 5; i++) {
                float4 w = *reinterpret_cast<const float4*>(&sWT[(tc + 8 * i) * 260 + k4 * 4]);
                acc[i] += xv.x * w.x + xv.y * w.y + xv.z * w.z + xv.w * w.w;
            }
        }
#pragma unroll
        for (int i = 0; i < 5; i++) {
            float v = acc[i];
            if (proj == 1) v = v / (1.0f + __expf(-v));
            sB[r * 44 + tc + 8 * i] = v;
        }
    }
    __syncthreads();

    if (proj == 0) {
#pragma unroll
        for (int i = 0; i < 5; i++) {
            int idx = tid + i * 256;
            int r2 = idx / 40, c = idx % 40;
            g_a[(size_t)(row0 + r2) * 40 + c] = sB[r2 * 44 + c];
        }
    } else if (proj == 1) {
#pragma unroll
        for (int i = 0; i < 5; i++) {
            int idx = tid + i * 256;
            int r2 = idx / 40, c = idx % 40;
            g_b[(size_t)(row0 + r2) * 48 + c] = __float2half_rn(sB[r2 * 44 + c]);
        }
    } else {
        const int bb = row0 >> 10;
        const int n0 = row0 & 1023;
#pragma unroll
        for (int i = 0; i < 5; i++) {
            int idx = tid + i * 256;
            int c = idx >> 5, r2 = idx & 31;
            g_ct[((size_t)bb * 40 + c) * 1024 + n0 + r2] = __float2half_rn(sB[r2 * 44 + c]);
        }
    }
}

// ---------------------------------------------------------------------------
// ahat: for each (b, h, h'): G = scale*log2e * wq2_h @ wk2_{h'}^T (40x40),
// then ahat = a @ G -> fp16 [1024][48] (cols 40..47 stay zero-init).
// ---------------------------------------------------------------------------
__global__ __launch_bounds__(256) void ahat_kernel(
    const float* __restrict__ wq2, const float* __restrict__ wk2) {
    __shared__ float sA[40 * 64];
    __shared__ float sK[40 * 64];
    __shared__ float G[40 * 40];

    const int bx = blockIdx.x;
    const int b = bx >> 6, h = (bx >> 3) & 7, hp = bx & 7;
    const int tid = threadIdx.x;

    for (int idx = tid; idx < 2560; idx += 256) {
        int i = idx >> 6, d = idx & 63;
        sA[idx] = wq2[(size_t)i * 512 + h * 64 + d];
        sK[idx] = wk2[(size_t)i * 512 + hp * 64 + d];
    }
    __syncthreads();

    const float SCALE = 0.125f * 1.4426950408889634f;  // d^-0.5 * log2(e)
    for (int idx = tid; idx < 1600; idx += 256) {
        int i = idx / 40, j = idx % 40;
        float s = 0.f;
#pragma unroll 8
        for (int d = 0; d < 64; d++) s += sA[i * 64 + d] * sK[j * 64 + d];
        G[idx] = s * SCALE;
    }
    __syncthreads();

    __half* dst = g_ah + (size_t)((b * 8 + h) * 8 + hp) * 1024 * 48;
    for (int r = tid; r < 1024; r += 256) {
        const float* ar = g_a + (size_t)(b * 1024 + r) * 40;
        float av[40];
#pragma unroll
        for (int i = 0; i < 40; i++) av[i] = ar[i];
        float acc[40];
#pragma unroll
        for (int j = 0; j < 40; j++) acc[j] = 0.f;
#pragma unroll 4
        for (int i = 0; i < 40; i++) {
            float a = av[i];
            const float4* g4 = reinterpret_cast<const float4*>(&G[i * 40]);
#pragma unroll
            for (int j4 = 0; j4 < 10; j4++) {
                float4 g = g4[j4];
                acc[j4 * 4 + 0] += a * g.x;
                acc[j4 * 4 + 1] += a * g.y;
                acc[j4 * 4 + 2] += a * g.z;
                acc[j4 * 4 + 3] += a * g.w;
            }
        }
        __half2* o2 = reinterpret_cast<__half2*>(dst + (size_t)r * 48);
#pragma unroll
        for (int j = 0; j < 20; j++)
            o2[j] = __floats2half2_rn(acc[2 * j], acc[2 * j + 1]);
    }
}

// ---------------------------------------------------------------------------
// wv2t: g_wv2t[h][d][k] = wv2[k][h*64+d], fp16 (cols 40..47 stay zero-init)
// ---------------------------------------------------------------------------
__global__ __launch_bounds__(256) void wv2t_kernel(const float* __restrict__ wv2) {
    const int h = blockIdx.x;
    for (int idx = threadIdx.x; idx < 64 * 40; idx += 256) {
        int d = idx / 40, k = idx % 40;
        g_wv2t[(size_t)h * 64 * 48 + d * 48 + k] =
            __float2half_rn(wv2[(size_t)k * 512 + h * 64 + d]);
    }
}

// ---------------------------------------------------------------------------
// Flash attention, restructured: 256 thr, 8 warps x 16 rows = 128 query rows.
// Key-side (b: [1024][48], c^T: [40][1024]) fully smem-resident per CTA.
// Loop: h' outer (8 runs), 16 tiles of 64 keys inner (no barriers inside).
// T (N=40) accumulator; flush O += T @ wv2t_{h'} per run.
// ---------------------------------------------------------------------------
#define BST 56
#define CST 1032
#define WST 56
#define SM_CT (1024 * BST)
#define SM_WV (SM_CT + 40 * CST)
#define ATTN_SMEM ((SM_WV + 64 * WST) * 2)

__global__ __launch_bounds__(256) void attn_kernel() {
    extern __shared__ __half sm[];
    __half* b_s = sm;
    __half* ct_s = sm + SM_CT;
    __half* wv_s = sm + SM_WV;

    const int b = blockIdx.y;
    const int qt = blockIdx.x;         // 0..63
    const int h = qt >> 3;
    const int n0 = (qt & 7) * 128;
    const int tid = threadIdx.x;
    const int w = tid >> 5, lane = tid & 31;
    const int gi = lane >> 2, tig = lane & 3;
    const int l8 = lane & 7, mrow = lane >> 3;

    // prologue: resident key-side data
    {
        const __half* gb = g_b + (size_t)b * 1024 * 48;
        for (int idx = tid; idx < 1024 * 6; idx += 256) {
            int row = idx / 6, seg = idx % 6;
            cp16(&b_s[row * BST + seg * 8], gb + row * 48 + seg * 8);
        }
        const __half* gct = g_ct + (size_t)b * 40 * 1024;
        for (int idx = tid; idx < 40 * 128; idx += 256) {
            int row = idx >> 7, seg = idx & 127;
            cp16(&ct_s[row * CST + seg * 8], gct + row * 1024 + seg * 8);
        }
        asm volatile("cp.async.commit_group;\n");
        asm volatile("cp.async.wait_group 0;\n");
    }
    __syncthreads();

    float m[2] = {-1e30f, -1e30f}, l[2] = {0.f, 0.f};
    float O[8][4], T[5][4];
#pragma unroll
    for (int dt = 0; dt < 8; dt++)
#pragma unroll
        for (int q = 0; q < 4; q++) O[dt][q] = 0.f;
#pragma unroll
    for (int n = 0; n < 5; n++)
#pragma unroll
        for (int q = 0; q < 4; q++) T[n][q] = 0.f;

    for (int hp = 0; hp < 8; hp++) {
        // stage wv2t_{hp} (consumed at flush; wv_s free here due to end-of-run sync)
        {
            const __half* gw = g_wv2t + (size_t)hp * 64 * 48;
            for (int idx = tid; idx < 64 * 6; idx += 256) {
                int row = idx / 6, seg = idx % 6;
                cp16(&wv_s[row * WST + seg * 8], gw + row * 48 + seg * 8);
            }
            asm volatile("cp.async.commit_group;\n");
        }

        // ahat A-fragments for this (h, hp): 3 k-steps covering 48 cols
        unsigned qf[3][4];
        {
            const __half* ah = g_ah +
                ((size_t)((b * 8 + h) * 8 + hp) * 1024 + n0 + w * 16) * 48;
#pragma unroll
            for (int kc = 0; kc < 3; kc++) {
                int cc = kc * 16 + tig * 2;
                qf[kc][0] = *reinterpret_cast<const unsigned*>(ah + gi * 48 + cc);
                qf[kc][1] = *reinterpret_cast<const unsigned*>(ah + (gi + 8) * 48 + cc);
                qf[kc][2] = *reinterpret_cast<const unsigned*>(ah + gi * 48 + cc + 8);
                qf[kc][3] = *reinterpret_cast<const unsigned*>(ah + (gi + 8) * 48 + cc + 8);
            }
        }

        for (int t = 0; t < 16; t++) {
            // ---- S = ahat @ b^T (k=48) ----
            float S[8][4];
#pragma unroll
            for (int nt = 0; nt < 8; nt++)
#pragma unroll
                for (int q = 0; q < 4; q++) S[nt][q] = 0.f;

#pragma unroll
            for (int nt = 0; nt < 8; nt++) {
                unsigned kb0[3], kb1[3];
                const __half* ka = &b_s[(t * 64 + nt * 8 + l8) * BST + mrow * 8];
                ldsm_x4(kb0[0], kb1[0], kb0[1], kb1[1], ka);
                ldsm_x2(kb0[2], kb1[2], ka + 32);
#pragma unroll
                for (int kc = 0; kc < 3; kc++)
                    mma16816(S[nt], qf[kc], kb0[kc], kb1[kc]);
            }

            // ---- online softmax (log2 domain) ----
#pragma unroll
            for (int h2 = 0; h2 < 2; h2++) {
                float tm = -1e30f;
#pragma unroll
                for (int nt = 0; nt < 8; nt++)
                    tm = fmaxf(tm, fmaxf(S[nt][2 * h2], S[nt][2 * h2 + 1]));
                tm = fmaxf(tm, __shfl_xor_sync(0xffffffffu, tm, 1));
                tm = fmaxf(tm, __shfl_xor_sync(0xffffffffu, tm, 2));
                if (tm > m[h2]) {
                    float al = ex2f(m[h2] - tm);
                    m[h2] = tm;
                    l[h2] *= al;
#pragma unroll
                    for (int dt = 0; dt < 8; dt++) {
                        O[dt][2 * h2] *= al;
                        O[dt][2 * h2 + 1] *= al;
                    }
#pragma unroll
                    for (int n = 0; n < 5; n++) {
                        T[n][2 * h2] *= al;
                        T[n][2 * h2 + 1] *= al;
                    }
                }
            }

            unsigned pa[4][4];
            __half2 ls0 = __floats2half2_rn(0.f, 0.f);
            __half2 ls1 = ls0;
#pragma unroll
            for (int nt = 0; nt < 8; nt++) {
                unsigned p01 = ex2h2(S[nt][0] - m[0], S[nt][1] - m[0]);
                unsigned p23 = ex2h2(S[nt][2] - m[1], S[nt][3] - m[1]);
                ls0 = __hadd2(ls0, *reinterpret_cast<__half2*>(&p01));
                ls1 = __hadd2(ls1, *reinterpret_cast<__half2*>(&p23));
                pa[nt >> 1][(nt & 1) * 2]     = p01;
                pa[nt >> 1][(nt & 1) * 2 + 1] = p23;
            }
            {
                float2 f0 = __half22float2(ls0);
                float2 f1 = __half22float2(ls1);
                l[0] += f0.x + f0.y;
                l[1] += f1.x + f1.y;
            }

            // ---- T += P @ c (N = 40: 5 n-tiles) ----
#pragma unroll
            for (int n = 0; n < 5; n++) {
                unsigned vb0[4], vb1[4];
                const __half* va = &ct_s[(n * 8 + l8) * CST + t * 64 + mrow * 8];
                ldsm_x4(vb0[0], vb1[0], vb0[1], vb1[1], va);
                ldsm_x4(vb0[2], vb1[2], vb0[3], vb1[3], va + 32);
#pragma unroll
                for (int kc = 0; kc < 4; kc++)
                    mma16816(T[n], pa[kc], vb0[kc], vb1[kc]);
            }
        }

        // ---- flush: O += T @ wv2t_{hp} (k = 40 pad 48) ----
        unsigned at[3][4];
#pragma unroll
        for (int kc = 0; kc < 2; kc++) {
            at[kc][0] = packh2(T[2 * kc][0],     T[2 * kc][1]);
            at[kc][1] = packh2(T[2 * kc][2],     T[2 * kc][3]);
            at[kc][2] = packh2(T[2 * kc + 1][0], T[2 * kc + 1][1]);
            at[kc][3] = packh2(T[2 * kc + 1][2], T[2 * kc + 1][3]);
        }
        at[2][0] = packh2(T[4][0], T[4][1]);
        at[2][1] = packh2(T[4][2], T[4][3]);
        at[2][2] = 0u;
        at[2][3] = 0u;

        asm volatile("cp.async.wait_group 0;\n");
        __syncthreads();   // wv_s ready for everyone

#pragma unroll
        for (int dt = 0; dt < 8; dt++) {
            unsigned wb0[3], wb1[3];
            const __half* wa = &wv_s[(dt * 8 + l8) * WST + mrow * 8];
            ldsm_x4(wb0[0], wb1[0], wb0[1], wb1[1], wa);
            ldsm_x2(wb0[2], wb1[2], wa + 32);
#pragma unroll
            for (int kc = 0; kc < 3; kc++)
                mma16816(O[dt], at[kc], wb0[kc], wb1[kc]);
        }
#pragma unroll
        for (int n = 0; n < 5; n++)
#pragma unroll
            for (int q = 0; q < 4; q++) T[n][q] = 0.f;

        __syncthreads();   // all reads of wv_s done before next run overwrites
    }

    // ---- epilogue: normalize + store ----
#pragma unroll
    for (int h2 = 0; h2 < 2; h2++) {
        float lt = l[h2];
        lt += __shfl_xor_sync(0xffffffffu, lt, 1);
        lt += __shfl_xor_sync(0xffffffffu, lt, 2);
        float inv = 1.0f / lt;
        int n = n0 + w * 16 + gi + h2 * 8;
        float* orow = g_attn + ((size_t)((b << 10) | n)) * 512 + h * 64;
#pragma unroll
        for (int dt = 0; dt < 8; dt++) {
            float2 o2 = make_float2(O[dt][2 * h2] * inv, O[dt][2 * h2 + 1] * inv);
            *reinterpret_cast<float2*>(orow + dt * 8 + tig * 2) = o2;
        }
    }
}

// ---------------------------------------------------------------------------
// Output projection: out = g_attn (4096x512) @ wo (512x256) + bo (fp32)
// ---------------------------------------------------------------------------
__global__ __launch_bounds__(256) void out_gemm(
    const float* __restrict__ wo, const float* __restrict__ bo,
    float* __restrict__ out) {
    __shared__ float As[32][68];
    __shared__ float Bs[32][64];

    const int bm0 = blockIdx.x * 64;
    const int bn0 = blockIdx.y * 64;
    const int tid = threadIdx.x;
    const int tx = tid & 15, ty = tid >> 4;

    float acc[4][4];
#pragma unroll
    for (int i = 0; i < 4; i++)
#pragma unroll
        for (int j = 0; j < 4; j++) acc[i][j] = 0.f;

    for (int kb = 0; kb < 16; kb++) {
#pragma unroll
        for (int i = 0; i < 2; i++) {
            int t = tid + i * 256;
            int ra = t >> 3, ca = (t & 7) * 4;
            float4 v = *reinterpret_cast<const float4*>(
                g_attn + (size_t)(bm0 + ra) * 512 + kb * 32 + ca);
            As[ca + 0][ra] = v.x;
            As[ca + 1][ra] = v.y;
            As[ca + 2][ra] = v.z;
            As[ca + 3][ra] = v.w;
            int rb2 = t >> 4, cb2 = (t & 15) * 4;
            *reinterpret_cast<float4*>(&Bs[rb2][cb2]) =
                *reinterpret_cast<const float4*>(wo + (size_t)(kb * 32 + rb2) * 256 + bn0 + cb2);
        }
        __syncthreads();
#pragma unroll
        for (int k = 0; k < 32; k++) {
            float4 av = *reinterpret_cast<const float4*>(&As[k][ty * 4]);
            float4 bv = *reinterpret_cast<const float4*>(&Bs[k][tx * 4]);
            float a[4] = {av.x, av.y, av.z, av.w};
#pragma unroll
            for (int i = 0; i < 4; i++) {
                acc[i][0] += a[i] * bv.x;
                acc[i][1] += a[i] * bv.y;
                acc[i][2] += a[i] * bv.z;
                acc[i][3] += a[i] * bv.w;
            }
        }
        __syncthreads();
    }

    float4 bias = *reinterpret_cast<const float4*>(bo + bn0 + tx * 4);
#pragma unroll
    for (int i = 0; i < 4; i++) {
        float4 o;
        o.x = acc[i][0] + bias.x;
        o.y = acc[i][1] + bias.y;
        o.z = acc[i][2] + bias.z;
        o.w = acc[i][3] + bias.w;
        *reinterpret_cast<float4*>(out + (size_t)(bm0 + ty * 4 + i) * 256 + bn0 + tx * 4) = o;
    }
}

// ---------------------------------------------------------------------------
extern "C" void kernel_launch(void* const* d_in, const int* in_sizes, int n_in,
                              void* d_out, int out_size) {
    const float* x   = (const float*)d_in[0];
    const float* wq1 = (const float*)d_in[1];
    const float* wq2 = (const float*)d_in[2];
    const float* wk1 = (const float*)d_in[3];
    const float* wk2 = (const float*)d_in[4];
    const float* wv1 = (const float*)d_in[5];
    const float* wv2 = (const float*)d_in[6];
    const float* wo  = (const float*)d_in[7];
    const float* bo  = (const float*)d_in[8];
    float* out = (float*)d_out;

    cudaFuncSetAttribute(attn_kernel, cudaFuncAttributeMaxDynamicSharedMemorySize,
                         ATTN_SMEM);

    proj_kernel<<<dim3(128, 3), 256>>>(x, wq1, wk1, wv1);
    wv2t_kernel<<<8, 256>>>(wv2);
    ahat_kernel<<<256, 256>>>(wq2, wk2);
    attn_kernel<<<dim3(64, 4), 256, ATTN_SMEM>>>();
    out_gemm<<<dim3(64, 4), 256>>>(wo, bo, out);
}

// round 6
// speedup vs baseline: 1.0643x; 1.0222x over previous
#include <cuda_runtime.h>
#include <cuda_fp16.h>
#include <cstdint>

#define NN    1024
#define QSZ   256
#define BOT   40

// ------------------------- scratch (no allocs allowed) -----------------------
__device__ float  g_a[(size_t)4096 * 40];              // a = x@wq1          [b*1024+n][40]
__device__ __half g_b[(size_t)4096 * 40];              // b = silu(x@wk1)    [b*1024+n][40]
__device__ __half g_ct[(size_t)4 * 40 * 1024];         // c^T (c = x@wv1)    [b][40][n]
__device__ __half g_ah[(size_t)4 * 8 * 8 * 1024 * 40]; // ahat = a@G_{h,h'}  [b][h][h'][n][40]
__device__ __half g_wv2t[(size_t)8 * 64 * 40];         // wv2^T per head     [h][d][40]
__device__ float  g_attn[(size_t)4096 * 512];          // attention out, unsplit

__device__ __forceinline__ float ex2f(float x) {
    float y;
    asm("ex2.approx.ftz.f32 %0, %1;" : "=f"(y) : "f"(x));
    return y;
}

__device__ __forceinline__ unsigned ex2h2(float a, float b) {
    __half2 h = __floats2half2_rn(a, b);
    unsigned u = *reinterpret_cast<unsigned*>(&h);
    unsigned r;
    asm("ex2.approx.f16x2 %0, %1;" : "=r"(r) : "r"(u));
    return r;
}

__device__ __forceinline__ unsigned packh2(float a, float b) {
    __half2 h = __floats2half2_rn(a, b);
    return *reinterpret_cast<unsigned*>(&h);
}

__device__ __forceinline__ void mma16816(float (&c)[4], const unsigned (&a)[4],
                                         unsigned b0, unsigned b1) {
    asm volatile(
        "mma.sync.aligned.m16n8k16.row.col.f32.f16.f16.f32 "
        "{%0,%1,%2,%3}, {%4,%5,%6,%7}, {%8,%9}, {%0,%1,%2,%3};\n"
        : "+f"(c[0]), "+f"(c[1]), "+f"(c[2]), "+f"(c[3])
        : "r"(a[0]), "r"(a[1]), "r"(a[2]), "r"(a[3]), "r"(b0), "r"(b1));
}

__device__ __forceinline__ void mma16808(float (&c)[4], unsigned a0, unsigned a1,
                                         unsigned b0) {
    asm volatile(
        "mma.sync.aligned.m16n8k8.row.col.f32.f16.f16.f32 "
        "{%0,%1,%2,%3}, {%4,%5}, {%6}, {%0,%1,%2,%3};\n"
        : "+f"(c[0]), "+f"(c[1]), "+f"(c[2]), "+f"(c[3])
        : "r"(a0), "r"(a1), "r"(b0));
}

__device__ __forceinline__ void cp16(void* s, const void* g) {
    unsigned sa = (unsigned)__cvta_generic_to_shared(s);
    asm volatile("cp.async.cg.shared.global [%0], [%1], 16;\n" :: "r"(sa), "l"(g));
}

__device__ __forceinline__ void ldsm_x4(unsigned& r0, unsigned& r1, unsigned& r2,
                                        unsigned& r3, const void* p) {
    unsigned a = (unsigned)__cvta_generic_to_shared(p);
    asm volatile("ldmatrix.sync.aligned.m8n8.x4.shared.b16 {%0,%1,%2,%3}, [%4];"
                 : "=r"(r0), "=r"(r1), "=r"(r2), "=r"(r3) : "r"(a));
}

__device__ __forceinline__ void ldsm_x1(unsigned& r0, const void* p) {
    unsigned a = (unsigned)__cvta_generic_to_shared(p);
    asm volatile("ldmatrix.sync.aligned.m8n8.x1.shared.b16 {%0}, [%1];"
                 : "=r"(r0) : "r"(a));
}

// ---------------------------------------------------------------------------
// Bottleneck-only projection: grid (128, 3), 32 rows/block.
// ---------------------------------------------------------------------------
__global__ __launch_bounds__(256) void proj_kernel(
    const float* __restrict__ x,
    const float* __restrict__ wq1, const float* __restrict__ wk1,
    const float* __restrict__ wv1) {
    __shared__ float sWT[40 * 260];
    __shared__ float sB[32 * 44];

    const int proj = blockIdx.y;
    const float* w1 = (proj == 0) ? wq1 : (proj == 1 ? wk1 : wv1);
    const int row0 = blockIdx.x * 32;
    const int tid = threadIdx.x;

#pragma unroll
    for (int i = 0; i < 40; i++) {
        int idx = tid + i * 256;
        int k = idx / 40, c = idx % 40;
        sWT[c * 260 + k] = w1[idx];
    }
    __syncthreads();

    const int r = tid >> 3;
    const int tc = tid & 7;
    {
        const float4* xr = reinterpret_cast<const float4*>(x + (size_t)(row0 + r) * QSZ);
        float acc[5] = {0.f, 0.f, 0.f, 0.f, 0.f};
#pragma unroll 8
        for (int k4 = 0; k4 < 64; k4++) {
            float4 xv = xr[k4];
#pragma unroll
            for (int i = 0; i < 5; i++) {
                float4 w = *reinterpret_cast<const float4*>(&sWT[(tc + 8 * i) * 260 + k4 * 4]);
                acc[i] += xv.x * w.x + xv.y * w.y + xv.z * w.z + xv.w * w.w;
            }
        }
#pragma unroll
        for (int i = 0; i < 5; i++) {
            float v = acc[i];
            if (proj == 1) v = v / (1.0f + __expf(-v));
            sB[r * 44 + tc + 8 * i] = v;
        }
    }
    __syncthreads();

    if (proj == 0) {
#pragma unroll
        for (int i = 0; i < 5; i++) {
            int idx = tid + i * 256;
            int r2 = idx / 40, c = idx % 40;
            g_a[(size_t)(row0 + r2) * 40 + c] = sB[r2 * 44 + c];
        }
    } else if (proj == 1) {
#pragma unroll
        for (int i = 0; i < 5; i++) {
            int idx = tid + i * 256;
            int r2 = idx / 40, c = idx % 40;
            g_b[(size_t)(row0 + r2) * 40 + c] = __float2half_rn(sB[r2 * 44 + c]);
        }
    } else {
        const int bb = row0 >> 10;
        const int n0 = row0 & 1023;
#pragma unroll
        for (int i = 0; i < 5; i++) {
            int idx = tid + i * 256;
            int c = idx >> 5, r2 = idx & 31;
            g_ct[((size_t)bb * 40 + c) * 1024 + n0 + r2] = __float2half_rn(sB[r2 * 44 + c]);
        }
    }
}

// ---------------------------------------------------------------------------
// ahat: G = scale*log2e * wq2_h @ wk2_{h'}^T (40x40); ahat = a @ G -> fp16.
// All gmem traffic staged through smem, fully coalesced.
// ---------------------------------------------------------------------------
#define AHAT_SMEM ((12096 + 5376) * 4)   // 69888 bytes

__global__ __launch_bounds__(256) void ahat_kernel(
    const float* __restrict__ wq2, const float* __restrict__ wk2) {
    extern __shared__ float sf[];
    float* G   = sf;                 // 1600
    float* sA  = sf + 1600;          // 2560
    float* sK  = sf + 4160;          // 2560
    float* aSt = sf + 1600;          // 256*41 = 10496 (reuses sA/sK after G)
    __half* oSt = reinterpret_cast<__half*>(sf + 12096);  // 256*42 halves

    const int bx = blockIdx.x;
    const int bb = bx >> 6, h = (bx >> 3) & 7, hp = bx & 7;
    const int tid = threadIdx.x;

    for (int idx = tid; idx < 2560; idx += 256) {
        int i = idx >> 6, d = idx & 63;
        sA[idx] = wq2[(size_t)i * 512 + h * 64 + d];
        sK[idx] = wk2[(size_t)i * 512 + hp * 64 + d];
    }
    __syncthreads();

    const float SCALE = 0.125f * 1.4426950408889634f;
    for (int idx = tid; idx < 1600; idx += 256) {
        int i = idx / 40, j = idx % 40;
        float s = 0.f;
#pragma unroll 8
        for (int d = 0; d < 64; d++) s += sA[i * 64 + d] * sK[j * 64 + d];
        G[idx] = s * SCALE;
    }
    __syncthreads();

    __half* dst = g_ah + (size_t)((bb * 8 + h) * 8 + hp) * 1024 * 40;

    for (int chunk = 0; chunk < 4; chunk++) {
        // stage a-chunk (coalesced float4 reads)
        const float* ga = g_a + ((size_t)(bb * 1024 + chunk * 256)) * 40;
        for (int u = tid; u < 2560; u += 256) {
            int row = u / 10, c4 = u % 10;
            float4 v = reinterpret_cast<const float4*>(ga + (size_t)row * 40)[c4];
            aSt[row * 41 + c4 * 4 + 0] = v.x;
            aSt[row * 41 + c4 * 4 + 1] = v.y;
            aSt[row * 41 + c4 * 4 + 2] = v.z;
            aSt[row * 41 + c4 * 4 + 3] = v.w;
        }
        __syncthreads();

        // each thread computes one row
        {
            float av[40];
#pragma unroll
            for (int i = 0; i < 40; i++) av[i] = aSt[tid * 41 + i];
            float acc[40];
#pragma unroll
            for (int j = 0; j < 40; j++) acc[j] = 0.f;
#pragma unroll 4
            for (int i = 0; i < 40; i++) {
                float a = av[i];
                const float4* g4 = reinterpret_cast<const float4*>(&G[i * 40]);
#pragma unroll
                for (int j4 = 0; j4 < 10; j4++) {
                    float4 g = g4[j4];
                    acc[j4 * 4 + 0] += a * g.x;
                    acc[j4 * 4 + 1] += a * g.y;
                    acc[j4 * 4 + 2] += a * g.z;
                    acc[j4 * 4 + 3] += a * g.w;
                }
            }
            __half2* o2 = reinterpret_cast<__half2*>(oSt);
#pragma unroll
            for (int j = 0; j < 20; j++)
                o2[tid * 21 + j] = __floats2half2_rn(acc[2 * j], acc[2 * j + 1]);
        }
        __syncthreads();

        // coalesced flush (u32)
        {
            unsigned* dst32 = reinterpret_cast<unsigned*>(dst + (size_t)chunk * 256 * 40);
            const unsigned* o32 = reinterpret_cast<const unsigned*>(oSt);
            for (int u = tid; u < 5120; u += 256) {
                int r2 = u / 20, c = u % 20;
                dst32[u] = o32[r2 * 21 + c];
            }
        }
        __syncthreads();
    }
}

// ---------------------------------------------------------------------------
// wv2t: g_wv2t[h][d][k] = wv2[k][h*64+d]
// ---------------------------------------------------------------------------
__global__ __launch_bounds__(256) void wv2t_kernel(const float* __restrict__ wv2) {
    const int h = blockIdx.x;
    for (int idx = threadIdx.x; idx < 64 * 40; idx += 256) {
        int d = idx / 40, k = idx % 40;
        g_wv2t[(size_t)h * 2560 + d * 40 + k] =
            __float2half_rn(wv2[(size_t)k * 512 + h * 64 + d]);
    }
}

// ---------------------------------------------------------------------------
// Flash attention: 256 thr (8 warps x 16 rows = 128 q rows), 2 CTAs/SM.
// b resident (80KB, stride 40, conflict-free); ct tiles streamed (3 bufs);
// wv streamed (2 bufs). k=40 contraction via 2x k16 + 1x k8.
// ---------------------------------------------------------------------------
#define CTS   72
#define CTSZ  (40 * CTS)          // 2880 halves per ct tile
#define WVSZ  2560                // 64*40 halves
#define B_HALVES 40960
#define ATTN_SMEM ((B_HALVES + 3 * CTSZ + 2 * WVSZ) * 2)   // 109440 B

__global__ __launch_bounds__(256, 2) void attn_kernel() {
    extern __shared__ __half sm[];
    __half* b_s  = sm;                       // [1024][40]
    __half* ct_s = sm + B_HALVES;            // 3 tiles [40][72]
    __half* wv_s = sm + B_HALVES + 3 * CTSZ; // 2 bufs [64][40]

    const int b = blockIdx.y;
    const int qt = blockIdx.x;
    const int h = qt >> 3;
    const int n0 = (qt & 7) * 128;
    const int tid = threadIdx.x;
    const int w = tid >> 5, lane = tid & 31;
    const int gi = lane >> 2, tig = lane & 3;
    const int l8 = lane & 7, mrow = lane >> 3;

    const __half* gb = g_b + (size_t)b * 1024 * 40;
    const __half* gct = g_ct + (size_t)b * 40 * 1024;

    // prologue: resident b + ct tile 0 + wv[0]
    for (int idx = tid; idx < 5120; idx += 256)
        cp16(&b_s[idx * 8], gb + idx * 8);
    for (int idx = tid; idx < 320; idx += 256) {
        int row = idx >> 3, seg = idx & 7;
        cp16(&ct_s[row * CTS + seg * 8], gct + (size_t)row * 1024 + seg * 8);
    }
    for (int idx = tid; idx < 320; idx += 256)
        cp16(&wv_s[idx * 8], g_wv2t + idx * 8);
    asm volatile("cp.async.commit_group;\n");
    asm volatile("cp.async.wait_group 0;\n");
    __syncthreads();

    float m[2] = {-1e30f, -1e30f}, l[2] = {0.f, 0.f};
    float O[8][4], T[5][4];
#pragma unroll
    for (int dt = 0; dt < 8; dt++)
#pragma unroll
        for (int q = 0; q < 4; q++) O[dt][q] = 0.f;
#pragma unroll
    for (int n = 0; n < 5; n++)
#pragma unroll
        for (int q = 0; q < 4; q++) T[n][q] = 0.f;

    unsigned qf[2][4], qf8[2];

    for (int tt = 0; tt < 128; tt++) {
        const int hp = tt >> 4, t = tt & 15;

        // prefetch next ct tile (+ next wv at run start)
        if (tt < 127) {
            int ntile = (tt + 1) & 15;
            __half* dc = ct_s + ((tt + 1) % 3) * CTSZ;
            for (int idx = tid; idx < 320; idx += 256) {
                int row = idx >> 3, seg = idx & 7;
                cp16(&dc[row * CTS + seg * 8],
                     gct + (size_t)row * 1024 + ntile * 64 + seg * 8);
            }
            if (t == 0 && hp < 7) {
                __half* dw = wv_s + ((hp + 1) & 1) * WVSZ;
                const __half* gw = g_wv2t + (size_t)(hp + 1) * 2560;
                for (int idx = tid; idx < 320; idx += 256)
                    cp16(&dw[idx * 8], gw + idx * 8);
            }
            asm volatile("cp.async.commit_group;\n");
            asm volatile("cp.async.wait_group 1;\n");
        } else {
            asm volatile("cp.async.wait_group 0;\n");
        }
        __syncthreads();

        if (t == 0) {
            const __half* ah = g_ah +
                ((size_t)((b * 8 + h) * 8 + hp) * 1024 + n0 + w * 16) * 40;
#pragma unroll
            for (int kc = 0; kc < 2; kc++) {
                int cc = kc * 16 + tig * 2;
                qf[kc][0] = *reinterpret_cast<const unsigned*>(ah + gi * 40 + cc);
                qf[kc][1] = *reinterpret_cast<const unsigned*>(ah + (gi + 8) * 40 + cc);
                qf[kc][2] = *reinterpret_cast<const unsigned*>(ah + gi * 40 + cc + 8);
                qf[kc][3] = *reinterpret_cast<const unsigned*>(ah + (gi + 8) * 40 + cc + 8);
            }
            int cc2 = 32 + tig * 2;
            qf8[0] = *reinterpret_cast<const unsigned*>(ah + gi * 40 + cc2);
            qf8[1] = *reinterpret_cast<const unsigned*>(ah + (gi + 8) * 40 + cc2);
        }

        // ---- S = ahat @ b^T (k=40) ----
        float S[8][4];
#pragma unroll
        for (int nt = 0; nt < 8; nt++)
#pragma unroll
            for (int q = 0; q < 4; q++) S[nt][q] = 0.f;

#pragma unroll
        for (int nt = 0; nt < 8; nt++) {
            unsigned kb0[2], kb1[2], kb8;
            const __half* ka = &b_s[(t * 64 + nt * 8 + l8) * 40 + mrow * 8];
            ldsm_x4(kb0[0], kb1[0], kb0[1], kb1[1], ka);
            ldsm_x1(kb8, &b_s[(t * 64 + nt * 8 + l8) * 40 + 32]);
            mma16816(S[nt], qf[0], kb0[0], kb1[0]);
            mma16816(S[nt], qf[1], kb0[1], kb1[1]);
            mma16808(S[nt], qf8[0], qf8[1], kb8);
        }

        // ---- online softmax (log2 domain) ----
#pragma unroll
        for (int h2 = 0; h2 < 2; h2++) {
            float tm = -1e30f;
#pragma unroll
            for (int nt = 0; nt < 8; nt++)
                tm = fmaxf(tm, fmaxf(S[nt][2 * h2], S[nt][2 * h2 + 1]));
            tm = fmaxf(tm, __shfl_xor_sync(0xffffffffu, tm, 1));
            tm = fmaxf(tm, __shfl_xor_sync(0xffffffffu, tm, 2));
            if (tm > m[h2]) {
                float al = ex2f(m[h2] - tm);
                m[h2] = tm;
                l[h2] *= al;
#pragma unroll
                for (int dt = 0; dt < 8; dt++) {
                    O[dt][2 * h2] *= al;
                    O[dt][2 * h2 + 1] *= al;
                }
#pragma unroll
                for (int n = 0; n < 5; n++) {
                    T[n][2 * h2] *= al;
                    T[n][2 * h2 + 1] *= al;
                }
            }
        }

        unsigned pa[4][4];
        __half2 ls0 = __floats2half2_rn(0.f, 0.f);
        __half2 ls1 = ls0;
#pragma unroll
        for (int nt = 0; nt < 8; nt++) {
            unsigned p01 = ex2h2(S[nt][0] - m[0], S[nt][1] - m[0]);
            unsigned p23 = ex2h2(S[nt][2] - m[1], S[nt][3] - m[1]);
            ls0 = __hadd2(ls0, *reinterpret_cast<__half2*>(&p01));
            ls1 = __hadd2(ls1, *reinterpret_cast<__half2*>(&p23));
            pa[nt >> 1][(nt & 1) * 2]     = p01;
            pa[nt >> 1][(nt & 1) * 2 + 1] = p23;
        }
        {
            float2 f0 = __half22float2(ls0);
            float2 f1 = __half22float2(ls1);
            l[0] += f0.x + f0.y;
            l[1] += f1.x + f1.y;
        }

        // ---- T += P @ c_tile (k=64 keys, N=40) ----
        const __half* ct_t = ct_s + (tt % 3) * CTSZ;
#pragma unroll
        for (int n = 0; n < 5; n++) {
            unsigned vb0[4], vb1[4];
            const __half* va = &ct_t[(n * 8 + l8) * CTS + mrow * 8];
            ldsm_x4(vb0[0], vb1[0], vb0[1], vb1[1], va);
            ldsm_x4(vb0[2], vb1[2], vb0[3], vb1[3], va + 32);
#pragma unroll
            for (int kc = 0; kc < 4; kc++)
                mma16816(T[n], pa[kc], vb0[kc], vb1[kc]);
        }

        // ---- end of run: O += T @ wv2t_{hp} (k=40) ----
        if (t == 15) {
            unsigned at16[2][4], at8a, at8b;
#pragma unroll
            for (int kc = 0; kc < 2; kc++) {
                at16[kc][0] = packh2(T[2 * kc][0],     T[2 * kc][1]);
                at16[kc][1] = packh2(T[2 * kc][2],     T[2 * kc][3]);
                at16[kc][2] = packh2(T[2 * kc + 1][0], T[2 * kc + 1][1]);
                at16[kc][3] = packh2(T[2 * kc + 1][2], T[2 * kc + 1][3]);
            }
            at8a = packh2(T[4][0], T[4][1]);
            at8b = packh2(T[4][2], T[4][3]);

            const __half* wvb = wv_s + (hp & 1) * WVSZ;
#pragma unroll
            for (int dt = 0; dt < 8; dt++) {
                unsigned wb0[2], wb1[2], wb8;
                const __half* wa = &wvb[(dt * 8 + l8) * 40 + mrow * 8];
                ldsm_x4(wb0[0], wb1[0], wb0[1], wb1[1], wa);
                ldsm_x1(wb8, &wvb[(dt * 8 + l8) * 40 + 32]);
                mma16816(O[dt], at16[0], wb0[0], wb1[0]);
                mma16816(O[dt], at16[1], wb0[1], wb1[1]);
                mma16808(O[dt], at8a, at8b, wb8);
            }
#pragma unroll
            for (int n = 0; n < 5; n++)
#pragma unroll
                for (int q = 0; q < 4; q++) T[n][q] = 0.f;
            __syncthreads();   // protect wv buffer before next run's prefetch
        }
    }

    // ---- epilogue: normalize + store ----
#pragma unroll
    for (int h2 = 0; h2 < 2; h2++) {
        float lt = l[h2];
        lt += __shfl_xor_sync(0xffffffffu, lt, 1);
        lt += __shfl_xor_sync(0xffffffffu, lt, 2);
        float inv = 1.0f / lt;
        int n = n0 + w * 16 + gi + h2 * 8;
        float* orow = g_attn + ((size_t)((b << 10) | n)) * 512 + h * 64;
#pragma unroll
        for (int dt = 0; dt < 8; dt++) {
            float2 o2 = make_float2(O[dt][2 * h2] * inv, O[dt][2 * h2 + 1] * inv);
            *reinterpret_cast<float2*>(orow + dt * 8 + tig * 2) = o2;
        }
    }
}

// ---------------------------------------------------------------------------
// Output projection: out = g_attn (4096x512) @ wo (512x256) + bo (fp32)
// ---------------------------------------------------------------------------
__global__ __launch_bounds__(256) void out_gemm(
    const float* __restrict__ wo, const float* __restrict__ bo,
    float* __restrict__ out) {
    __shared__ float As[32][68];
    __shared__ float Bs[32][64];

    const int bm0 = blockIdx.x * 64;
    const int bn0 = blockIdx.y * 64;
    const int tid = threadIdx.x;
    const int tx = tid & 15, ty = tid >> 4;

    float acc[4][4];
#pragma unroll
    for (int i = 0; i < 4; i++)
#pragma unroll
        for (int j = 0; j < 4; j++) acc[i][j] = 0.f;

    for (int kb = 0; kb < 16; kb++) {
#pragma unroll
        for (int i = 0; i < 2; i++) {
            int t = tid + i * 256;
            int ra = t >> 3, ca = (t & 7) * 4;
            float4 v = *reinterpret_cast<const float4*>(
                g_attn + (size_t)(bm0 + ra) * 512 + kb * 32 + ca);
            As[ca + 0][ra] = v.x;
            As[ca + 1][ra] = v.y;
            As[ca + 2][ra] = v.z;
            As[ca + 3][ra] = v.w;
            int rb2 = t >> 4, cb2 = (t & 15) * 4;
            *reinterpret_cast<float4*>(&Bs[rb2][cb2]) =
                *reinterpret_cast<const float4*>(wo + (size_t)(kb * 32 + rb2) * 256 + bn0 + cb2);
        }
        __syncthreads();
#pragma unroll
        for (int k = 0; k < 32; k++) {
            float4 av = *reinterpret_cast<const float4*>(&As[k][ty * 4]);
            float4 bv = *reinterpret_cast<const float4*>(&Bs[k][tx * 4]);
            float a[4] = {av.x, av.y, av.z, av.w};
#pragma unroll
            for (int i = 0; i < 4; i++) {
                acc[i][0] += a[i] * bv.x;
                acc[i][1] += a[i] * bv.y;
                acc[i][2] += a[i] * bv.z;
                acc[i][3] += a[i] * bv.w;
            }
        }
        __syncthreads();
    }

    float4 bias = *reinterpret_cast<const float4*>(bo + bn0 + tx * 4);
#pragma unroll
    for (int i = 0; i < 4; i++) {
        float4 o;
        o.x = acc[i][0] + bias.x;
        o.y = acc[i][1] + bias.y;
        o.z = acc[i][2] + bias.z;
        o.w = acc[i][3] + bias.w;
        *reinterpret_cast<float4*>(out + (size_t)(bm0 + ty * 4 + i) * 256 + bn0 + tx * 4) = o;
    }
}

// ---------------------------------------------------------------------------
extern "C" void kernel_launch(void* const* d_in, const int* in_sizes, int n_in,
                              void* d_out, int out_size) {
    const float* x   = (const float*)d_in[0];
    const float* wq1 = (const float*)d_in[1];
    const float* wq2 = (const float*)d_in[2];
    const float* wk1 = (const float*)d_in[3];
    const float* wk2 = (const float*)d_in[4];
    const float* wv1 = (const float*)d_in[5];
    const float* wv2 = (const float*)d_in[6];
    const float* wo  = (const float*)d_in[7];
    const float* bo  = (const float*)d_in[8];
    float* out = (float*)d_out;

    cudaFuncSetAttribute(attn_kernel, cudaFuncAttributeMaxDynamicSharedMemorySize,
                         ATTN_SMEM);
    cudaFuncSetAttribute(ahat_kernel, cudaFuncAttributeMaxDynamicSharedMemorySize,
                         AHAT_SMEM);

    proj_kernel<<<dim3(128, 3), 256>>>(x, wq1, wk1, wv1);
    wv2t_kernel<<<8, 256>>>(wv2);
    ahat_kernel<<<256, 256, AHAT_SMEM>>>(wq2, wk2);
    attn_kernel<<<dim3(64, 4), 256, ATTN_SMEM>>>();
    out_gemm<<<dim3(64, 4), 256>>>(wo, bo, out);
}

// round 7
// speedup vs baseline: 1.3342x; 1.2535x over previous
#include <cuda_runtime.h>
#include <cuda_fp16.h>
#include <cstdint>

#define NN    1024
#define QSZ   256
#define BOT   40

// ------------------------- scratch (no allocs allowed) -----------------------
__device__ __half g_ahalf[(size_t)4096 * 40];          // a = x@wq1 (fp16)
__device__ __half g_b[(size_t)4096 * 40];              // b = silu(x@wk1)
__device__ __half g_ct[(size_t)4 * 40 * 1024];         // c^T  [b][40][n]
__device__ __half g_gt[(size_t)64 * 1600];             // G^T per (h,hp)  [hh'][c][k]
__device__ __half g_ah[(size_t)4 * 64 * 1024 * 40];    // ahat [b][h][h'][n][40]
__device__ __half g_wv2t[(size_t)8 * 64 * 40];         // wv2^T per head [h][d][40]
__device__ __half g_attn16[(size_t)4096 * 512];        // attention out (fp16)
__device__ __half g_woT[(size_t)256 * 512];            // wo^T fp16 [n][k]

__device__ __forceinline__ float ex2f(float x) {
    float y;
    asm("ex2.approx.ftz.f32 %0, %1;" : "=f"(y) : "f"(x));
    return y;
}

__device__ __forceinline__ unsigned ex2h2(float a, float b) {
    __half2 h = __floats2half2_rn(a, b);
    unsigned u = *reinterpret_cast<unsigned*>(&h);
    unsigned r;
    asm("ex2.approx.f16x2 %0, %1;" : "=r"(r) : "r"(u));
    return r;
}

__device__ __forceinline__ unsigned packh2(float a, float b) {
    __half2 h = __floats2half2_rn(a, b);
    return *reinterpret_cast<unsigned*>(&h);
}

__device__ __forceinline__ void mma16816(float (&c)[4], const unsigned (&a)[4],
                                         unsigned b0, unsigned b1) {
    asm volatile(
        "mma.sync.aligned.m16n8k16.row.col.f32.f16.f16.f32 "
        "{%0,%1,%2,%3}, {%4,%5,%6,%7}, {%8,%9}, {%0,%1,%2,%3};\n"
        : "+f"(c[0]), "+f"(c[1]), "+f"(c[2]), "+f"(c[3])
        : "r"(a[0]), "r"(a[1]), "r"(a[2]), "r"(a[3]), "r"(b0), "r"(b1));
}

__device__ __forceinline__ void mma16808(float (&c)[4], unsigned a0, unsigned a1,
                                         unsigned b0) {
    asm volatile(
        "mma.sync.aligned.m16n8k8.row.col.f32.f16.f16.f32 "
        "{%0,%1,%2,%3}, {%4,%5}, {%6}, {%0,%1,%2,%3};\n"
        : "+f"(c[0]), "+f"(c[1]), "+f"(c[2]), "+f"(c[3])
        : "r"(a0), "r"(a1), "r"(b0));
}

__device__ __forceinline__ void cp16(void* s, const void* g) {
    unsigned sa = (unsigned)__cvta_generic_to_shared(s);
    asm volatile("cp.async.cg.shared.global [%0], [%1], 16;\n" :: "r"(sa), "l"(g));
}

__device__ __forceinline__ void ldsm_x4(unsigned& r0, unsigned& r1, unsigned& r2,
                                        unsigned& r3, const void* p) {
    unsigned a = (unsigned)__cvta_generic_to_shared(p);
    asm volatile("ldmatrix.sync.aligned.m8n8.x4.shared.b16 {%0,%1,%2,%3}, [%4];"
                 : "=r"(r0), "=r"(r1), "=r"(r2), "=r"(r3) : "r"(a));
}

__device__ __forceinline__ void ldsm_x2(unsigned& r0, unsigned& r1, const void* p) {
    unsigned a = (unsigned)__cvta_generic_to_shared(p);
    asm volatile("ldmatrix.sync.aligned.m8n8.x2.shared.b16 {%0,%1}, [%2];"
                 : "=r"(r0), "=r"(r1) : "r"(a));
}

__device__ __forceinline__ void ldsm_x1(unsigned& r0, const void* p) {
    unsigned a = (unsigned)__cvta_generic_to_shared(p);
    asm volatile("ldmatrix.sync.aligned.m8n8.x1.shared.b16 {%0}, [%1];"
                 : "=r"(r0) : "r"(a));
}

// ---------------------------------------------------------------------------
// proj v3: thread-per-row, broadcast weights. grid (16, 12):
//   blockIdx.y: colgroup cg -> proj = cg/4, cols (cg%4)*10 .. +9
// ---------------------------------------------------------------------------
__global__ __launch_bounds__(256) void proj_kernel(
    const float* __restrict__ x,
    const float* __restrict__ wq1, const float* __restrict__ wk1,
    const float* __restrict__ wv1) {
    __shared__ float sWT[10][256];

    const int cg = blockIdx.y;
    const int proj = cg >> 2;
    const int c0 = (cg & 3) * 10;
    const float* w1 = (proj == 0) ? wq1 : (proj == 1 ? wk1 : wv1);
    const int tid = threadIdx.x;

    for (int idx = tid; idx < 2560; idx += 256) {
        int k = idx / 10, c = idx % 10;
        sWT[c][k] = w1[k * 40 + c0 + c];
    }
    __syncthreads();

    const int row = blockIdx.x * 256 + tid;
    const float4* xr = reinterpret_cast<const float4*>(x + (size_t)row * QSZ);

    float acc[10];
#pragma unroll
    for (int c = 0; c < 10; c++) acc[c] = 0.f;

#pragma unroll 4
    for (int k4 = 0; k4 < 64; k4++) {
        float4 xv = xr[k4];
#pragma unroll
        for (int c = 0; c < 10; c++) {
            float4 wv = *reinterpret_cast<const float4*>(&sWT[c][k4 * 4]);
            acc[c] += xv.x * wv.x + xv.y * wv.y + xv.z * wv.z + xv.w * wv.w;
        }
    }

    if (proj == 0) {
        __half2* dst = reinterpret_cast<__half2*>(g_ahalf + (size_t)row * 40 + c0);
#pragma unroll
        for (int i = 0; i < 5; i++)
            dst[i] = __floats2half2_rn(acc[2 * i], acc[2 * i + 1]);
    } else if (proj == 1) {
#pragma unroll
        for (int c = 0; c < 10; c++)
            acc[c] = acc[c] / (1.0f + __expf(-acc[c]));
        __half2* dst = reinterpret_cast<__half2*>(g_b + (size_t)row * 40 + c0);
#pragma unroll
        for (int i = 0; i < 5; i++)
            dst[i] = __floats2half2_rn(acc[2 * i], acc[2 * i + 1]);
    } else {
        const int bb = row >> 10, n = row & 1023;
#pragma unroll
        for (int c = 0; c < 10; c++)
            g_ct[((size_t)bb * 40 + c0 + c) * 1024 + n] = __float2half_rn(acc[c]);
    }
}

// ---------------------------------------------------------------------------
// gmat: G^T[hh'][c][k] = fp16( SCALE * sum_d wq2[k][h*64+d] * wk2[c][hp*64+d] )
// ---------------------------------------------------------------------------
__global__ __launch_bounds__(256) void gmat_kernel(
    const float* __restrict__ wq2, const float* __restrict__ wk2) {
    __shared__ float sQ[40][65];
    __shared__ float sK[40][65];

    const int h = blockIdx.x >> 3, hp = blockIdx.x & 7;
    const int tid = threadIdx.x;

    for (int idx = tid; idx < 2560; idx += 256) {
        int k = idx >> 6, d = idx & 63;
        sQ[k][d] = wq2[(size_t)k * 512 + h * 64 + d];
        sK[k][d] = wk2[(size_t)k * 512 + hp * 64 + d];
    }
    __syncthreads();

    const float SCALE = 0.125f * 1.4426950408889634f;  // d^-0.5 * log2(e)
    for (int idx = tid; idx < 1600; idx += 256) {
        int c = idx / 40, k = idx % 40;
        float s = 0.f;
#pragma unroll 8
        for (int d = 0; d < 64; d++) s += sQ[k][d] * sK[c][d];
        g_gt[(size_t)blockIdx.x * 1600 + c * 40 + k] = __float2half_rn(s * SCALE);
    }
}

// ---------------------------------------------------------------------------
// wv2t: g_wv2t[h][d][k] = wv2[k][h*64+d]
// ---------------------------------------------------------------------------
__global__ __launch_bounds__(256) void wv2t_kernel(const float* __restrict__ wv2) {
    const int h = blockIdx.x;
    for (int idx = threadIdx.x; idx < 64 * 40; idx += 256) {
        int d = idx / 40, k = idx % 40;
        g_wv2t[(size_t)h * 2560 + d * 40 + k] =
            __float2half_rn(wv2[(size_t)k * 512 + h * 64 + d]);
    }
}

// ---------------------------------------------------------------------------
// wot: g_woT[n][k] = wo[k][n] fp16
// ---------------------------------------------------------------------------
__global__ __launch_bounds__(256) void wot_kernel(const float* __restrict__ wo) {
    int idx = blockIdx.x * 256 + threadIdx.x;  // 131072
    int n = idx >> 9, k = idx & 511;
    g_woT[idx] = __float2half_rn(wo[(size_t)k * 256 + n]);
}

// ---------------------------------------------------------------------------
// ahat via fp16 mma: per block (b,h,hp): ahat = a @ G  (M=1024, N=40, K=40)
// ---------------------------------------------------------------------------
#define AH_SMEM ((40960 + 1600) * 2)   // 85120 bytes

__global__ __launch_bounds__(256, 2) void ahat_kernel() {
    extern __shared__ __half sh[];
    __half* sA = sh;             // [1024][40]
    __half* sG = sh + 40960;     // [40][40]

    const int bx = blockIdx.x;   // bb*64 + h*8 + hp
    const int bb = bx >> 6;
    const int tid = threadIdx.x;
    const int w = tid >> 5, lane = tid & 31;
    const int gi = lane >> 2, tig = lane & 3;
    const int l8 = lane & 7, mrow = lane >> 3;

    const __half* ga = g_ahalf + (size_t)bb * 1024 * 40;
    for (int idx = tid; idx < 5120; idx += 256) cp16(&sA[idx * 8], ga + idx * 8);
    const __half* gg = g_gt + (size_t)(bx & 63) * 1600;
    for (int idx = tid; idx < 200; idx += 256) cp16(&sG[idx * 8], gg + idx * 8);
    asm volatile("cp.async.commit_group;\n");
    asm volatile("cp.async.wait_group 0;\n");
    __syncthreads();

    // B frags (G^T), hoisted across all m-tiles
    unsigned gb0[5][2], gb1[5][2], gb8[5];
#pragma unroll
    for (int nt = 0; nt < 5; nt++) {
        ldsm_x4(gb0[nt][0], gb1[nt][0], gb0[nt][1], gb1[nt][1],
                &sG[(nt * 8 + l8) * 40 + mrow * 8]);
        ldsm_x1(gb8[nt], &sG[(nt * 8 + l8) * 40 + 32]);
    }

    __half* dst = g_ah + (size_t)bx * 1024 * 40;
    const int ar = (lane & 15);
    const int ac = (lane >> 4) * 8;

#pragma unroll
    for (int mt = 0; mt < 8; mt++) {
        const int m0 = w * 128 + mt * 16;
        unsigned a16[2][4], a8[2];
        ldsm_x4(a16[0][0], a16[0][1], a16[0][2], a16[0][3],
                &sA[(m0 + ar) * 40 + ac]);
        ldsm_x4(a16[1][0], a16[1][1], a16[1][2], a16[1][3],
                &sA[(m0 + ar) * 40 + 16 + ac]);
        ldsm_x2(a8[0], a8[1], &sA[(m0 + ar) * 40 + 32]);

        float acc[5][4];
#pragma unroll
        for (int nt = 0; nt < 5; nt++)
#pragma unroll
            for (int q = 0; q < 4; q++) acc[nt][q] = 0.f;

#pragma unroll
        for (int nt = 0; nt < 5; nt++) {
            mma16816(acc[nt], a16[0], gb0[nt][0], gb1[nt][0]);
            mma16816(acc[nt], a16[1], gb0[nt][1], gb1[nt][1]);
            mma16808(acc[nt], a8[0], a8[1], gb8[nt]);
        }

#pragma unroll
        for (int nt = 0; nt < 5; nt++) {
            *reinterpret_cast<unsigned*>(&dst[(size_t)(m0 + gi) * 40 + nt * 8 + tig * 2]) =
                packh2(acc[nt][0], acc[nt][1]);
            *reinterpret_cast<unsigned*>(&dst[(size_t)(m0 + gi + 8) * 40 + nt * 8 + tig * 2]) =
                packh2(acc[nt][2], acc[nt][3]);
        }
    }
}

// ---------------------------------------------------------------------------
// Flash attention (unchanged mainloop from R6; epilogue now writes fp16)
// ---------------------------------------------------------------------------
#define CTS   72
#define CTSZ  (40 * CTS)
#define WVSZ  2560
#define B_HALVES 40960
#define ATTN_SMEM ((B_HALVES + 3 * CTSZ + 2 * WVSZ) * 2)

__global__ __launch_bounds__(256, 2) void attn_kernel() {
    extern __shared__ __half sm[];
    __half* b_s  = sm;
    __half* ct_s = sm + B_HALVES;
    __half* wv_s = sm + B_HALVES + 3 * CTSZ;

    const int b = blockIdx.y;
    const int qt = blockIdx.x;
    const int h = qt >> 3;
    const int n0 = (qt & 7) * 128;
    const int tid = threadIdx.x;
    const int w = tid >> 5, lane = tid & 31;
    const int gi = lane >> 2, tig = lane & 3;
    const int l8 = lane & 7, mrow = lane >> 3;

    const __half* gb = g_b + (size_t)b * 1024 * 40;
    const __half* gct = g_ct + (size_t)b * 40 * 1024;

    for (int idx = tid; idx < 5120; idx += 256)
        cp16(&b_s[idx * 8], gb + idx * 8);
    for (int idx = tid; idx < 320; idx += 256) {
        int row = idx >> 3, seg = idx & 7;
        cp16(&ct_s[row * CTS + seg * 8], gct + (size_t)row * 1024 + seg * 8);
    }
    for (int idx = tid; idx < 320; idx += 256)
        cp16(&wv_s[idx * 8], g_wv2t + idx * 8);
    asm volatile("cp.async.commit_group;\n");
    asm volatile("cp.async.wait_group 0;\n");
    __syncthreads();

    float m[2] = {-1e30f, -1e30f}, l[2] = {0.f, 0.f};
    float O[8][4], T[5][4];
#pragma unroll
    for (int dt = 0; dt < 8; dt++)
#pragma unroll
        for (int q = 0; q < 4; q++) O[dt][q] = 0.f;
#pragma unroll
    for (int n = 0; n < 5; n++)
#pragma unroll
        for (int q = 0; q < 4; q++) T[n][q] = 0.f;

    unsigned qf[2][4], qf8[2];

    for (int tt = 0; tt < 128; tt++) {
        const int hp = tt >> 4, t = tt & 15;

        if (tt < 127) {
            int ntile = (tt + 1) & 15;
            __half* dc = ct_s + ((tt + 1) % 3) * CTSZ;
            for (int idx = tid; idx < 320; idx += 256) {
                int row = idx >> 3, seg = idx & 7;
                cp16(&dc[row * CTS + seg * 8],
                     gct + (size_t)row * 1024 + ntile * 64 + seg * 8);
            }
            if (t == 0 && hp < 7) {
                __half* dw = wv_s + ((hp + 1) & 1) * WVSZ;
                const __half* gw = g_wv2t + (size_t)(hp + 1) * 2560;
                for (int idx = tid; idx < 320; idx += 256)
                    cp16(&dw[idx * 8], gw + idx * 8);
            }
            asm volatile("cp.async.commit_group;\n");
            asm volatile("cp.async.wait_group 1;\n");
        } else {
            asm volatile("cp.async.wait_group 0;\n");
        }
        __syncthreads();

        if (t == 0) {
            const __half* ah = g_ah +
                ((size_t)((b * 8 + h) * 8 + hp) * 1024 + n0 + w * 16) * 40;
#pragma unroll
            for (int kc = 0; kc < 2; kc++) {
                int cc = kc * 16 + tig * 2;
                qf[kc][0] = *reinterpret_cast<const unsigned*>(ah + gi * 40 + cc);
                qf[kc][1] = *reinterpret_cast<const unsigned*>(ah + (gi + 8) * 40 + cc);
                qf[kc][2] = *reinterpret_cast<const unsigned*>(ah + gi * 40 + cc + 8);
                qf[kc][3] = *reinterpret_cast<const unsigned*>(ah + (gi + 8) * 40 + cc + 8);
            }
            int cc2 = 32 + tig * 2;
            qf8[0] = *reinterpret_cast<const unsigned*>(ah + gi * 40 + cc2);
            qf8[1] = *reinterpret_cast<const unsigned*>(ah + (gi + 8) * 40 + cc2);
        }

        float S[8][4];
#pragma unroll
        for (int nt = 0; nt < 8; nt++)
#pragma unroll
            for (int q = 0; q < 4; q++) S[nt][q] = 0.f;

#pragma unroll
        for (int nt = 0; nt < 8; nt++) {
            unsigned kb0[2], kb1[2], kb8;
            const __half* ka = &b_s[(t * 64 + nt * 8 + l8) * 40 + mrow * 8];
            ldsm_x4(kb0[0], kb1[0], kb0[1], kb1[1], ka);
            ldsm_x1(kb8, &b_s[(t * 64 + nt * 8 + l8) * 40 + 32]);
            mma16816(S[nt], qf[0], kb0[0], kb1[0]);
            mma16816(S[nt], qf[1], kb0[1], kb1[1]);
            mma16808(S[nt], qf8[0], qf8[1], kb8);
        }

#pragma unroll
        for (int h2 = 0; h2 < 2; h2++) {
            float tm = -1e30f;
#pragma unroll
            for (int nt = 0; nt < 8; nt++)
                tm = fmaxf(tm, fmaxf(S[nt][2 * h2], S[nt][2 * h2 + 1]));
            tm = fmaxf(tm, __shfl_xor_sync(0xffffffffu, tm, 1));
            tm = fmaxf(tm, __shfl_xor_sync(0xffffffffu, tm, 2));
            if (tm > m[h2]) {
                float al = ex2f(m[h2] - tm);
                m[h2] = tm;
                l[h2] *= al;
#pragma unroll
                for (int dt = 0; dt < 8; dt++) {
                    O[dt][2 * h2] *= al;
                    O[dt][2 * h2 + 1] *= al;
                }
#pragma unroll
                for (int n = 0; n < 5; n++) {
                    T[n][2 * h2] *= al;
                    T[n][2 * h2 + 1] *= al;
                }
            }
        }

        unsigned pa[4][4];
        __half2 ls0 = __floats2half2_rn(0.f, 0.f);
        __half2 ls1 = ls0;
#pragma unroll
        for (int nt = 0; nt < 8; nt++) {
            unsigned p01 = ex2h2(S[nt][0] - m[0], S[nt][1] - m[0]);
            unsigned p23 = ex2h2(S[nt][2] - m[1], S[nt][3] - m[1]);
            ls0 = __hadd2(ls0, *reinterpret_cast<__half2*>(&p01));
            ls1 = __hadd2(ls1, *reinterpret_cast<__half2*>(&p23));
            pa[nt >> 1][(nt & 1) * 2]     = p01;
            pa[nt >> 1][(nt & 1) * 2 + 1] = p23;
        }
        {
            float2 f0 = __half22float2(ls0);
            float2 f1 = __half22float2(ls1);
            l[0] += f0.x + f0.y;
            l[1] += f1.x + f1.y;
        }

        const __half* ct_t = ct_s + (tt % 3) * CTSZ;
#pragma unroll
        for (int n = 0; n < 5; n++) {
            unsigned vb0[4], vb1[4];
            const __half* va = &ct_t[(n * 8 + l8) * CTS + mrow * 8];
            ldsm_x4(vb0[0], vb1[0], vb0[1], vb1[1], va);
            ldsm_x4(vb0[2], vb1[2], vb0[3], vb1[3], va + 32);
#pragma unroll
            for (int kc = 0; kc < 4; kc++)
                mma16816(T[n], pa[kc], vb0[kc], vb1[kc]);
        }

        if (t == 15) {
            unsigned at16[2][4], at8a, at8b;
#pragma unroll
            for (int kc = 0; kc < 2; kc++) {
                at16[kc][0] = packh2(T[2 * kc][0],     T[2 * kc][1]);
                at16[kc][1] = packh2(T[2 * kc][2],     T[2 * kc][3]);
                at16[kc][2] = packh2(T[2 * kc + 1][0], T[2 * kc + 1][1]);
                at16[kc][3] = packh2(T[2 * kc + 1][2], T[2 * kc + 1][3]);
            }
            at8a = packh2(T[4][0], T[4][1]);
            at8b = packh2(T[4][2], T[4][3]);

            const __half* wvb = wv_s + (hp & 1) * WVSZ;
#pragma unroll
            for (int dt = 0; dt < 8; dt++) {
                unsigned wb0[2], wb1[2], wb8;
                const __half* wa = &wvb[(dt * 8 + l8) * 40 + mrow * 8];
                ldsm_x4(wb0[0], wb1[0], wb0[1], wb1[1], wa);
                ldsm_x1(wb8, &wvb[(dt * 8 + l8) * 40 + 32]);
                mma16816(O[dt], at16[0], wb0[0], wb1[0]);
                mma16816(O[dt], at16[1], wb0[1], wb1[1]);
                mma16808(O[dt], at8a, at8b, wb8);
            }
#pragma unroll
            for (int n = 0; n < 5; n++)
#pragma unroll
                for (int q = 0; q < 4; q++) T[n][q] = 0.f;
            __syncthreads();
        }
    }

    // epilogue: normalize + store fp16
#pragma unroll
    for (int h2 = 0; h2 < 2; h2++) {
        float lt = l[h2];
        lt += __shfl_xor_sync(0xffffffffu, lt, 1);
        lt += __shfl_xor_sync(0xffffffffu, lt, 2);
        float inv = 1.0f / lt;
        int n = n0 + w * 16 + gi + h2 * 8;
        __half* orow = g_attn16 + ((size_t)((b << 10) | n)) * 512 + h * 64;
#pragma unroll
        for (int dt = 0; dt < 8; dt++) {
            *reinterpret_cast<unsigned*>(orow + dt * 8 + tig * 2) =
                packh2(O[dt][2 * h2] * inv, O[dt][2 * h2 + 1] * inv);
        }
    }
}

// ---------------------------------------------------------------------------
// out_gemm via fp16 mma: out = g_attn16 (4096x512) @ wo (512x256) + bo
// CTA: 128 thr (4 warps), tile 64x64. grid (64, 4).
// ---------------------------------------------------------------------------
__global__ __launch_bounds__(128) void out_gemm(
    const float* __restrict__ bo, float* __restrict__ out) {
    __shared__ __half sA2[64 * 72];
    __shared__ __half sB2[64 * 72];

    const int bm0 = blockIdx.x * 64;
    const int bn0 = blockIdx.y * 64;
    const int tid = threadIdx.x;
    const int w = tid >> 5, lane = tid & 31;
    const int gi = lane >> 2, tig = lane & 3;
    const int l8 = lane & 7, mrow = lane >> 3;

    float acc[8][4];
#pragma unroll
    for (int nt = 0; nt < 8; nt++)
#pragma unroll
        for (int q = 0; q < 4; q++) acc[nt][q] = 0.f;

    const int ar = (lane & 15);
    const int ac = (lane >> 4) * 8;

    for (int kc = 0; kc < 8; kc++) {
        __syncthreads();
        for (int idx = tid; idx < 512; idx += 128) {
            int r = idx >> 3, s = idx & 7;
            cp16(&sA2[r * 72 + s * 8],
                 g_attn16 + (size_t)(bm0 + r) * 512 + kc * 64 + s * 8);
            cp16(&sB2[r * 72 + s * 8],
                 g_woT + (size_t)(bn0 + r) * 512 + kc * 64 + s * 8);
        }
        asm volatile("cp.async.commit_group;\n");
        asm volatile("cp.async.wait_group 0;\n");
        __syncthreads();

        const int m0 = w * 16;
#pragma unroll
        for (int ksp = 0; ksp < 2; ksp++) {
            unsigned af0[4], af1[4];
            ldsm_x4(af0[0], af0[1], af0[2], af0[3],
                    &sA2[(m0 + ar) * 72 + ksp * 32 + ac]);
            ldsm_x4(af1[0], af1[1], af1[2], af1[3],
                    &sA2[(m0 + ar) * 72 + ksp * 32 + 16 + ac]);
#pragma unroll
            for (int nt = 0; nt < 8; nt++) {
                unsigned b0a, b1a, b0b, b1b;
                ldsm_x4(b0a, b1a, b0b, b1b,
                        &sB2[(nt * 8 + l8) * 72 + ksp * 32 + mrow * 8]);
                mma16816(acc[nt], af0, b0a, b1a);
                mma16816(acc[nt], af1, b0b, b1b);
            }
        }
    }

    const int r0 = bm0 + w * 16 + gi;
#pragma unroll
    for (int nt = 0; nt < 8; nt++) {
        int col = bn0 + nt * 8 + tig * 2;
        float b0 = bo[col], b1 = bo[col + 1];
        float2 o0 = make_float2(acc[nt][0] + b0, acc[nt][1] + b1);
        float2 o1 = make_float2(acc[nt][2] + b0, acc[nt][3] + b1);
        *reinterpret_cast<float2*>(out + (size_t)r0 * 256 + col) = o0;
        *reinterpret_cast<float2*>(out + (size_t)(r0 + 8) * 256 + col) = o1;
    }
}

// ---------------------------------------------------------------------------
extern "C" void kernel_launch(void* const* d_in, const int* in_sizes, int n_in,
                              void* d_out, int out_size) {
    const float* x   = (const float*)d_in[0];
    const float* wq1 = (const float*)d_in[1];
    const float* wq2 = (const float*)d_in[2];
    const float* wk1 = (const float*)d_in[3];
    const float* wk2 = (const float*)d_in[4];
    const float* wv1 = (const float*)d_in[5];
    const float* wv2 = (const float*)d_in[6];
    const float* wo  = (const float*)d_in[7];
    const float* bo  = (const float*)d_in[8];
    float* out = (float*)d_out;

    cudaFuncSetAttribute(attn_kernel, cudaFuncAttributeMaxDynamicSharedMemorySize,
                         ATTN_SMEM);
    cudaFuncSetAttribute(ahat_kernel, cudaFuncAttributeMaxDynamicSharedMemorySize,
                         AH_SMEM);

    proj_kernel<<<dim3(16, 12), 256>>>(x, wq1, wk1, wv1);
    gmat_kernel<<<64, 256>>>(wq2, wk2);
    wv2t_kernel<<<8, 256>>>(wv2);
    wot_kernel<<<512, 256>>>(wo);
    ahat_kernel<<<256, 256, AH_SMEM>>>();
    attn_kernel<<<dim3(64, 4), 256, ATTN_SMEM>>>();
    out_gemm<<<dim3(64, 4), 128>>>(bo, out);
}

// round 8
// speedup vs baseline: 1.5059x; 1.1287x over previous
#include <cuda_runtime.h>
#include <cuda_fp16.h>
#include <cstdint>

#define NN    1024
#define QSZ   256
#define BOT   40

// ------------------------- scratch (no allocs allowed) -----------------------
__device__ __half g_ahalf[(size_t)4096 * 40];          // a = x@wq1 (fp16)
__device__ __half g_b[(size_t)4096 * 40];              // b = silu(x@wk1)
__device__ __half g_ct[(size_t)4 * 40 * 1024];         // c^T  [b][40][n]
__device__ __half g_gt[(size_t)64 * 1600];             // G^T per (h,hp)  [hh'][c][k]
__device__ __half g_ah[(size_t)4 * 64 * 1024 * 40];    // ahat [b][h][h'][n][40]
__device__ __half g_wv2t[(size_t)8 * 64 * 40];         // wv2^T per head [h][d][40]
__device__ __half g_attn16[(size_t)4096 * 512];        // attention out (fp16)
__device__ __half g_woT[(size_t)256 * 512];            // wo^T fp16 [n][k]

__device__ __forceinline__ float ex2f(float x) {
    float y;
    asm("ex2.approx.ftz.f32 %0, %1;" : "=f"(y) : "f"(x));
    return y;
}

__device__ __forceinline__ unsigned ex2h2(float a, float b) {
    __half2 h = __floats2half2_rn(a, b);
    unsigned u = *reinterpret_cast<unsigned*>(&h);
    unsigned r;
    asm("ex2.approx.f16x2 %0, %1;" : "=r"(r) : "r"(u));
    return r;
}

__device__ __forceinline__ unsigned packh2(float a, float b) {
    __half2 h = __floats2half2_rn(a, b);
    return *reinterpret_cast<unsigned*>(&h);
}

__device__ __forceinline__ void mma16816(float (&c)[4], const unsigned (&a)[4],
                                         unsigned b0, unsigned b1) {
    asm volatile(
        "mma.sync.aligned.m16n8k16.row.col.f32.f16.f16.f32 "
        "{%0,%1,%2,%3}, {%4,%5,%6,%7}, {%8,%9}, {%0,%1,%2,%3};\n"
        : "+f"(c[0]), "+f"(c[1]), "+f"(c[2]), "+f"(c[3])
        : "r"(a[0]), "r"(a[1]), "r"(a[2]), "r"(a[3]), "r"(b0), "r"(b1));
}

__device__ __forceinline__ void mma16808(float (&c)[4], unsigned a0, unsigned a1,
                                         unsigned b0) {
    asm volatile(
        "mma.sync.aligned.m16n8k8.row.col.f32.f16.f16.f32 "
        "{%0,%1,%2,%3}, {%4,%5}, {%6}, {%0,%1,%2,%3};\n"
        : "+f"(c[0]), "+f"(c[1]), "+f"(c[2]), "+f"(c[3])
        : "r"(a0), "r"(a1), "r"(b0));
}

__device__ __forceinline__ void cp16(void* s, const void* g) {
    unsigned sa = (unsigned)__cvta_generic_to_shared(s);
    asm volatile("cp.async.cg.shared.global [%0], [%1], 16;\n" :: "r"(sa), "l"(g));
}

__device__ __forceinline__ void ldsm_x4(unsigned& r0, unsigned& r1, unsigned& r2,
                                        unsigned& r3, const void* p) {
    unsigned a = (unsigned)__cvta_generic_to_shared(p);
    asm volatile("ldmatrix.sync.aligned.m8n8.x4.shared.b16 {%0,%1,%2,%3}, [%4];"
                 : "=r"(r0), "=r"(r1), "=r"(r2), "=r"(r3) : "r"(a));
}

__device__ __forceinline__ void ldsm_x2(unsigned& r0, unsigned& r1, const void* p) {
    unsigned a = (unsigned)__cvta_generic_to_shared(p);
    asm volatile("ldmatrix.sync.aligned.m8n8.x2.shared.b16 {%0,%1}, [%2];"
                 : "=r"(r0), "=r"(r1) : "r"(a));
}

// ---------------------------------------------------------------------------
// proj v3: thread-per-row, broadcast weights. grid (16, 12).
// ---------------------------------------------------------------------------
__global__ __launch_bounds__(256) void proj_kernel(
    const float* __restrict__ x,
    const float* __restrict__ wq1, const float* __restrict__ wk1,
    const float* __restrict__ wv1) {
    __shared__ float sWT[10][256];

    const int cg = blockIdx.y;
    const int proj = cg >> 2;
    const int c0 = (cg & 3) * 10;
    const float* w1 = (proj == 0) ? wq1 : (proj == 1 ? wk1 : wv1);
    const int tid = threadIdx.x;

    for (int idx = tid; idx < 2560; idx += 256) {
        int k = idx / 10, c = idx % 10;
        sWT[c][k] = w1[k * 40 + c0 + c];
    }
    __syncthreads();

    const int row = blockIdx.x * 256 + tid;
    const float4* xr = reinterpret_cast<const float4*>(x + (size_t)row * QSZ);

    float acc[10];
#pragma unroll
    for (int c = 0; c < 10; c++) acc[c] = 0.f;

#pragma unroll 4
    for (int k4 = 0; k4 < 64; k4++) {
        float4 xv = xr[k4];
#pragma unroll
        for (int c = 0; c < 10; c++) {
            float4 wv = *reinterpret_cast<const float4*>(&sWT[c][k4 * 4]);
            acc[c] += xv.x * wv.x + xv.y * wv.y + xv.z * wv.z + xv.w * wv.w;
        }
    }

    if (proj == 0) {
        __half2* dst = reinterpret_cast<__half2*>(g_ahalf + (size_t)row * 40 + c0);
#pragma unroll
        for (int i = 0; i < 5; i++)
            dst[i] = __floats2half2_rn(acc[2 * i], acc[2 * i + 1]);
    } else if (proj == 1) {
#pragma unroll
        for (int c = 0; c < 10; c++)
            acc[c] = acc[c] / (1.0f + __expf(-acc[c]));
        __half2* dst = reinterpret_cast<__half2*>(g_b + (size_t)row * 40 + c0);
#pragma unroll
        for (int i = 0; i < 5; i++)
            dst[i] = __floats2half2_rn(acc[2 * i], acc[2 * i + 1]);
    } else {
        const int bb = row >> 10, n = row & 1023;
#pragma unroll
        for (int c = 0; c < 10; c++)
            g_ct[((size_t)bb * 40 + c0 + c) * 1024 + n] = __float2half_rn(acc[c]);
    }
}

// ---------------------------------------------------------------------------
// prep: fused gmat (bx<64) + wv2t (64..71) + wot (72..135)
// ---------------------------------------------------------------------------
__global__ __launch_bounds__(256) void prep_kernel(
    const float* __restrict__ wq2, const float* __restrict__ wk2,
    const float* __restrict__ wv2, const float* __restrict__ wo) {
    __shared__ float sQK[2][40][65];

    const int bx = blockIdx.x;
    const int tid = threadIdx.x;

    if (bx < 64) {
        const int h = bx >> 3, hp = bx & 7;
        for (int idx = tid; idx < 2560; idx += 256) {
            int k = idx >> 6, d = idx & 63;
            sQK[0][k][d] = wq2[(size_t)k * 512 + h * 64 + d];
            sQK[1][k][d] = wk2[(size_t)k * 512 + hp * 64 + d];
        }
        __syncthreads();
        const float SCALE = 0.125f * 1.4426950408889634f;
        for (int idx = tid; idx < 1600; idx += 256) {
            int c = idx / 40, k = idx % 40;
            float s = 0.f;
#pragma unroll 8
            for (int d = 0; d < 64; d++) s += sQK[0][k][d] * sQK[1][c][d];
            g_gt[(size_t)bx * 1600 + c * 40 + k] = __float2half_rn(s * SCALE);
        }
    } else if (bx < 72) {
        const int h = bx - 64;
        for (int idx = tid; idx < 64 * 40; idx += 256) {
            int d = idx / 40, k = idx % 40;
            g_wv2t[(size_t)h * 2560 + d * 40 + k] =
                __float2half_rn(wv2[(size_t)k * 512 + h * 64 + d]);
        }
    } else {
        const int base = (bx - 72) * 2048;
#pragma unroll
        for (int i = 0; i < 8; i++) {
            int idx = base + i * 256 + tid;
            int n = idx >> 9, k = idx & 511;
            g_woT[idx] = __float2half_rn(wo[(size_t)k * 256 + n]);
        }
    }
}

// ---------------------------------------------------------------------------
// ahat via fp16 mma (unchanged from R7)
// ---------------------------------------------------------------------------
#define AH_SMEM ((40960 + 1600) * 2)

__global__ __launch_bounds__(256, 2) void ahat_kernel() {
    extern __shared__ __half sh[];
    __half* sA = sh;
    __half* sG = sh + 40960;

    const int bx = blockIdx.x;
    const int bb = bx >> 6;
    const int tid = threadIdx.x;
    const int w = tid >> 5, lane = tid & 31;
    const int gi = lane >> 2, tig = lane & 3;
    const int l8 = lane & 7, mrow = lane >> 3;

    const __half* ga = g_ahalf + (size_t)bb * 1024 * 40;
    for (int idx = tid; idx < 5120; idx += 256) cp16(&sA[idx * 8], ga + idx * 8);
    const __half* gg = g_gt + (size_t)(bx & 63) * 1600;
    for (int idx = tid; idx < 200; idx += 256) cp16(&sG[idx * 8], gg + idx * 8);
    asm volatile("cp.async.commit_group;\n");
    asm volatile("cp.async.wait_group 0;\n");
    __syncthreads();

    unsigned gb0[5][2], gb1[5][2], gb8[5];
#pragma unroll
    for (int nt = 0; nt < 5; nt++) {
        ldsm_x4(gb0[nt][0], gb1[nt][0], gb0[nt][1], gb1[nt][1],
                &sG[(nt * 8 + l8) * 40 + mrow * 8]);
        unsigned dummy;
        ldsm_x2(gb8[nt], dummy, &sG[(nt * 8 + l8) * 40 + 32]);
        (void)dummy;
    }

    __half* dst = g_ah + (size_t)bx * 1024 * 40;
    const int ar = (lane & 15);
    const int ac = (lane >> 4) * 8;

#pragma unroll
    for (int mt = 0; mt < 8; mt++) {
        const int m0 = w * 128 + mt * 16;
        unsigned a16[2][4], a8[2];
        ldsm_x4(a16[0][0], a16[0][1], a16[0][2], a16[0][3],
                &sA[(m0 + ar) * 40 + ac]);
        ldsm_x4(a16[1][0], a16[1][1], a16[1][2], a16[1][3],
                &sA[(m0 + ar) * 40 + 16 + ac]);
        ldsm_x2(a8[0], a8[1], &sA[(m0 + ar) * 40 + 32]);

        float acc[5][4];
#pragma unroll
        for (int nt = 0; nt < 5; nt++)
#pragma unroll
            for (int q = 0; q < 4; q++) acc[nt][q] = 0.f;

#pragma unroll
        for (int nt = 0; nt < 5; nt++) {
            mma16816(acc[nt], a16[0], gb0[nt][0], gb1[nt][0]);
            mma16816(acc[nt], a16[1], gb0[nt][1], gb1[nt][1]);
            mma16808(acc[nt], a8[0], a8[1], gb8[nt]);
        }

#pragma unroll
        for (int nt = 0; nt < 5; nt++) {
            *reinterpret_cast<unsigned*>(&dst[(size_t)(m0 + gi) * 40 + nt * 8 + tig * 2]) =
                packh2(acc[nt][0], acc[nt][1]);
            *reinterpret_cast<unsigned*>(&dst[(size_t)(m0 + gi + 8) * 40 + nt * 8 + tig * 2]) =
                packh2(acc[nt][2], acc[nt][3]);
        }
    }
}

// ---------------------------------------------------------------------------
// Flash attention v4: barrier per tile-PAIR, l via ones-row tensor reduction,
// batched k8 fragments. 2 CTAs/SM.
// ---------------------------------------------------------------------------
#define CTS   72
#define CT_BUFSZ (41 * CTS)                 // 2952 halves
#define CT_REGION (4 * CT_BUFSZ + 7 * CTS)  // 12312 halves
#define WVSZ  2560
#define B_HALVES 40960
#define ATTN_SMEM ((B_HALVES + CT_REGION + WVSZ) * 2)   // 111,664 B

__global__ __launch_bounds__(256, 2) void attn_kernel() {
    extern __shared__ __half sm[];
    __half* b_s  = sm;                         // [1024][40]
    __half* ct_s = sm + B_HALVES;              // 4 bufs [41][72] (+tail pad)
    __half* wv_s = sm + B_HALVES + CT_REGION;  // [64][40]

    const int b = blockIdx.y;
    const int qt = blockIdx.x;
    const int h = qt >> 3;
    const int n0 = (qt & 7) * 128;
    const int tid = threadIdx.x;
    const int w = tid >> 5, lane = tid & 31;
    const int gi = lane >> 2, tig = lane & 3;
    const int l8 = lane & 7, mrow = lane >> 3;
    const int r8 = (lane >> 3) * 8 + (lane & 7);

    const __half* gb = g_b + (size_t)b * 1024 * 40;
    const __half* gct = g_ct + (size_t)b * 40 * 1024;

    // prologue: b + ct tiles 0,1 + wv(0)
    for (int idx = tid; idx < 5120; idx += 256)
        cp16(&b_s[idx * 8], gb + idx * 8);
#pragma unroll
    for (int pf = 0; pf < 2; pf++) {
        __half* dc = ct_s + pf * CT_BUFSZ;
        for (int idx = tid; idx < 320; idx += 256) {
            int row = idx >> 3, seg = idx & 7;
            cp16(&dc[row * CTS + seg * 8], gct + (size_t)row * 1024 + pf * 64 + seg * 8);
        }
    }
    for (int idx = tid; idx < 320; idx += 256)
        cp16(&wv_s[idx * 8], g_wv2t + idx * 8);
    asm volatile("cp.async.commit_group;\n");
    asm volatile("cp.async.wait_group 0;\n");
    // ones row (row 40) of all 4 ct buffers — written once, never overwritten
    if (tid < 128) {
        int bufi = tid >> 5, seg = tid & 31;
        *reinterpret_cast<unsigned*>(&ct_s[bufi * CT_BUFSZ + 40 * CTS + seg * 2]) =
            0x3C003C00u;
    }
    __syncthreads();

    float m[2] = {-1e30f, -1e30f}, l[2] = {0.f, 0.f};
    float O[8][4], T[6][4];
#pragma unroll
    for (int dt = 0; dt < 8; dt++)
#pragma unroll
        for (int q = 0; q < 4; q++) O[dt][q] = 0.f;
#pragma unroll
    for (int n = 0; n < 6; n++)
#pragma unroll
        for (int q = 0; q < 4; q++) T[n][q] = 0.f;

    unsigned qf[2][4], qf8[2];

    for (int tt = 0; tt < 128; tt += 2) {
        const int hp = tt >> 4;

        asm volatile("cp.async.wait_group 0;\n");
        __syncthreads();

        // issue prefetches for tiles tt+2, tt+3 (+ wv at run start)
        if (tt + 2 < 128) {
#pragma unroll
            for (int pf = 0; pf < 2; pf++) {
                int ntile = tt + 2 + pf;
                int key0 = (ntile & 15) * 64;
                __half* dc = ct_s + (ntile & 3) * CT_BUFSZ;
                for (int idx = tid; idx < 320; idx += 256) {
                    int row = idx >> 3, seg = idx & 7;
                    cp16(&dc[row * CTS + seg * 8],
                         gct + (size_t)row * 1024 + key0 + seg * 8);
                }
            }
        }
        if ((tt & 15) == 0 && tt > 0) {
            const __half* gw = g_wv2t + (size_t)hp * 2560;
            for (int idx = tid; idx < 320; idx += 256)
                cp16(&wv_s[idx * 8], gw + idx * 8);
        }
        asm volatile("cp.async.commit_group;\n");

        if ((tt & 15) == 0) {
            const __half* ah = g_ah +
                ((size_t)((b * 8 + h) * 8 + hp) * 1024 + n0 + w * 16) * 40;
#pragma unroll
            for (int kc = 0; kc < 2; kc++) {
                int cc = kc * 16 + tig * 2;
                qf[kc][0] = *reinterpret_cast<const unsigned*>(ah + gi * 40 + cc);
                qf[kc][1] = *reinterpret_cast<const unsigned*>(ah + (gi + 8) * 40 + cc);
                qf[kc][2] = *reinterpret_cast<const unsigned*>(ah + gi * 40 + cc + 8);
                qf[kc][3] = *reinterpret_cast<const unsigned*>(ah + (gi + 8) * 40 + cc + 8);
            }
            int cc2 = 32 + tig * 2;
            qf8[0] = *reinterpret_cast<const unsigned*>(ah + gi * 40 + cc2);
            qf8[1] = *reinterpret_cast<const unsigned*>(ah + (gi + 8) * 40 + cc2);
        }

#pragma unroll
        for (int sub = 0; sub < 2; sub++) {
            const int tile = tt + sub;
            const int t = tile & 15;
            const __half* ct_t = ct_s + (tile & 3) * CT_BUFSZ;

            // ---- S = ahat @ b^T (k=40) ----
            unsigned kb8v[8];
            ldsm_x4(kb8v[0], kb8v[1], kb8v[2], kb8v[3],
                    &b_s[(t * 64 + r8) * 40 + 32]);
            ldsm_x4(kb8v[4], kb8v[5], kb8v[6], kb8v[7],
                    &b_s[(t * 64 + 32 + r8) * 40 + 32]);

            float S[8][4];
#pragma unroll
            for (int nt = 0; nt < 8; nt++)
#pragma unroll
                for (int q = 0; q < 4; q++) S[nt][q] = 0.f;

#pragma unroll
            for (int nt = 0; nt < 8; nt++) {
                unsigned kb0[2], kb1[2];
                ldsm_x4(kb0[0], kb1[0], kb0[1], kb1[1],
                        &b_s[(t * 64 + nt * 8 + l8) * 40 + mrow * 8]);
                mma16816(S[nt], qf[0], kb0[0], kb1[0]);
                mma16816(S[nt], qf[1], kb0[1], kb1[1]);
                mma16808(S[nt], qf8[0], qf8[1], kb8v[nt]);
            }

            // ---- online softmax (log2 domain) ----
#pragma unroll
            for (int h2 = 0; h2 < 2; h2++) {
                float tm = -1e30f;
#pragma unroll
                for (int nt = 0; nt < 8; nt++)
                    tm = fmaxf(tm, fmaxf(S[nt][2 * h2], S[nt][2 * h2 + 1]));
                tm = fmaxf(tm, __shfl_xor_sync(0xffffffffu, tm, 1));
                tm = fmaxf(tm, __shfl_xor_sync(0xffffffffu, tm, 2));
                if (tm > m[h2]) {
                    float al = ex2f(m[h2] - tm);
                    m[h2] = tm;
                    l[h2] *= al;
#pragma unroll
                    for (int dt = 0; dt < 8; dt++) {
                        O[dt][2 * h2] *= al;
                        O[dt][2 * h2 + 1] *= al;
                    }
#pragma unroll
                    for (int n = 0; n < 6; n++) {
                        T[n][2 * h2] *= al;
                        T[n][2 * h2 + 1] *= al;
                    }
                }
            }

            unsigned pa[4][4];
#pragma unroll
            for (int nt = 0; nt < 8; nt++) {
                unsigned p01 = ex2h2(S[nt][0] - m[0], S[nt][1] - m[0]);
                unsigned p23 = ex2h2(S[nt][2] - m[1], S[nt][3] - m[1]);
                pa[nt >> 1][(nt & 1) * 2]     = p01;
                pa[nt >> 1][(nt & 1) * 2 + 1] = p23;
            }

            // ---- T += P @ [c; ones] (N=48: 6 n-tiles; tile 5 col40 = l) ----
#pragma unroll
            for (int n = 0; n < 6; n++) {
                unsigned vb0[4], vb1[4];
                const __half* va = &ct_t[(n * 8 + l8) * CTS + mrow * 8];
                ldsm_x4(vb0[0], vb1[0], vb0[1], vb1[1], va);
                ldsm_x4(vb0[2], vb1[2], vb0[3], vb1[3], va + 32);
#pragma unroll
                for (int kc = 0; kc < 4; kc++)
                    mma16816(T[n], pa[kc], vb0[kc], vb1[kc]);
            }

            // ---- end of run: O += T @ wv2t_{hp}; harvest l ----
            if (t == 15) {
                unsigned at16[2][4], at8a, at8b;
#pragma unroll
                for (int kc = 0; kc < 2; kc++) {
                    at16[kc][0] = packh2(T[2 * kc][0],     T[2 * kc][1]);
                    at16[kc][1] = packh2(T[2 * kc][2],     T[2 * kc][3]);
                    at16[kc][2] = packh2(T[2 * kc + 1][0], T[2 * kc + 1][1]);
                    at16[kc][3] = packh2(T[2 * kc + 1][2], T[2 * kc + 1][3]);
                }
                at8a = packh2(T[4][0], T[4][1]);
                at8b = packh2(T[4][2], T[4][3]);

                unsigned wb8v[8];
                ldsm_x4(wb8v[0], wb8v[1], wb8v[2], wb8v[3],
                        &wv_s[r8 * 40 + 32]);
                ldsm_x4(wb8v[4], wb8v[5], wb8v[6], wb8v[7],
                        &wv_s[(32 + r8) * 40 + 32]);

#pragma unroll
                for (int dt = 0; dt < 8; dt++) {
                    unsigned wb0[2], wb1[2];
                    ldsm_x4(wb0[0], wb1[0], wb0[1], wb1[1],
                            &wv_s[(dt * 8 + l8) * 40 + mrow * 8]);
                    mma16816(O[dt], at16[0], wb0[0], wb1[0]);
                    mma16816(O[dt], at16[1], wb0[1], wb1[1]);
                    mma16808(O[dt], at8a, at8b, wb8v[dt]);
                }
                if (tig == 0) {
                    l[0] += T[5][0];
                    l[1] += T[5][2];
                }
#pragma unroll
                for (int n = 0; n < 6; n++)
#pragma unroll
                    for (int q = 0; q < 4; q++) T[n][q] = 0.f;
            }
        }
    }

    // epilogue: normalize (l lives in tig==0 lanes) + store fp16
#pragma unroll
    for (int h2 = 0; h2 < 2; h2++) {
        float lt = __shfl_sync(0xffffffffu, l[h2], lane & 28);
        float inv = 1.0f / lt;
        int n = n0 + w * 16 + gi + h2 * 8;
        __half* orow = g_attn16 + ((size_t)((b << 10) | n)) * 512 + h * 64;
#pragma unroll
        for (int dt = 0; dt < 8; dt++) {
            *reinterpret_cast<unsigned*>(orow + dt * 8 + tig * 2) =
                packh2(O[dt][2 * h2] * inv, O[dt][2 * h2 + 1] * inv);
        }
    }
}

// ---------------------------------------------------------------------------
// out_gemm via fp16 mma (unchanged from R7)
// ---------------------------------------------------------------------------
__global__ __launch_bounds__(128) void out_gemm(
    const float* __restrict__ bo, float* __restrict__ out) {
    __shared__ __half sA2[64 * 72];
    __shared__ __half sB2[64 * 72];

    const int bm0 = blockIdx.x * 64;
    const int bn0 = blockIdx.y * 64;
    const int tid = threadIdx.x;
    const int w = tid >> 5, lane = tid & 31;
    const int gi = lane >> 2, tig = lane & 3;
    const int l8 = lane & 7, mrow = lane >> 3;

    float acc[8][4];
#pragma unroll
    for (int nt = 0; nt < 8; nt++)
#pragma unroll
        for (int q = 0; q < 4; q++) acc[nt][q] = 0.f;

    const int ar = (lane & 15);
    const int ac = (lane >> 4) * 8;

    for (int kc = 0; kc < 8; kc++) {
        __syncthreads();
        for (int idx = tid; idx < 512; idx += 128) {
            int r = idx >> 3, s = idx & 7;
            cp16(&sA2[r * 72 + s * 8],
                 g_attn16 + (size_t)(bm0 + r) * 512 + kc * 64 + s * 8);
            cp16(&sB2[r * 72 + s * 8],
                 g_woT + (size_t)(bn0 + r) * 512 + kc * 64 + s * 8);
        }
        asm volatile("cp.async.commit_group;\n");
        asm volatile("cp.async.wait_group 0;\n");
        __syncthreads();

        const int m0 = w * 16;
#pragma unroll
        for (int ksp = 0; ksp < 2; ksp++) {
            unsigned af0[4], af1[4];
            ldsm_x4(af0[0], af0[1], af0[2], af0[3],
                    &sA2[(m0 + ar) * 72 + ksp * 32 + ac]);
            ldsm_x4(af1[0], af1[1], af1[2], af1[3],
                    &sA2[(m0 + ar) * 72 + ksp * 32 + 16 + ac]);
#pragma unroll
            for (int nt = 0; nt < 8; nt++) {
                unsigned b0a, b1a, b0b, b1b;
                ldsm_x4(b0a, b1a, b0b, b1b,
                        &sB2[(nt * 8 + l8) * 72 + ksp * 32 + mrow * 8]);
                mma16816(acc[nt], af0, b0a, b1a);
                mma16816(acc[nt], af1, b0b, b1b);
            }
        }
    }

    const int r0 = bm0 + w * 16 + gi;
#pragma unroll
    for (int nt = 0; nt < 8; nt++) {
        int col = bn0 + nt * 8 + tig * 2;
        float b0 = bo[col], b1 = bo[col + 1];
        float2 o0 = make_float2(acc[nt][0] + b0, acc[nt][1] + b1);
        float2 o1 = make_float2(acc[nt][2] + b0, acc[nt][3] + b1);
        *reinterpret_cast<float2*>(out + (size_t)r0 * 256 + col) = o0;
        *reinterpret_cast<float2*>(out + (size_t)(r0 + 8) * 256 + col) = o1;
    }
}

// ---------------------------------------------------------------------------
extern "C" void kernel_launch(void* const* d_in, const int* in_sizes, int n_in,
                              void* d_out, int out_size) {
    const float* x   = (const float*)d_in[0];
    const float* wq1 = (const float*)d_in[1];
    const float* wq2 = (const float*)d_in[2];
    const float* wk1 = (const float*)d_in[3];
    const float* wk2 = (const float*)d_in[4];
    const float* wv1 = (const float*)d_in[5];
    const float* wv2 = (const float*)d_in[6];
    const float* wo  = (const float*)d_in[7];
    const float* bo  = (const float*)d_in[8];
    float* out = (float*)d_out;

    cudaFuncSetAttribute(attn_kernel, cudaFuncAttributeMaxDynamicSharedMemorySize,
                         ATTN_SMEM);
    cudaFuncSetAttribute(ahat_kernel, cudaFuncAttributeMaxDynamicSharedMemorySize,
                         AH_SMEM);

    proj_kernel<<<dim3(16, 12), 256>>>(x, wq1, wk1, wv1);
    prep_kernel<<<136, 256>>>(wq2, wk2, wv2, wo);
    ahat_kernel<<<256, 256, AH_SMEM>>>();
    attn_kernel<<<dim3(64, 4), 256, ATTN_SMEM>>>();
    out_gemm<<<dim3(64, 4), 128>>>(bo, out);
}

// round 9
// speedup vs baseline: 1.6198x; 1.0757x over previous
#include <cuda_runtime.h>
#include <cuda_fp16.h>
#include <cstdint>

#define NN    1024
#define QSZ   256
#define BOT   40

// ------------------------- scratch (no allocs allowed) -----------------------
__device__ __half g_ahalf[(size_t)4096 * 40];          // a = x@wq1 (fp16)
__device__ __half g_b[(size_t)4096 * 40];              // b = silu(x@wk1)
__device__ __half g_ct[(size_t)4 * 40 * 1024];         // c^T  [b][40][n]
__device__ __half g_gt[(size_t)64 * 1600];             // G^T per (h,hp)  [hh'][c][k]
__device__ __half g_wv2t[(size_t)8 * 64 * 40];         // wv2^T per head [h][d][40]
__device__ __half g_attn16[(size_t)4096 * 512];        // attention out (fp16)
__device__ __half g_woT[(size_t)256 * 512];            // wo^T fp16 [n][k]

__device__ __forceinline__ float ex2f(float x) {
    float y;
    asm("ex2.approx.ftz.f32 %0, %1;" : "=f"(y) : "f"(x));
    return y;
}

__device__ __forceinline__ unsigned ex2h2(float a, float b) {
    __half2 h = __floats2half2_rn(a, b);
    unsigned u = *reinterpret_cast<unsigned*>(&h);
    unsigned r;
    asm("ex2.approx.f16x2 %0, %1;" : "=r"(r) : "r"(u));
    return r;
}

__device__ __forceinline__ unsigned packh2(float a, float b) {
    __half2 h = __floats2half2_rn(a, b);
    return *reinterpret_cast<unsigned*>(&h);
}

__device__ __forceinline__ void mma16816(float (&c)[4], const unsigned (&a)[4],
                                         unsigned b0, unsigned b1) {
    asm volatile(
        "mma.sync.aligned.m16n8k16.row.col.f32.f16.f16.f32 "
        "{%0,%1,%2,%3}, {%4,%5,%6,%7}, {%8,%9}, {%0,%1,%2,%3};\n"
        : "+f"(c[0]), "+f"(c[1]), "+f"(c[2]), "+f"(c[3])
        : "r"(a[0]), "r"(a[1]), "r"(a[2]), "r"(a[3]), "r"(b0), "r"(b1));
}

__device__ __forceinline__ void mma16808(float (&c)[4], unsigned a0, unsigned a1,
                                         unsigned b0) {
    asm volatile(
        "mma.sync.aligned.m16n8k8.row.col.f32.f16.f16.f32 "
        "{%0,%1,%2,%3}, {%4,%5}, {%6}, {%0,%1,%2,%3};\n"
        : "+f"(c[0]), "+f"(c[1]), "+f"(c[2]), "+f"(c[3])
        : "r"(a0), "r"(a1), "r"(b0));
}

__device__ __forceinline__ void cp16(void* s, const void* g) {
    unsigned sa = (unsigned)__cvta_generic_to_shared(s);
    asm volatile("cp.async.cg.shared.global [%0], [%1], 16;\n" :: "r"(sa), "l"(g));
}

__device__ __forceinline__ void ldsm_x4(unsigned& r0, unsigned& r1, unsigned& r2,
                                        unsigned& r3, const void* p) {
    unsigned a = (unsigned)__cvta_generic_to_shared(p);
    asm volatile("ldmatrix.sync.aligned.m8n8.x4.shared.b16 {%0,%1,%2,%3}, [%4];"
                 : "=r"(r0), "=r"(r1), "=r"(r2), "=r"(r3) : "r"(a));
}

// ---------------------------------------------------------------------------
// pre_kernel: fused proj (bx<192) + gmat (192..255) + wv2t (256..263) +
//             wot (264..327).  grid 328, 256 thr.
// ---------------------------------------------------------------------------
__global__ __launch_bounds__(256) void pre_kernel(
    const float* __restrict__ x,
    const float* __restrict__ wq1, const float* __restrict__ wk1,
    const float* __restrict__ wv1,
    const float* __restrict__ wq2, const float* __restrict__ wk2,
    const float* __restrict__ wv2, const float* __restrict__ wo) {
    __shared__ float sf[5200];

    const int bx = blockIdx.x;
    const int tid = threadIdx.x;

    if (bx < 192) {
        // ---- bottleneck projection: 16 row-chunks x 12 colgroups ----
        float (*sWT)[256] = reinterpret_cast<float (*)[256]>(sf);
        const int cg = bx >> 4;            // colgroup 0..11
        const int xc = bx & 15;            // row chunk
        const int proj = cg >> 2;
        const int c0 = (cg & 3) * 10;
        const float* w1 = (proj == 0) ? wq1 : (proj == 1 ? wk1 : wv1);

        for (int idx = tid; idx < 2560; idx += 256) {
            int k = idx / 10, c = idx % 10;
            sWT[c][k] = w1[k * 40 + c0 + c];
        }
        __syncthreads();

        const int row = xc * 256 + tid;
        const float4* xr = reinterpret_cast<const float4*>(x + (size_t)row * QSZ);

        float acc[10];
#pragma unroll
        for (int c = 0; c < 10; c++) acc[c] = 0.f;

#pragma unroll 4
        for (int k4 = 0; k4 < 64; k4++) {
            float4 xv = xr[k4];
#pragma unroll
            for (int c = 0; c < 10; c++) {
                float4 wv = *reinterpret_cast<const float4*>(&sWT[c][k4 * 4]);
                acc[c] += xv.x * wv.x + xv.y * wv.y + xv.z * wv.z + xv.w * wv.w;
            }
        }

        if (proj == 0) {
            __half2* dst = reinterpret_cast<__half2*>(g_ahalf + (size_t)row * 40 + c0);
#pragma unroll
            for (int i = 0; i < 5; i++)
                dst[i] = __floats2half2_rn(acc[2 * i], acc[2 * i + 1]);
        } else if (proj == 1) {
#pragma unroll
            for (int c = 0; c < 10; c++)
                acc[c] = acc[c] / (1.0f + __expf(-acc[c]));
            __half2* dst = reinterpret_cast<__half2*>(g_b + (size_t)row * 40 + c0);
#pragma unroll
            for (int i = 0; i < 5; i++)
                dst[i] = __floats2half2_rn(acc[2 * i], acc[2 * i + 1]);
        } else {
            const int bb = row >> 10, n = row & 1023;
#pragma unroll
            for (int c = 0; c < 10; c++)
                g_ct[((size_t)bb * 40 + c0 + c) * 1024 + n] = __float2half_rn(acc[c]);
        }
    } else if (bx < 256) {
        // ---- gmat: G^T[hh'][c][k] ----
        float (*sQ)[65] = reinterpret_cast<float (*)[65]>(sf);
        float (*sK)[65] = reinterpret_cast<float (*)[65]>(sf + 2600);
        const int id = bx - 192;
        const int h = id >> 3, hp = id & 7;
        for (int idx = tid; idx < 2560; idx += 256) {
            int k = idx >> 6, d = idx & 63;
            sQ[k][d] = wq2[(size_t)k * 512 + h * 64 + d];
            sK[k][d] = wk2[(size_t)k * 512 + hp * 64 + d];
        }
        __syncthreads();
        const float SCALE = 0.125f * 1.4426950408889634f;
        for (int idx = tid; idx < 1600; idx += 256) {
            int c = idx / 40, k = idx % 40;
            float s = 0.f;
#pragma unroll 8
            for (int d = 0; d < 64; d++) s += sQ[k][d] * sK[c][d];
            g_gt[(size_t)id * 1600 + c * 40 + k] = __float2half_rn(s * SCALE);
        }
    } else if (bx < 264) {
        const int h = bx - 256;
        for (int idx = tid; idx < 64 * 40; idx += 256) {
            int d = idx / 40, k = idx % 40;
            g_wv2t[(size_t)h * 2560 + d * 40 + k] =
                __float2half_rn(wv2[(size_t)k * 512 + h * 64 + d]);
        }
    } else {
        const int base = (bx - 264) * 2048;
#pragma unroll
        for (int i = 0; i < 8; i++) {
            int idx = base + i * 256 + tid;
            int n = idx >> 9, k = idx & 511;
            g_woT[idx] = __float2half_rn(wo[(size_t)k * 256 + n]);
        }
    }
}

// ---------------------------------------------------------------------------
// Flash attention v5: qf computed in-kernel (a-frags + G-frags via LDG, mma,
// C->A fragment reuse). No ahat materialization. 2 CTAs/SM.
// ---------------------------------------------------------------------------
#define CTS   72
#define CT_BUFSZ (41 * CTS)
#define CT_REGION (4 * CT_BUFSZ + 7 * CTS)
#define WVSZ  2560
#define B_HALVES 40960
#define ATTN_SMEM ((B_HALVES + CT_REGION + WVSZ) * 2)   // 111,664 B

__global__ __launch_bounds__(256, 2) void attn_kernel() {
    extern __shared__ __half sm[];
    __half* b_s  = sm;                         // [1024][40]
    __half* ct_s = sm + B_HALVES;              // 4 bufs [41][72]
    __half* wv_s = sm + B_HALVES + CT_REGION;  // [64][40]

    const int b = blockIdx.y;
    const int qt = blockIdx.x;
    const int h = qt >> 3;
    const int n0 = (qt & 7) * 128;
    const int tid = threadIdx.x;
    const int w = tid >> 5, lane = tid & 31;
    const int gi = lane >> 2, tig = lane & 3;
    const int l8 = lane & 7, mrow = lane >> 3;
    const int r8 = (lane >> 3) * 8 + (lane & 7);

    const __half* gb = g_b + (size_t)b * 1024 * 40;
    const __half* gct = g_ct + (size_t)b * 40 * 1024;

    // prologue: b + ct tiles 0,1 + wv(0)
    for (int idx = tid; idx < 5120; idx += 256)
        cp16(&b_s[idx * 8], gb + idx * 8);
#pragma unroll
    for (int pf = 0; pf < 2; pf++) {
        __half* dc = ct_s + pf * CT_BUFSZ;
        for (int idx = tid; idx < 320; idx += 256) {
            int row = idx >> 3, seg = idx & 7;
            cp16(&dc[row * CTS + seg * 8], gct + (size_t)row * 1024 + pf * 64 + seg * 8);
        }
    }
    for (int idx = tid; idx < 320; idx += 256)
        cp16(&wv_s[idx * 8], g_wv2t + idx * 8);
    asm volatile("cp.async.commit_group;\n");
    asm volatile("cp.async.wait_group 0;\n");
    // ones row (row 40) of all 4 ct buffers
    if (tid < 128) {
        int bufi = tid >> 5, seg = tid & 31;
        *reinterpret_cast<unsigned*>(&ct_s[bufi * CT_BUFSZ + 40 * CTS + seg * 2]) =
            0x3C003C00u;
    }
    __syncthreads();

    float m[2] = {-1e30f, -1e30f}, l[2] = {0.f, 0.f};
    float O[8][4], T[6][4];
#pragma unroll
    for (int dt = 0; dt < 8; dt++)
#pragma unroll
        for (int q = 0; q < 4; q++) O[dt][q] = 0.f;
#pragma unroll
    for (int n = 0; n < 6; n++)
#pragma unroll
        for (int q = 0; q < 4; q++) T[n][q] = 0.f;

    unsigned qf[2][4], qf8[2];
    const __half* ar0 = g_ahalf + (size_t)(((b << 10) | n0) + w * 16 + gi) * 40;
    const __half* ar1 = ar0 + 8 * 40;

    for (int tt = 0; tt < 128; tt += 2) {
        const int hp = tt >> 4;

        asm volatile("cp.async.wait_group 0;\n");
        __syncthreads();

        // prefetches for tiles tt+2, tt+3 (+ wv at run start)
        if (tt + 2 < 128) {
#pragma unroll
            for (int pf = 0; pf < 2; pf++) {
                int ntile = tt + 2 + pf;
                int key0 = (ntile & 15) * 64;
                __half* dc = ct_s + (ntile & 3) * CT_BUFSZ;
                for (int idx = tid; idx < 320; idx += 256) {
                    int row = idx >> 3, seg = idx & 7;
                    cp16(&dc[row * CTS + seg * 8],
                         gct + (size_t)row * 1024 + key0 + seg * 8);
                }
            }
        }
        if ((tt & 15) == 0 && tt > 0) {
            const __half* gw = g_wv2t + (size_t)hp * 2560;
            for (int idx = tid; idx < 320; idx += 256)
                cp16(&wv_s[idx * 8], gw + idx * 8);
        }
        asm volatile("cp.async.commit_group;\n");

        // ---- run start: qf = pack( a_rows @ G_hp )  (C->A fragment reuse) ----
        if ((tt & 15) == 0) {
            unsigned af[2][4], af8[2];
#pragma unroll
            for (int kc = 0; kc < 2; kc++) {
                int cc = kc * 16 + tig * 2;
                af[kc][0] = *reinterpret_cast<const unsigned*>(ar0 + cc);
                af[kc][1] = *reinterpret_cast<const unsigned*>(ar1 + cc);
                af[kc][2] = *reinterpret_cast<const unsigned*>(ar0 + cc + 8);
                af[kc][3] = *reinterpret_cast<const unsigned*>(ar1 + cc + 8);
            }
            af8[0] = *reinterpret_cast<const unsigned*>(ar0 + 32 + tig * 2);
            af8[1] = *reinterpret_cast<const unsigned*>(ar1 + 32 + tig * 2);

            const __half* gg = g_gt + (size_t)(h * 8 + hp) * 1600;
            float tq[5][4];
#pragma unroll
            for (int nt = 0; nt < 5; nt++) {
                const __half* gr = gg + (nt * 8 + gi) * 40 + tig * 2;
                unsigned g0 = *reinterpret_cast<const unsigned*>(gr);
                unsigned g1 = *reinterpret_cast<const unsigned*>(gr + 8);
                unsigned g2 = *reinterpret_cast<const unsigned*>(gr + 16);
                unsigned g3 = *reinterpret_cast<const unsigned*>(gr + 24);
                unsigned g4 = *reinterpret_cast<const unsigned*>(gr + 32);
                tq[nt][0] = tq[nt][1] = tq[nt][2] = tq[nt][3] = 0.f;
                mma16816(tq[nt], af[0], g0, g1);
                mma16816(tq[nt], af[1], g2, g3);
                mma16808(tq[nt], af8[0], af8[1], g4);
            }
#pragma unroll
            for (int kc = 0; kc < 2; kc++) {
                qf[kc][0] = packh2(tq[2 * kc][0],     tq[2 * kc][1]);
                qf[kc][1] = packh2(tq[2 * kc][2],     tq[2 * kc][3]);
                qf[kc][2] = packh2(tq[2 * kc + 1][0], tq[2 * kc + 1][1]);
                qf[kc][3] = packh2(tq[2 * kc + 1][2], tq[2 * kc + 1][3]);
            }
            qf8[0] = packh2(tq[4][0], tq[4][1]);
            qf8[1] = packh2(tq[4][2], tq[4][3]);
        }

#pragma unroll
        for (int sub = 0; sub < 2; sub++) {
            const int tile = tt + sub;
            const int t = tile & 15;
            const __half* ct_t = ct_s + (tile & 3) * CT_BUFSZ;

            // ---- S = ahat @ b^T (k=40) ----
            unsigned kb8v[8];
            ldsm_x4(kb8v[0], kb8v[1], kb8v[2], kb8v[3],
                    &b_s[(t * 64 + r8) * 40 + 32]);
            ldsm_x4(kb8v[4], kb8v[5], kb8v[6], kb8v[7],
                    &b_s[(t * 64 + 32 + r8) * 40 + 32]);

            float S[8][4];
#pragma unroll
            for (int nt = 0; nt < 8; nt++)
#pragma unroll
                for (int q = 0; q < 4; q++) S[nt][q] = 0.f;

#pragma unroll
            for (int nt = 0; nt < 8; nt++) {
                unsigned kb0[2], kb1[2];
                ldsm_x4(kb0[0], kb1[0], kb0[1], kb1[1],
                        &b_s[(t * 64 + nt * 8 + l8) * 40 + mrow * 8]);
                mma16816(S[nt], qf[0], kb0[0], kb1[0]);
                mma16816(S[nt], qf[1], kb0[1], kb1[1]);
                mma16808(S[nt], qf8[0], qf8[1], kb8v[nt]);
            }

            // ---- online softmax (log2 domain) ----
#pragma unroll
            for (int h2 = 0; h2 < 2; h2++) {
                float tm = -1e30f;
#pragma unroll
                for (int nt = 0; nt < 8; nt++)
                    tm = fmaxf(tm, fmaxf(S[nt][2 * h2], S[nt][2 * h2 + 1]));
                tm = fmaxf(tm, __shfl_xor_sync(0xffffffffu, tm, 1));
                tm = fmaxf(tm, __shfl_xor_sync(0xffffffffu, tm, 2));
                if (tm > m[h2]) {
                    float al = ex2f(m[h2] - tm);
                    m[h2] = tm;
                    l[h2] *= al;
#pragma unroll
                    for (int dt = 0; dt < 8; dt++) {
                        O[dt][2 * h2] *= al;
                        O[dt][2 * h2 + 1] *= al;
                    }
#pragma unroll
                    for (int n = 0; n < 6; n++) {
                        T[n][2 * h2] *= al;
                        T[n][2 * h2 + 1] *= al;
                    }
                }
            }

            unsigned pa[4][4];
#pragma unroll
            for (int nt = 0; nt < 8; nt++) {
                unsigned p01 = ex2h2(S[nt][0] - m[0], S[nt][1] - m[0]);
                unsigned p23 = ex2h2(S[nt][2] - m[1], S[nt][3] - m[1]);
                pa[nt >> 1][(nt & 1) * 2]     = p01;
                pa[nt >> 1][(nt & 1) * 2 + 1] = p23;
            }

            // ---- T += P @ [c; ones] (N=48) ----
#pragma unroll
            for (int n = 0; n < 6; n++) {
                unsigned vb0[4], vb1[4];
                const __half* va = &ct_t[(n * 8 + l8) * CTS + mrow * 8];
                ldsm_x4(vb0[0], vb1[0], vb0[1], vb1[1], va);
                ldsm_x4(vb0[2], vb1[2], vb0[3], vb1[3], va + 32);
#pragma unroll
                for (int kc = 0; kc < 4; kc++)
                    mma16816(T[n], pa[kc], vb0[kc], vb1[kc]);
            }

            // ---- end of run: O += T @ wv2t_{hp}; harvest l ----
            if (t == 15) {
                unsigned at16[2][4], at8a, at8b;
#pragma unroll
                for (int kc = 0; kc < 2; kc++) {
                    at16[kc][0] = packh2(T[2 * kc][0],     T[2 * kc][1]);
                    at16[kc][1] = packh2(T[2 * kc][2],     T[2 * kc][3]);
                    at16[kc][2] = packh2(T[2 * kc + 1][0], T[2 * kc + 1][1]);
                    at16[kc][3] = packh2(T[2 * kc + 1][2], T[2 * kc + 1][3]);
                }
                at8a = packh2(T[4][0], T[4][1]);
                at8b = packh2(T[4][2], T[4][3]);

                unsigned wb8v[8];
                ldsm_x4(wb8v[0], wb8v[1], wb8v[2], wb8v[3],
                        &wv_s[r8 * 40 + 32]);
                ldsm_x4(wb8v[4], wb8v[5], wb8v[6], wb8v[7],
                        &wv_s[(32 + r8) * 40 + 32]);

#pragma unroll
                for (int dt = 0; dt < 8; dt++) {
                    unsigned wb0[2], wb1[2];
                    ldsm_x4(wb0[0], wb1[0], wb0[1], wb1[1],
                            &wv_s[(dt * 8 + l8) * 40 + mrow * 8]);
                    mma16816(O[dt], at16[0], wb0[0], wb1[0]);
                    mma16816(O[dt], at16[1], wb0[1], wb1[1]);
                    mma16808(O[dt], at8a, at8b, wb8v[dt]);
                }
                if (tig == 0) {
                    l[0] += T[5][0];
                    l[1] += T[5][2];
                }
#pragma unroll
                for (int n = 0; n < 6; n++)
#pragma unroll
                    for (int q = 0; q < 4; q++) T[n][q] = 0.f;
            }
        }
    }

    // epilogue: normalize (l lives in tig==0 lanes) + store fp16
#pragma unroll
    for (int h2 = 0; h2 < 2; h2++) {
        float lt = __shfl_sync(0xffffffffu, l[h2], lane & 28);
        float inv = 1.0f / lt;
        int n = n0 + w * 16 + gi + h2 * 8;
        __half* orow = g_attn16 + ((size_t)((b << 10) | n)) * 512 + h * 64;
#pragma unroll
        for (int dt = 0; dt < 8; dt++) {
            *reinterpret_cast<unsigned*>(orow + dt * 8 + tig * 2) =
                packh2(O[dt][2 * h2] * inv, O[dt][2 * h2 + 1] * inv);
        }
    }
}

// ---------------------------------------------------------------------------
// out_gemm via fp16 mma
// ---------------------------------------------------------------------------
__global__ __launch_bounds__(128) void out_gemm(
    const float* __restrict__ bo, float* __restrict__ out) {
    __shared__ __half sA2[64 * 72];
    __shared__ __half sB2[64 * 72];

    const int bm0 = blockIdx.x * 64;
    const int bn0 = blockIdx.y * 64;
    const int tid = threadIdx.x;
    const int w = tid >> 5, lane = tid & 31;
    const int gi = lane >> 2, tig = lane & 3;
    const int l8 = lane & 7, mrow = lane >> 3;

    float acc[8][4];
#pragma unroll
    for (int nt = 0; nt < 8; nt++)
#pragma unroll
        for (int q = 0; q < 4; q++) acc[nt][q] = 0.f;

    const int ar = (lane & 15);
    const int ac = (lane >> 4) * 8;

    for (int kc = 0; kc < 8; kc++) {
        __syncthreads();
        for (int idx = tid; idx < 512; idx += 128) {
            int r = idx >> 3, s = idx & 7;
            cp16(&sA2[r * 72 + s * 8],
                 g_attn16 + (size_t)(bm0 + r) * 512 + kc * 64 + s * 8);
            cp16(&sB2[r * 72 + s * 8],
                 g_woT + (size_t)(bn0 + r) * 512 + kc * 64 + s * 8);
        }
        asm volatile("cp.async.commit_group;\n");
        asm volatile("cp.async.wait_group 0;\n");
        __syncthreads();

        const int m0 = w * 16;
#pragma unroll
        for (int ksp = 0; ksp < 2; ksp++) {
            unsigned af0[4], af1[4];
            ldsm_x4(af0[0], af0[1], af0[2], af0[3],
                    &sA2[(m0 + ar) * 72 + ksp * 32 + ac]);
            ldsm_x4(af1[0], af1[1], af1[2], af1[3],
                    &sA2[(m0 + ar) * 72 + ksp * 32 + 16 + ac]);
#pragma unroll
            for (int nt = 0; nt < 8; nt++) {
                unsigned b0a, b1a, b0b, b1b;
                ldsm_x4(b0a, b1a, b0b, b1b,
                        &sB2[(nt * 8 + l8) * 72 + ksp * 32 + mrow * 8]);
                mma16816(acc[nt], af0, b0a, b1a);
                mma16816(acc[nt], af1, b0b, b1b);
            }
        }
    }

    const int r0 = bm0 + w * 16 + gi;
#pragma unroll
    for (int nt = 0; nt < 8; nt++) {
        int col = bn0 + nt * 8 + tig * 2;
        float b0 = bo[col], b1 = bo[col + 1];
        float2 o0 = make_float2(acc[nt][0] + b0, acc[nt][1] + b1);
        float2 o1 = make_float2(acc[nt][2] + b0, acc[nt][3] + b1);
        *reinterpret_cast<float2*>(out + (size_t)r0 * 256 + col) = o0;
        *reinterpret_cast<float2*>(out + (size_t)(r0 + 8) * 256 + col) = o1;
    }
}

// ---------------------------------------------------------------------------
extern "C" void kernel_launch(void* const* d_in, const int* in_sizes, int n_in,
                              void* d_out, int out_size) {
    const float* x   = (const float*)d_in[0];
    const float* wq1 = (const float*)d_in[1];
    const float* wq2 = (const float*)d_in[2];
    const float* wk1 = (const float*)d_in[3];
    const float* wk2 = (const float*)d_in[4];
    const float* wv1 = (const float*)d_in[5];
    const float* wv2 = (const float*)d_in[6];
    const float* wo  = (const float*)d_in[7];
    const float* bo  = (const float*)d_in[8];
    float* out = (float*)d_out;

    cudaFuncSetAttribute(attn_kernel, cudaFuncAttributeMaxDynamicSharedMemorySize,
                         ATTN_SMEM);

    pre_kernel<<<328, 256>>>(x, wq1, wk1, wv1, wq2, wk2, wv2, wo);
    attn_kernel<<<dim3(64, 4), 256, ATTN_SMEM>>>();
    out_gemm<<<dim3(64, 4), 128>>>(bo, out);
}

// round 10
// speedup vs baseline: 1.6434x; 1.0145x over previous
#include <cuda_runtime.h>
#include <cuda_fp16.h>
#include <cstdint>

#define NN    1024
#define QSZ   256
#define BOT   40

// ------------------------- scratch (no allocs allowed) -----------------------
__device__ __half g_x16h[(size_t)4096 * 256];          // x hi (fp16)
__device__ __half g_x16l[(size_t)4096 * 256];          // x lo (fp16)
__device__ __half g_w1th[(size_t)128 * 256];           // w1^T hi [n][k] (rows 120..127 zero)
__device__ __half g_w1tl[(size_t)128 * 256];           // w1^T lo
__device__ __half g_ahalf[(size_t)4096 * 40];          // a = x@wq1 (fp16)
__device__ __half g_b[(size_t)4096 * 40];              // b = silu(x@wk1)
__device__ __half g_ct[(size_t)4 * 40 * 1024];         // c^T  [b][40][n]
__device__ __half g_gt[(size_t)64 * 1600];             // G^T per (h,hp)  [hh'][c][k]
__device__ __half g_wv2t[(size_t)8 * 64 * 40];         // wv2^T per head [h][d][40]
__device__ __half g_attn16[(size_t)4096 * 512];        // attention out (fp16)
__device__ __half g_woT[(size_t)256 * 512];            // wo^T fp16 [n][k]

__device__ __forceinline__ float ex2f(float x) {
    float y;
    asm("ex2.approx.ftz.f32 %0, %1;" : "=f"(y) : "f"(x));
    return y;
}

__device__ __forceinline__ unsigned ex2h2(float a, float b) {
    __half2 h = __floats2half2_rn(a, b);
    unsigned u = *reinterpret_cast<unsigned*>(&h);
    unsigned r;
    asm("ex2.approx.f16x2 %0, %1;" : "=r"(r) : "r"(u));
    return r;
}

__device__ __forceinline__ unsigned packh2(float a, float b) {
    __half2 h = __floats2half2_rn(a, b);
    return *reinterpret_cast<unsigned*>(&h);
}

__device__ __forceinline__ void mma16816(float (&c)[4], const unsigned (&a)[4],
                                         unsigned b0, unsigned b1) {
    asm volatile(
        "mma.sync.aligned.m16n8k16.row.col.f32.f16.f16.f32 "
        "{%0,%1,%2,%3}, {%4,%5,%6,%7}, {%8,%9}, {%0,%1,%2,%3};\n"
        : "+f"(c[0]), "+f"(c[1]), "+f"(c[2]), "+f"(c[3])
        : "r"(a[0]), "r"(a[1]), "r"(a[2]), "r"(a[3]), "r"(b0), "r"(b1));
}

__device__ __forceinline__ void mma16808(float (&c)[4], unsigned a0, unsigned a1,
                                         unsigned b0) {
    asm volatile(
        "mma.sync.aligned.m16n8k8.row.col.f32.f16.f16.f32 "
        "{%0,%1,%2,%3}, {%4,%5}, {%6}, {%0,%1,%2,%3};\n"
        : "+f"(c[0]), "+f"(c[1]), "+f"(c[2]), "+f"(c[3])
        : "r"(a0), "r"(a1), "r"(b0));
}

__device__ __forceinline__ void cp16(void* s, const void* g) {
    unsigned sa = (unsigned)__cvta_generic_to_shared(s);
    asm volatile("cp.async.cg.shared.global [%0], [%1], 16;\n" :: "r"(sa), "l"(g));
}

__device__ __forceinline__ void ldsm_x4(unsigned& r0, unsigned& r1, unsigned& r2,
                                        unsigned& r3, const void* p) {
    unsigned a = (unsigned)__cvta_generic_to_shared(p);
    asm volatile("ldmatrix.sync.aligned.m8n8.x4.shared.b16 {%0,%1,%2,%3}, [%4];"
                 : "=r"(r0), "=r"(r1), "=r"(r2), "=r"(r3) : "r"(a));
}

// ---------------------------------------------------------------------------
// pre_kernel v2: x hi/lo convert (0..127) + gmat (128..191) + wv2t (192..199)
//                + wot (200..263) + w1t hi/lo (264..265). grid 266.
// ---------------------------------------------------------------------------
__global__ __launch_bounds__(256) void pre_kernel(
    const float* __restrict__ x,
    const float* __restrict__ wq1, const float* __restrict__ wk1,
    const float* __restrict__ wv1,
    const float* __restrict__ wq2, const float* __restrict__ wk2,
    const float* __restrict__ wv2, const float* __restrict__ wo) {
    __shared__ float sf[5200];

    const int bx = blockIdx.x;
    const int tid = threadIdx.x;

    if (bx < 128) {
        // ---- x split-convert: 8192 floats per block ----
        const float4* x4 = reinterpret_cast<const float4*>(x) + (size_t)bx * 2048;
        uint2* dh = reinterpret_cast<uint2*>(g_x16h) + (size_t)bx * 2048;
        uint2* dl = reinterpret_cast<uint2*>(g_x16l) + (size_t)bx * 2048;
        for (int i = tid; i < 2048; i += 256) {
            float4 v = x4[i];
            __half h0 = __float2half_rn(v.x), h1 = __float2half_rn(v.y);
            __half h2 = __float2half_rn(v.z), h3 = __float2half_rn(v.w);
            float l0 = v.x - __half2float(h0), l1 = v.y - __half2float(h1);
            float l2 = v.z - __half2float(h2), l3 = v.w - __half2float(h3);
            __half2 hh0 = __halves2half2(h0, h1), hh1 = __halves2half2(h2, h3);
            uint2 uh = make_uint2(*reinterpret_cast<unsigned*>(&hh0),
                                  *reinterpret_cast<unsigned*>(&hh1));
            dh[i] = uh;
            __half2 ll0 = __floats2half2_rn(l0, l1), ll1 = __floats2half2_rn(l2, l3);
            uint2 ul = make_uint2(*reinterpret_cast<unsigned*>(&ll0),
                                  *reinterpret_cast<unsigned*>(&ll1));
            dl[i] = ul;
        }
    } else if (bx < 192) {
        // ---- gmat: G^T[hh'][c][k] ----
        float (*sQ)[65] = reinterpret_cast<float (*)[65]>(sf);
        float (*sK)[65] = reinterpret_cast<float (*)[65]>(sf + 2600);
        const int id = bx - 128;
        const int h = id >> 3, hp = id & 7;
        for (int idx = tid; idx < 2560; idx += 256) {
            int k = idx >> 6, d = idx & 63;
            sQ[k][d] = wq2[(size_t)k * 512 + h * 64 + d];
            sK[k][d] = wk2[(size_t)k * 512 + hp * 64 + d];
        }
        __syncthreads();
        const float SCALE = 0.125f * 1.4426950408889634f;
        for (int idx = tid; idx < 1600; idx += 256) {
            int c = idx / 40, k = idx % 40;
            float s = 0.f;
#pragma unroll 8
            for (int d = 0; d < 64; d++) s += sQ[k][d] * sK[c][d];
            g_gt[(size_t)id * 1600 + c * 40 + k] = __float2half_rn(s * SCALE);
        }
    } else if (bx < 200) {
        const int h = bx - 192;
        for (int idx = tid; idx < 64 * 40; idx += 256) {
            int d = idx / 40, k = idx % 40;
            g_wv2t[(size_t)h * 2560 + d * 40 + k] =
                __float2half_rn(wv2[(size_t)k * 512 + h * 64 + d]);
        }
    } else if (bx < 264) {
        const int base = (bx - 200) * 2048;
#pragma unroll
        for (int i = 0; i < 8; i++) {
            int idx = base + i * 256 + tid;
            int n = idx >> 9, k = idx & 511;
            g_woT[idx] = __float2half_rn(wo[(size_t)k * 256 + n]);
        }
    } else {
        // ---- w1t hi/lo: n-major [128][256], rows 0..119 ----
        const int base = (bx - 264) * 15360;
        for (int i = tid; i < 15360; i += 256) {
            int e = base + i;
            int n = e >> 8, k = e & 255;
            int proj = n / 40, c = n % 40;
            const float* w1 = (proj == 0) ? wq1 : (proj == 1 ? wk1 : wv1);
            float v = w1[(size_t)k * 40 + c];
            __half hh = __float2half_rn(v);
            g_w1th[(size_t)n * 256 + k] = hh;
            g_w1tl[(size_t)n * 256 + k] = __float2half_rn(v - __half2float(hh));
        }
    }
}

// ---------------------------------------------------------------------------
// proj_mma: [a|b|c] = x @ w1 via split-fp16 mma (hi*hi + lo*hi + hi*lo).
// grid 128 blocks x 32 rows; 4 warps: (w&1)=m-half, (w>>1)=n-half (8 ntiles).
// ---------------------------------------------------------------------------
__global__ __launch_bounds__(128) void proj_mma() {
    const int tid = threadIdx.x;
    const int w = tid >> 5, lane = tid & 31;
    const int gi = lane >> 2, tig = lane & 3;
    const int row0 = blockIdx.x * 32 + (w & 1) * 16;
    const int n0 = (w >> 1) * 64;

    const __half* xh0 = g_x16h + (size_t)(row0 + gi) * 256;
    const __half* xh8 = xh0 + 8 * 256;
    const __half* xl0 = g_x16l + (size_t)(row0 + gi) * 256;
    const __half* xl8 = xl0 + 8 * 256;

    float acc[8][4];
#pragma unroll
    for (int nt = 0; nt < 8; nt++)
#pragma unroll
        for (int q = 0; q < 4; q++) acc[nt][q] = 0.f;

#pragma unroll
    for (int k = 0; k < 16; k++) {
        const int kc = k * 16 + tig * 2;
        unsigned ah[4], al[4];
        ah[0] = *reinterpret_cast<const unsigned*>(xh0 + kc);
        ah[1] = *reinterpret_cast<const unsigned*>(xh8 + kc);
        ah[2] = *reinterpret_cast<const unsigned*>(xh0 + kc + 8);
        ah[3] = *reinterpret_cast<const unsigned*>(xh8 + kc + 8);
        al[0] = *reinterpret_cast<const unsigned*>(xl0 + kc);
        al[1] = *reinterpret_cast<const unsigned*>(xl8 + kc);
        al[2] = *reinterpret_cast<const unsigned*>(xl0 + kc + 8);
        al[3] = *reinterpret_cast<const unsigned*>(xl8 + kc + 8);

#pragma unroll
        for (int nt = 0; nt < 8; nt++) {
            const size_t wrow = (size_t)(n0 + nt * 8 + gi) * 256 + k * 16 + tig * 2;
            unsigned b0h = *reinterpret_cast<const unsigned*>(g_w1th + wrow);
            unsigned b1h = *reinterpret_cast<const unsigned*>(g_w1th + wrow + 8);
            unsigned b0l = *reinterpret_cast<const unsigned*>(g_w1tl + wrow);
            unsigned b1l = *reinterpret_cast<const unsigned*>(g_w1tl + wrow + 8);
            mma16816(acc[nt], ah, b0h, b1h);
            mma16816(acc[nt], al, b0h, b1h);
            mma16816(acc[nt], ah, b0l, b1l);
        }
    }

    // epilogue: scatter into a / b(silu) / c^T
#pragma unroll
    for (int nt = 0; nt < 8; nt++) {
        const int col = n0 + nt * 8 + tig * 2;
        if (col >= 120) continue;
        const int proj = col / 40, c = col % 40;
#pragma unroll
        for (int half = 0; half < 2; half++) {
            const int r = row0 + gi + half * 8;
            float v0 = acc[nt][2 * half], v1 = acc[nt][2 * half + 1];
            if (proj == 0) {
                *reinterpret_cast<unsigned*>(g_ahalf + (size_t)r * 40 + c) =
                    packh2(v0, v1);
            } else if (proj == 1) {
                v0 = v0 / (1.0f + __expf(-v0));
                v1 = v1 / (1.0f + __expf(-v1));
                *reinterpret_cast<unsigned*>(g_b + (size_t)r * 40 + c) =
                    packh2(v0, v1);
            } else {
                const int bb = r >> 10, n = r & 1023;
                g_ct[((size_t)bb * 40 + c) * 1024 + n]       = __float2half_rn(v0);
                g_ct[((size_t)bb * 40 + c + 1) * 1024 + n]   = __float2half_rn(v1);
            }
        }
    }
}

// ---------------------------------------------------------------------------
// Flash attention v5 (unchanged from R9): in-kernel qf, ones-row l, 2 CTA/SM.
// ---------------------------------------------------------------------------
#define CTS   72
#define CT_BUFSZ (41 * CTS)
#define CT_REGION (4 * CT_BUFSZ + 7 * CTS)
#define WVSZ  2560
#define B_HALVES 40960
#define ATTN_SMEM ((B_HALVES + CT_REGION + WVSZ) * 2)

__global__ __launch_bounds__(256, 2) void attn_kernel() {
    extern __shared__ __half sm[];
    __half* b_s  = sm;
    __half* ct_s = sm + B_HALVES;
    __half* wv_s = sm + B_HALVES + CT_REGION;

    const int b = blockIdx.y;
    const int qt = blockIdx.x;
    const int h = qt >> 3;
    const int n0 = (qt & 7) * 128;
    const int tid = threadIdx.x;
    const int w = tid >> 5, lane = tid & 31;
    const int gi = lane >> 2, tig = lane & 3;
    const int l8 = lane & 7, mrow = lane >> 3;
    const int r8 = (lane >> 3) * 8 + (lane & 7);

    const __half* gb = g_b + (size_t)b * 1024 * 40;
    const __half* gct = g_ct + (size_t)b * 40 * 1024;

    for (int idx = tid; idx < 5120; idx += 256)
        cp16(&b_s[idx * 8], gb + idx * 8);
#pragma unroll
    for (int pf = 0; pf < 2; pf++) {
        __half* dc = ct_s + pf * CT_BUFSZ;
        for (int idx = tid; idx < 320; idx += 256) {
            int row = idx >> 3, seg = idx & 7;
            cp16(&dc[row * CTS + seg * 8], gct + (size_t)row * 1024 + pf * 64 + seg * 8);
        }
    }
    for (int idx = tid; idx < 320; idx += 256)
        cp16(&wv_s[idx * 8], g_wv2t + idx * 8);
    asm volatile("cp.async.commit_group;\n");
    asm volatile("cp.async.wait_group 0;\n");
    if (tid < 128) {
        int bufi = tid >> 5, seg = tid & 31;
        *reinterpret_cast<unsigned*>(&ct_s[bufi * CT_BUFSZ + 40 * CTS + seg * 2]) =
            0x3C003C00u;
    }
    __syncthreads();

    float m[2] = {-1e30f, -1e30f}, l[2] = {0.f, 0.f};
    float O[8][4], T[6][4];
#pragma unroll
    for (int dt = 0; dt < 8; dt++)
#pragma unroll
        for (int q = 0; q < 4; q++) O[dt][q] = 0.f;
#pragma unroll
    for (int n = 0; n < 6; n++)
#pragma unroll
        for (int q = 0; q < 4; q++) T[n][q] = 0.f;

    unsigned qf[2][4], qf8[2];
    const __half* ar0 = g_ahalf + (size_t)(((b << 10) | n0) + w * 16 + gi) * 40;
    const __half* ar1 = ar0 + 8 * 40;

    for (int tt = 0; tt < 128; tt += 2) {
        const int hp = tt >> 4;

        asm volatile("cp.async.wait_group 0;\n");
        __syncthreads();

        if (tt + 2 < 128) {
#pragma unroll
            for (int pf = 0; pf < 2; pf++) {
                int ntile = tt + 2 + pf;
                int key0 = (ntile & 15) * 64;
                __half* dc = ct_s + (ntile & 3) * CT_BUFSZ;
                for (int idx = tid; idx < 320; idx += 256) {
                    int row = idx >> 3, seg = idx & 7;
                    cp16(&dc[row * CTS + seg * 8],
                         gct + (size_t)row * 1024 + key0 + seg * 8);
                }
            }
        }
        if ((tt & 15) == 0 && tt > 0) {
            const __half* gw = g_wv2t + (size_t)hp * 2560;
            for (int idx = tid; idx < 320; idx += 256)
                cp16(&wv_s[idx * 8], gw + idx * 8);
        }
        asm volatile("cp.async.commit_group;\n");

        if ((tt & 15) == 0) {
            unsigned af[2][4], af8[2];
#pragma unroll
            for (int kc = 0; kc < 2; kc++) {
                int cc = kc * 16 + tig * 2;
                af[kc][0] = *reinterpret_cast<const unsigned*>(ar0 + cc);
                af[kc][1] = *reinterpret_cast<const unsigned*>(ar1 + cc);
                af[kc][2] = *reinterpret_cast<const unsigned*>(ar0 + cc + 8);
                af[kc][3] = *reinterpret_cast<const unsigned*>(ar1 + cc + 8);
            }
            af8[0] = *reinterpret_cast<const unsigned*>(ar0 + 32 + tig * 2);
            af8[1] = *reinterpret_cast<const unsigned*>(ar1 + 32 + tig * 2);

            const __half* gg = g_gt + (size_t)(h * 8 + hp) * 1600;
            float tq[5][4];
#pragma unroll
            for (int nt = 0; nt < 5; nt++) {
                const __half* gr = gg + (nt * 8 + gi) * 40 + tig * 2;
                unsigned g0 = *reinterpret_cast<const unsigned*>(gr);
                unsigned g1 = *reinterpret_cast<const unsigned*>(gr + 8);
                unsigned g2 = *reinterpret_cast<const unsigned*>(gr + 16);
                unsigned g3 = *reinterpret_cast<const unsigned*>(gr + 24);
                unsigned g4 = *reinterpret_cast<const unsigned*>(gr + 32);
                tq[nt][0] = tq[nt][1] = tq[nt][2] = tq[nt][3] = 0.f;
                mma16816(tq[nt], af[0], g0, g1);
                mma16816(tq[nt], af[1], g2, g3);
                mma16808(tq[nt], af8[0], af8[1], g4);
            }
#pragma unroll
            for (int kc = 0; kc < 2; kc++) {
                qf[kc][0] = packh2(tq[2 * kc][0],     tq[2 * kc][1]);
                qf[kc][1] = packh2(tq[2 * kc][2],     tq[2 * kc][3]);
                qf[kc][2] = packh2(tq[2 * kc + 1][0], tq[2 * kc + 1][1]);
                qf[kc][3] = packh2(tq[2 * kc + 1][2], tq[2 * kc + 1][3]);
            }
            qf8[0] = packh2(tq[4][0], tq[4][1]);
            qf8[1] = packh2(tq[4][2], tq[4][3]);
        }

#pragma unroll
        for (int sub = 0; sub < 2; sub++) {
            const int tile = tt + sub;
            const int t = tile & 15;
            const __half* ct_t = ct_s + (tile & 3) * CT_BUFSZ;

            unsigned kb8v[8];
            ldsm_x4(kb8v[0], kb8v[1], kb8v[2], kb8v[3],
                    &b_s[(t * 64 + r8) * 40 + 32]);
            ldsm_x4(kb8v[4], kb8v[5], kb8v[6], kb8v[7],
                    &b_s[(t * 64 + 32 + r8) * 40 + 32]);

            float S[8][4];
#pragma unroll
            for (int nt = 0; nt < 8; nt++)
#pragma unroll
                for (int q = 0; q < 4; q++) S[nt][q] = 0.f;

#pragma unroll
            for (int nt = 0; nt < 8; nt++) {
                unsigned kb0[2], kb1[2];
                ldsm_x4(kb0[0], kb1[0], kb0[1], kb1[1],
                        &b_s[(t * 64 + nt * 8 + l8) * 40 + mrow * 8]);
                mma16816(S[nt], qf[0], kb0[0], kb1[0]);
                mma16816(S[nt], qf[1], kb0[1], kb1[1]);
                mma16808(S[nt], qf8[0], qf8[1], kb8v[nt]);
            }

#pragma unroll
            for (int h2 = 0; h2 < 2; h2++) {
                float tm = -1e30f;
#pragma unroll
                for (int nt = 0; nt < 8; nt++)
                    tm = fmaxf(tm, fmaxf(S[nt][2 * h2], S[nt][2 * h2 + 1]));
                tm = fmaxf(tm, __shfl_xor_sync(0xffffffffu, tm, 1));
                tm = fmaxf(tm, __shfl_xor_sync(0xffffffffu, tm, 2));
                if (tm > m[h2]) {
                    float al = ex2f(m[h2] - tm);
                    m[h2] = tm;
                    l[h2] *= al;
#pragma unroll
                    for (int dt = 0; dt < 8; dt++) {
                        O[dt][2 * h2] *= al;
                        O[dt][2 * h2 + 1] *= al;
                    }
#pragma unroll
                    for (int n = 0; n < 6; n++) {
                        T[n][2 * h2] *= al;
                        T[n][2 * h2 + 1] *= al;
                    }
                }
            }

            unsigned pa[4][4];
#pragma unroll
            for (int nt = 0; nt < 8; nt++) {
                unsigned p01 = ex2h2(S[nt][0] - m[0], S[nt][1] - m[0]);
                unsigned p23 = ex2h2(S[nt][2] - m[1], S[nt][3] - m[1]);
                pa[nt >> 1][(nt & 1) * 2]     = p01;
                pa[nt >> 1][(nt & 1) * 2 + 1] = p23;
            }

#pragma unroll
            for (int n = 0; n < 6; n++) {
                unsigned vb0[4], vb1[4];
                const __half* va = &ct_t[(n * 8 + l8) * CTS + mrow * 8];
                ldsm_x4(vb0[0], vb1[0], vb0[1], vb1[1], va);
                ldsm_x4(vb0[2], vb1[2], vb0[3], vb1[3], va + 32);
#pragma unroll
                for (int kc = 0; kc < 4; kc++)
                    mma16816(T[n], pa[kc], vb0[kc], vb1[kc]);
            }

            if (t == 15) {
                unsigned at16[2][4], at8a, at8b;
#pragma unroll
                for (int kc = 0; kc < 2; kc++) {
                    at16[kc][0] = packh2(T[2 * kc][0],     T[2 * kc][1]);
                    at16[kc][1] = packh2(T[2 * kc][2],     T[2 * kc][3]);
                    at16[kc][2] = packh2(T[2 * kc + 1][0], T[2 * kc + 1][1]);
                    at16[kc][3] = packh2(T[2 * kc + 1][2], T[2 * kc + 1][3]);
                }
                at8a = packh2(T[4][0], T[4][1]);
                at8b = packh2(T[4][2], T[4][3]);

                unsigned wb8v[8];
                ldsm_x4(wb8v[0], wb8v[1], wb8v[2], wb8v[3],
                        &wv_s[r8 * 40 + 32]);
                ldsm_x4(wb8v[4], wb8v[5], wb8v[6], wb8v[7],
                        &wv_s[(32 + r8) * 40 + 32]);

#pragma unroll
                for (int dt = 0; dt < 8; dt++) {
                    unsigned wb0[2], wb1[2];
                    ldsm_x4(wb0[0], wb1[0], wb0[1], wb1[1],
                            &wv_s[(dt * 8 + l8) * 40 + mrow * 8]);
                    mma16816(O[dt], at16[0], wb0[0], wb1[0]);
                    mma16816(O[dt], at16[1], wb0[1], wb1[1]);
                    mma16808(O[dt], at8a, at8b, wb8v[dt]);
                }
                if (tig == 0) {
                    l[0] += T[5][0];
                    l[1] += T[5][2];
                }
#pragma unroll
                for (int n = 0; n < 6; n++)
#pragma unroll
                    for (int q = 0; q < 4; q++) T[n][q] = 0.f;
            }
        }
    }

#pragma unroll
    for (int h2 = 0; h2 < 2; h2++) {
        float lt = __shfl_sync(0xffffffffu, l[h2], lane & 28);
        float inv = 1.0f / lt;
        int n = n0 + w * 16 + gi + h2 * 8;
        __half* orow = g_attn16 + ((size_t)((b << 10) | n)) * 512 + h * 64;
#pragma unroll
        for (int dt = 0; dt < 8; dt++) {
            *reinterpret_cast<unsigned*>(orow + dt * 8 + tig * 2) =
                packh2(O[dt][2 * h2] * inv, O[dt][2 * h2 + 1] * inv);
        }
    }
}

// ---------------------------------------------------------------------------
// out_gemm via fp16 mma (unchanged)
// ---------------------------------------------------------------------------
__global__ __launch_bounds__(128) void out_gemm(
    const float* __restrict__ bo, float* __restrict__ out) {
    __shared__ __half sA2[64 * 72];
    __shared__ __half sB2[64 * 72];

    const int bm0 = blockIdx.x * 64;
    const int bn0 = blockIdx.y * 64;
    const int tid = threadIdx.x;
    const int w = tid >> 5, lane = tid & 31;
    const int gi = lane >> 2, tig = lane & 3;
    const int l8 = lane & 7, mrow = lane >> 3;

    float acc[8][4];
#pragma unroll
    for (int nt = 0; nt < 8; nt++)
#pragma unroll
        for (int q = 0; q < 4; q++) acc[nt][q] = 0.f;

    const int ar = (lane & 15);
    const int ac = (lane >> 4) * 8;

    for (int kc = 0; kc < 8; kc++) {
        __syncthreads();
        for (int idx = tid; idx < 512; idx += 128) {
            int r = idx >> 3, s = idx & 7;
            cp16(&sA2[r * 72 + s * 8],
                 g_attn16 + (size_t)(bm0 + r) * 512 + kc * 64 + s * 8);
            cp16(&sB2[r * 72 + s * 8],
                 g_woT + (size_t)(bn0 + r) * 512 + kc * 64 + s * 8);
        }
        asm volatile("cp.async.commit_group;\n");
        asm volatile("cp.async.wait_group 0;\n");
        __syncthreads();

        const int m0 = w * 16;
#pragma unroll
        for (int ksp = 0; ksp < 2; ksp++) {
            unsigned af0[4], af1[4];
            ldsm_x4(af0[0], af0[1], af0[2], af0[3],
                    &sA2[(m0 + ar) * 72 + ksp * 32 + ac]);
            ldsm_x4(af1[0], af1[1], af1[2], af1[3],
                    &sA2[(m0 + ar) * 72 + ksp * 32 + 16 + ac]);
#pragma unroll
            for (int nt = 0; nt < 8; nt++) {
                unsigned b0a, b1a, b0b, b1b;
                ldsm_x4(b0a, b1a, b0b, b1b,
                        &sB2[(nt * 8 + l8) * 72 + ksp * 32 + mrow * 8]);
                mma16816(acc[nt], af0, b0a, b1a);
                mma16816(acc[nt], af1, b0b, b1b);
            }
        }
    }

    const int r0 = bm0 + w * 16 + gi;
#pragma unroll
    for (int nt = 0; nt < 8; nt++) {
        int col = bn0 + nt * 8 + tig * 2;
        float b0 = bo[col], b1 = bo[col + 1];
        float2 o0 = make_float2(acc[nt][0] + b0, acc[nt][1] + b1);
        float2 o1 = make_float2(acc[nt][2] + b0, acc[nt][3] + b1);
        *reinterpret_cast<float2*>(out + (size_t)r0 * 256 + col) = o0;
        *reinterpret_cast<float2*>(out + (size_t)(r0 + 8) * 256 + col) = o1;
    }
}

// ---------------------------------------------------------------------------
extern "C" void kernel_launch(void* const* d_in, const int* in_sizes, int n_in,
                              void* d_out, int out_size) {
    const float* x   = (const float*)d_in[0];
    const float* wq1 = (const float*)d_in[1];
    const float* wq2 = (const float*)d_in[2];
    const float* wk1 = (const float*)d_in[3];
    const float* wk2 = (const float*)d_in[4];
    const float* wv1 = (const float*)d_in[5];
    const float* wv2 = (const float*)d_in[6];
    const float* wo  = (const float*)d_in[7];
    const float* bo  = (const float*)d_in[8];
    float* out = (float*)d_out;

    cudaFuncSetAttribute(attn_kernel, cudaFuncAttributeMaxDynamicSharedMemorySize,
                         ATTN_SMEM);

    pre_kernel<<<266, 256>>>(x, wq1, wk1, wv1, wq2, wk2, wv2, wo);
    proj_mma<<<128, 128>>>();
    attn_kernel<<<dim3(64, 4), 256, ATTN_SMEM>>>();
    out_gemm<<<dim3(64, 4), 128>>>(bo, out);
}

// round 11
// speedup vs baseline: 1.6651x; 1.0132x over previous
#include <cuda_runtime.h>
#include <cuda_fp16.h>
#include <cstdint>

#define NN    1024
#define QSZ   256
#define BOT   40

// ------------------------- scratch (no allocs allowed) -----------------------
__device__ __half g_x16h[(size_t)4096 * 256];          // x hi (fp16)
__device__ __half g_x16l[(size_t)4096 * 256];          // x lo (fp16)
__device__ __half g_w1th[(size_t)128 * 256];           // w1^T hi [n][k]
__device__ __half g_w1tl[(size_t)128 * 256];           // w1^T lo
__device__ __half g_ahalf[(size_t)4096 * 40];          // a = x@wq1 (fp16)
__device__ __half g_b[(size_t)4096 * 40];              // b = silu(x@wk1)
__device__ __half g_ct[(size_t)4 * 40 * 1024];         // c^T  [b][40][n]
__device__ __half g_gt[(size_t)64 * 1600];             // G^T per (h,hp)
__device__ __half g_wv2t[(size_t)8 * 64 * 40];         // wv2^T per head [h][d][40]
__device__ __half g_attn16[(size_t)4096 * 512];        // attention out (fp16)
__device__ __half g_woT[(size_t)256 * 512];            // wo^T fp16 [n][k]

__device__ __forceinline__ float ex2f(float x) {
    float y;
    asm("ex2.approx.ftz.f32 %0, %1;" : "=f"(y) : "f"(x));
    return y;
}

__device__ __forceinline__ unsigned ex2h2(float a, float b) {
    __half2 h = __floats2half2_rn(a, b);
    unsigned u = *reinterpret_cast<unsigned*>(&h);
    unsigned r;
    asm("ex2.approx.f16x2 %0, %1;" : "=r"(r) : "r"(u));
    return r;
}

__device__ __forceinline__ unsigned packh2(float a, float b) {
    __half2 h = __floats2half2_rn(a, b);
    return *reinterpret_cast<unsigned*>(&h);
}

__device__ __forceinline__ void mma16816(float (&c)[4], const unsigned (&a)[4],
                                         unsigned b0, unsigned b1) {
    asm volatile(
        "mma.sync.aligned.m16n8k16.row.col.f32.f16.f16.f32 "
        "{%0,%1,%2,%3}, {%4,%5,%6,%7}, {%8,%9}, {%0,%1,%2,%3};\n"
        : "+f"(c[0]), "+f"(c[1]), "+f"(c[2]), "+f"(c[3])
        : "r"(a[0]), "r"(a[1]), "r"(a[2]), "r"(a[3]), "r"(b0), "r"(b1));
}

__device__ __forceinline__ void mma16808(float (&c)[4], unsigned a0, unsigned a1,
                                         unsigned b0) {
    asm volatile(
        "mma.sync.aligned.m16n8k8.row.col.f32.f16.f16.f32 "
        "{%0,%1,%2,%3}, {%4,%5}, {%6}, {%0,%1,%2,%3};\n"
        : "+f"(c[0]), "+f"(c[1]), "+f"(c[2]), "+f"(c[3])
        : "r"(a0), "r"(a1), "r"(b0));
}

__device__ __forceinline__ void cp16(void* s, const void* g) {
    unsigned sa = (unsigned)__cvta_generic_to_shared(s);
    asm volatile("cp.async.cg.shared.global [%0], [%1], 16;\n" :: "r"(sa), "l"(g));
}

__device__ __forceinline__ void ldsm_x4(unsigned& r0, unsigned& r1, unsigned& r2,
                                        unsigned& r3, const void* p) {
    unsigned a = (unsigned)__cvta_generic_to_shared(p);
    asm volatile("ldmatrix.sync.aligned.m8n8.x4.shared.b16 {%0,%1,%2,%3}, [%4];"
                 : "=r"(r0), "=r"(r1), "=r"(r2), "=r"(r3) : "r"(a));
}

// ---------------------------------------------------------------------------
// pre_kernel v3: x convert (0..127) + gmat (128..191) + wv2t transpose
// (192..199) + wo transpose (200..231) + w1t hi/lo (232..233). grid 234.
// ---------------------------------------------------------------------------
__global__ __launch_bounds__(256) void pre_kernel(
    const float* __restrict__ x,
    const float* __restrict__ wq1, const float* __restrict__ wk1,
    const float* __restrict__ wv1,
    const float* __restrict__ wq2, const float* __restrict__ wk2,
    const float* __restrict__ wv2, const float* __restrict__ wo) {
    __shared__ float sf[5200];

    const int bx = blockIdx.x;
    const int tid = threadIdx.x;

    if (bx < 128) {
        // ---- x split-convert ----
        const float4* x4 = reinterpret_cast<const float4*>(x) + (size_t)bx * 2048;
        uint2* dh = reinterpret_cast<uint2*>(g_x16h) + (size_t)bx * 2048;
        uint2* dl = reinterpret_cast<uint2*>(g_x16l) + (size_t)bx * 2048;
        for (int i = tid; i < 2048; i += 256) {
            float4 v = x4[i];
            __half h0 = __float2half_rn(v.x), h1 = __float2half_rn(v.y);
            __half h2 = __float2half_rn(v.z), h3 = __float2half_rn(v.w);
            float l0 = v.x - __half2float(h0), l1 = v.y - __half2float(h1);
            float l2 = v.z - __half2float(h2), l3 = v.w - __half2float(h3);
            __half2 hh0 = __halves2half2(h0, h1), hh1 = __halves2half2(h2, h3);
            dh[i] = make_uint2(*reinterpret_cast<unsigned*>(&hh0),
                               *reinterpret_cast<unsigned*>(&hh1));
            __half2 ll0 = __floats2half2_rn(l0, l1), ll1 = __floats2half2_rn(l2, l3);
            dl[i] = make_uint2(*reinterpret_cast<unsigned*>(&ll0),
                               *reinterpret_cast<unsigned*>(&ll1));
        }
    } else if (bx < 192) {
        // ---- gmat ----
        float (*sQ)[65] = reinterpret_cast<float (*)[65]>(sf);
        float (*sK)[65] = reinterpret_cast<float (*)[65]>(sf + 2600);
        const int id = bx - 128;
        const int h = id >> 3, hp = id & 7;
        for (int idx = tid; idx < 2560; idx += 256) {
            int k = idx >> 6, d = idx & 63;
            sQ[k][d] = wq2[(size_t)k * 512 + h * 64 + d];
            sK[k][d] = wk2[(size_t)k * 512 + hp * 64 + d];
        }
        __syncthreads();
        const float SCALE = 0.125f * 1.4426950408889634f;
        for (int idx = tid; idx < 1600; idx += 256) {
            int c = idx / 40, k = idx % 40;
            float s = 0.f;
#pragma unroll 8
            for (int d = 0; d < 64; d++) s += sQ[k][d] * sK[c][d];
            g_gt[(size_t)id * 1600 + c * 40 + k] = __float2half_rn(s * SCALE);
        }
    } else if (bx < 200) {
        // ---- wv2t via smem transpose: load [40k][64d] coalesced, write [d][k] ----
        float (*sT)[65] = reinterpret_cast<float (*)[65]>(sf);
        const int h = bx - 192;
        for (int idx = tid; idx < 2560; idx += 256) {
            int k = idx >> 6, d = idx & 63;
            sT[k][d] = wv2[(size_t)k * 512 + h * 64 + d];
        }
        __syncthreads();
        for (int idx = tid; idx < 2560; idx += 256) {
            int d = idx / 40, k = idx % 40;
            g_wv2t[(size_t)h * 2560 + idx] = __float2half_rn(sT[k][d]);
        }
    } else if (bx < 232) {
        // ---- wo transpose 64x64 tiles: both gmem sides coalesced ----
        float (*sT)[65] = reinterpret_cast<float (*)[65]>(sf);
        const int blk = bx - 200;
        const int k0 = (blk & 7) * 64, n0 = (blk >> 3) * 64;
#pragma unroll
        for (int i = 0; i < 16; i++) {
            int idx = i * 256 + tid;
            int r = idx >> 6, c = idx & 63;   // r=k, c=n
            sT[r][c] = wo[(size_t)(k0 + r) * 256 + n0 + c];
        }
        __syncthreads();
#pragma unroll
        for (int i = 0; i < 16; i++) {
            int idx = i * 256 + tid;
            int rn = idx >> 6, ck = idx & 63;
            g_woT[(size_t)(n0 + rn) * 512 + k0 + ck] = __float2half_rn(sT[ck][rn]);
        }
    } else {
        // ---- w1t hi/lo ----
        const int base = (bx - 232) * 15360;
        for (int i = tid; i < 15360; i += 256) {
            int e = base + i;
            int n = e >> 8, k = e & 255;
            int proj = n / 40, c = n % 40;
            const float* w1 = (proj == 0) ? wq1 : (proj == 1 ? wk1 : wv1);
            float v = w1[(size_t)k * 40 + c];
            __half hh = __float2half_rn(v);
            g_w1th[(size_t)n * 256 + k] = hh;
            g_w1tl[(size_t)n * 256 + k] = __float2half_rn(v - __half2float(hh));
        }
    }
}

// ---------------------------------------------------------------------------
// proj_mma (unchanged from R10)
// ---------------------------------------------------------------------------
__global__ __launch_bounds__(128) void proj_mma() {
    const int tid = threadIdx.x;
    const int w = tid >> 5, lane = tid & 31;
    const int gi = lane >> 2, tig = lane & 3;
    const int row0 = blockIdx.x * 32 + (w & 1) * 16;
    const int n0 = (w >> 1) * 64;

    const __half* xh0 = g_x16h + (size_t)(row0 + gi) * 256;
    const __half* xh8 = xh0 + 8 * 256;
    const __half* xl0 = g_x16l + (size_t)(row0 + gi) * 256;
    const __half* xl8 = xl0 + 8 * 256;

    float acc[8][4];
#pragma unroll
    for (int nt = 0; nt < 8; nt++)
#pragma unroll
        for (int q = 0; q < 4; q++) acc[nt][q] = 0.f;

#pragma unroll
    for (int k = 0; k < 16; k++) {
        const int kc = k * 16 + tig * 2;
        unsigned ah[4], al[4];
        ah[0] = *reinterpret_cast<const unsigned*>(xh0 + kc);
        ah[1] = *reinterpret_cast<const unsigned*>(xh8 + kc);
        ah[2] = *reinterpret_cast<const unsigned*>(xh0 + kc + 8);
        ah[3] = *reinterpret_cast<const unsigned*>(xh8 + kc + 8);
        al[0] = *reinterpret_cast<const unsigned*>(xl0 + kc);
        al[1] = *reinterpret_cast<const unsigned*>(xl8 + kc);
        al[2] = *reinterpret_cast<const unsigned*>(xl0 + kc + 8);
        al[3] = *reinterpret_cast<const unsigned*>(xl8 + kc + 8);

#pragma unroll
        for (int nt = 0; nt < 8; nt++) {
            const size_t wrow = (size_t)(n0 + nt * 8 + gi) * 256 + k * 16 + tig * 2;
            unsigned b0h = *reinterpret_cast<const unsigned*>(g_w1th + wrow);
            unsigned b1h = *reinterpret_cast<const unsigned*>(g_w1th + wrow + 8);
            unsigned b0l = *reinterpret_cast<const unsigned*>(g_w1tl + wrow);
            unsigned b1l = *reinterpret_cast<const unsigned*>(g_w1tl + wrow + 8);
            mma16816(acc[nt], ah, b0h, b1h);
            mma16816(acc[nt], al, b0h, b1h);
            mma16816(acc[nt], ah, b0l, b1l);
        }
    }

#pragma unroll
    for (int nt = 0; nt < 8; nt++) {
        const int col = n0 + nt * 8 + tig * 2;
        if (col >= 120) continue;
        const int proj = col / 40, c = col % 40;
#pragma unroll
        for (int half = 0; half < 2; half++) {
            const int r = row0 + gi + half * 8;
            float v0 = acc[nt][2 * half], v1 = acc[nt][2 * half + 1];
            if (proj == 0) {
                *reinterpret_cast<unsigned*>(g_ahalf + (size_t)r * 40 + c) =
                    packh2(v0, v1);
            } else if (proj == 1) {
                v0 = v0 / (1.0f + __expf(-v0));
                v1 = v1 / (1.0f + __expf(-v1));
                *reinterpret_cast<unsigned*>(g_b + (size_t)r * 40 + c) =
                    packh2(v0, v1);
            } else {
                const int bb = r >> 10, n = r & 1023;
                g_ct[((size_t)bb * 40 + c) * 1024 + n]     = __float2half_rn(v0);
                g_ct[((size_t)bb * 40 + c + 1) * 1024 + n] = __float2half_rn(v1);
            }
        }
    }
}

// ---------------------------------------------------------------------------
// Flash attention v5 (byte-identical to R10)
// ---------------------------------------------------------------------------
#define CTS   72
#define CT_BUFSZ (41 * CTS)
#define CT_REGION (4 * CT_BUFSZ + 7 * CTS)
#define WVSZ  2560
#define B_HALVES 40960
#define ATTN_SMEM ((B_HALVES + CT_REGION + WVSZ) * 2)

__global__ __launch_bounds__(256, 2) void attn_kernel() {
    extern __shared__ __half sm[];
    __half* b_s  = sm;
    __half* ct_s = sm + B_HALVES;
    __half* wv_s = sm + B_HALVES + CT_REGION;

    const int b = blockIdx.y;
    const int qt = blockIdx.x;
    const int h = qt >> 3;
    const int n0 = (qt & 7) * 128;
    const int tid = threadIdx.x;
    const int w = tid >> 5, lane = tid & 31;
    const int gi = lane >> 2, tig = lane & 3;
    const int l8 = lane & 7, mrow = lane >> 3;
    const int r8 = (lane >> 3) * 8 + (lane & 7);

    const __half* gb = g_b + (size_t)b * 1024 * 40;
    const __half* gct = g_ct + (size_t)b * 40 * 1024;

    for (int idx = tid; idx < 5120; idx += 256)
        cp16(&b_s[idx * 8], gb + idx * 8);
#pragma unroll
    for (int pf = 0; pf < 2; pf++) {
        __half* dc = ct_s + pf * CT_BUFSZ;
        for (int idx = tid; idx < 320; idx += 256) {
            int row = idx >> 3, seg = idx & 7;
            cp16(&dc[row * CTS + seg * 8], gct + (size_t)row * 1024 + pf * 64 + seg * 8);
        }
    }
    for (int idx = tid; idx < 320; idx += 256)
        cp16(&wv_s[idx * 8], g_wv2t + idx * 8);
    asm volatile("cp.async.commit_group;\n");
    asm volatile("cp.async.wait_group 0;\n");
    if (tid < 128) {
        int bufi = tid >> 5, seg = tid & 31;
        *reinterpret_cast<unsigned*>(&ct_s[bufi * CT_BUFSZ + 40 * CTS + seg * 2]) =
            0x3C003C00u;
    }
    __syncthreads();

    float m[2] = {-1e30f, -1e30f}, l[2] = {0.f, 0.f};
    float O[8][4], T[6][4];
#pragma unroll
    for (int dt = 0; dt < 8; dt++)
#pragma unroll
        for (int q = 0; q < 4; q++) O[dt][q] = 0.f;
#pragma unroll
    for (int n = 0; n < 6; n++)
#pragma unroll
        for (int q = 0; q < 4; q++) T[n][q] = 0.f;

    unsigned qf[2][4], qf8[2];
    const __half* ar0 = g_ahalf + (size_t)(((b << 10) | n0) + w * 16 + gi) * 40;
    const __half* ar1 = ar0 + 8 * 40;

    for (int tt = 0; tt < 128; tt += 2) {
        const int hp = tt >> 4;

        asm volatile("cp.async.wait_group 0;\n");
        __syncthreads();

        if (tt + 2 < 128) {
#pragma unroll
            for (int pf = 0; pf < 2; pf++) {
                int ntile = tt + 2 + pf;
                int key0 = (ntile & 15) * 64;
                __half* dc = ct_s + (ntile & 3) * CT_BUFSZ;
                for (int idx = tid; idx < 320; idx += 256) {
                    int row = idx >> 3, seg = idx & 7;
                    cp16(&dc[row * CTS + seg * 8],
                         gct + (size_t)row * 1024 + key0 + seg * 8);
                }
            }
        }
        if ((tt & 15) == 0 && tt > 0) {
            const __half* gw = g_wv2t + (size_t)hp * 2560;
            for (int idx = tid; idx < 320; idx += 256)
                cp16(&wv_s[idx * 8], gw + idx * 8);
        }
        asm volatile("cp.async.commit_group;\n");

        if ((tt & 15) == 0) {
            unsigned af[2][4], af8[2];
#pragma unroll
            for (int kc = 0; kc < 2; kc++) {
                int cc = kc * 16 + tig * 2;
                af[kc][0] = *reinterpret_cast<const unsigned*>(ar0 + cc);
                af[kc][1] = *reinterpret_cast<const unsigned*>(ar1 + cc);
                af[kc][2] = *reinterpret_cast<const unsigned*>(ar0 + cc + 8);
                af[kc][3] = *reinterpret_cast<const unsigned*>(ar1 + cc + 8);
            }
            af8[0] = *reinterpret_cast<const unsigned*>(ar0 + 32 + tig * 2);
            af8[1] = *reinterpret_cast<const unsigned*>(ar1 + 32 + tig * 2);

            const __half* gg = g_gt + (size_t)(h * 8 + hp) * 1600;
            float tq[5][4];
#pragma unroll
            for (int nt = 0; nt < 5; nt++) {
                const __half* gr = gg + (nt * 8 + gi) * 40 + tig * 2;
                unsigned g0 = *reinterpret_cast<const unsigned*>(gr);
                unsigned g1 = *reinterpret_cast<const unsigned*>(gr + 8);
                unsigned g2 = *reinterpret_cast<const unsigned*>(gr + 16);
                unsigned g3 = *reinterpret_cast<const unsigned*>(gr + 24);
                unsigned g4 = *reinterpret_cast<const unsigned*>(gr + 32);
                tq[nt][0] = tq[nt][1] = tq[nt][2] = tq[nt][3] = 0.f;
                mma16816(tq[nt], af[0], g0, g1);
                mma16816(tq[nt], af[1], g2, g3);
                mma16808(tq[nt], af8[0], af8[1], g4);
            }
#pragma unroll
            for (int kc = 0; kc < 2; kc++) {
                qf[kc][0] = packh2(tq[2 * kc][0],     tq[2 * kc][1]);
                qf[kc][1] = packh2(tq[2 * kc][2],     tq[2 * kc][3]);
                qf[kc][2] = packh2(tq[2 * kc + 1][0], tq[2 * kc + 1][1]);
                qf[kc][3] = packh2(tq[2 * kc + 1][2], tq[2 * kc + 1][3]);
            }
            qf8[0] = packh2(tq[4][0], tq[4][1]);
            qf8[1] = packh2(tq[4][2], tq[4][3]);
        }

#pragma unroll
        for (int sub = 0; sub < 2; sub++) {
            const int tile = tt + sub;
            const int t = tile & 15;
            const __half* ct_t = ct_s + (tile & 3) * CT_BUFSZ;

            unsigned kb8v[8];
            ldsm_x4(kb8v[0], kb8v[1], kb8v[2], kb8v[3],
                    &b_s[(t * 64 + r8) * 40 + 32]);
            ldsm_x4(kb8v[4], kb8v[5], kb8v[6], kb8v[7],
                    &b_s[(t * 64 + 32 + r8) * 40 + 32]);

            float S[8][4];
#pragma unroll
            for (int nt = 0; nt < 8; nt++)
#pragma unroll
                for (int q = 0; q < 4; q++) S[nt][q] = 0.f;

#pragma unroll
            for (int nt = 0; nt < 8; nt++) {
                unsigned kb0[2], kb1[2];
                ldsm_x4(kb0[0], kb1[0], kb0[1], kb1[1],
                        &b_s[(t * 64 + nt * 8 + l8) * 40 + mrow * 8]);
                mma16816(S[nt], qf[0], kb0[0], kb1[0]);
                mma16816(S[nt], qf[1], kb0[1], kb1[1]);
                mma16808(S[nt], qf8[0], qf8[1], kb8v[nt]);
            }

#pragma unroll
            for (int h2 = 0; h2 < 2; h2++) {
                float tm = -1e30f;
#pragma unroll
                for (int nt = 0; nt < 8; nt++)
                    tm = fmaxf(tm, fmaxf(S[nt][2 * h2], S[nt][2 * h2 + 1]));
                tm = fmaxf(tm, __shfl_xor_sync(0xffffffffu, tm, 1));
                tm = fmaxf(tm, __shfl_xor_sync(0xffffffffu, tm, 2));
                if (tm > m[h2]) {
                    float al = ex2f(m[h2] - tm);
                    m[h2] = tm;
                    l[h2] *= al;
#pragma unroll
                    for (int dt = 0; dt < 8; dt++) {
                        O[dt][2 * h2] *= al;
                        O[dt][2 * h2 + 1] *= al;
                    }
#pragma unroll
                    for (int n = 0; n < 6; n++) {
                        T[n][2 * h2] *= al;
                        T[n][2 * h2 + 1] *= al;
                    }
                }
            }

            unsigned pa[4][4];
#pragma unroll
            for (int nt = 0; nt < 8; nt++) {
                unsigned p01 = ex2h2(S[nt][0] - m[0], S[nt][1] - m[0]);
                unsigned p23 = ex2h2(S[nt][2] - m[1], S[nt][3] - m[1]);
                pa[nt >> 1][(nt & 1) * 2]     = p01;
                pa[nt >> 1][(nt & 1) * 2 + 1] = p23;
            }

#pragma unroll
            for (int n = 0; n < 6; n++) {
                unsigned vb0[4], vb1[4];
                const __half* va = &ct_t[(n * 8 + l8) * CTS + mrow * 8];
                ldsm_x4(vb0[0], vb1[0], vb0[1], vb1[1], va);
                ldsm_x4(vb0[2], vb1[2], vb0[3], vb1[3], va + 32);
#pragma unroll
                for (int kc = 0; kc < 4; kc++)
                    mma16816(T[n], pa[kc], vb0[kc], vb1[kc]);
            }

            if (t == 15) {
                unsigned at16[2][4], at8a, at8b;
#pragma unroll
                for (int kc = 0; kc < 2; kc++) {
                    at16[kc][0] = packh2(T[2 * kc][0],     T[2 * kc][1]);
                    at16[kc][1] = packh2(T[2 * kc][2],     T[2 * kc][3]);
                    at16[kc][2] = packh2(T[2 * kc + 1][0], T[2 * kc + 1][1]);
                    at16[kc][3] = packh2(T[2 * kc + 1][2], T[2 * kc + 1][3]);
                }
                at8a = packh2(T[4][0], T[4][1]);
                at8b = packh2(T[4][2], T[4][3]);

                unsigned wb8v[8];
                ldsm_x4(wb8v[0], wb8v[1], wb8v[2], wb8v[3],
                        &wv_s[r8 * 40 + 32]);
                ldsm_x4(wb8v[4], wb8v[5], wb8v[6], wb8v[7],
                        &wv_s[(32 + r8) * 40 + 32]);

#pragma unroll
                for (int dt = 0; dt < 8; dt++) {
                    unsigned wb0[2], wb1[2];
                    ldsm_x4(wb0[0], wb1[0], wb0[1], wb1[1],
                            &wv_s[(dt * 8 + l8) * 40 + mrow * 8]);
                    mma16816(O[dt], at16[0], wb0[0], wb1[0]);
                    mma16816(O[dt], at16[1], wb0[1], wb1[1]);
                    mma16808(O[dt], at8a, at8b, wb8v[dt]);
                }
                if (tig == 0) {
                    l[0] += T[5][0];
                    l[1] += T[5][2];
                }
#pragma unroll
                for (int n = 0; n < 6; n++)
#pragma unroll
                    for (int q = 0; q < 4; q++) T[n][q] = 0.f;
            }
        }
    }

#pragma unroll
    for (int h2 = 0; h2 < 2; h2++) {
        float lt = __shfl_sync(0xffffffffu, l[h2], lane & 28);
        float inv = 1.0f / lt;
        int n = n0 + w * 16 + gi + h2 * 8;
        __half* orow = g_attn16 + ((size_t)((b << 10) | n)) * 512 + h * 64;
#pragma unroll
        for (int dt = 0; dt < 8; dt++) {
            *reinterpret_cast<unsigned*>(orow + dt * 8 + tig * 2) =
                packh2(O[dt][2 * h2] * inv, O[dt][2 * h2 + 1] * inv);
        }
    }
}

// ---------------------------------------------------------------------------
// out_gemm v2: 2-stage cp.async pipeline, 64x64 tile, 128 thr.
// ---------------------------------------------------------------------------
__global__ __launch_bounds__(128) void out_gemm(
    const float* __restrict__ bo, float* __restrict__ out) {
    __shared__ __half sA2[2][64 * 72];
    __shared__ __half sB2[2][64 * 72];

    const int bm0 = blockIdx.x * 64;
    const int bn0 = blockIdx.y * 64;
    const int tid = threadIdx.x;
    const int w = tid >> 5, lane = tid & 31;
    const int gi = lane >> 2, tig = lane & 3;
    const int l8 = lane & 7, mrow = lane >> 3;

    float acc[8][4];
#pragma unroll
    for (int nt = 0; nt < 8; nt++)
#pragma unroll
        for (int q = 0; q < 4; q++) acc[nt][q] = 0.f;

    const int ar = (lane & 15);
    const int ac = (lane >> 4) * 8;

    // prologue: chunk 0 -> buf 0
#pragma unroll
    for (int i = 0; i < 4; i++) {
        int idx = tid + i * 128;
        int r = idx >> 3, s = idx & 7;
        cp16(&sA2[0][r * 72 + s * 8], g_attn16 + (size_t)(bm0 + r) * 512 + s * 8);
        cp16(&sB2[0][r * 72 + s * 8], g_woT + (size_t)(bn0 + r) * 512 + s * 8);
    }
    asm volatile("cp.async.commit_group;\n");

    for (int kc = 0; kc < 8; kc++) {
        const int buf = kc & 1;
        if (kc + 1 < 8) {
#pragma unroll
            for (int i = 0; i < 4; i++) {
                int idx = tid + i * 128;
                int r = idx >> 3, s = idx & 7;
                cp16(&sA2[buf ^ 1][r * 72 + s * 8],
                     g_attn16 + (size_t)(bm0 + r) * 512 + (kc + 1) * 64 + s * 8);
                cp16(&sB2[buf ^ 1][r * 72 + s * 8],
                     g_woT + (size_t)(bn0 + r) * 512 + (kc + 1) * 64 + s * 8);
            }
            asm volatile("cp.async.commit_group;\n");
            asm volatile("cp.async.wait_group 1;\n");
        } else {
            asm volatile("cp.async.wait_group 0;\n");
        }
        __syncthreads();

        const int m0 = w * 16;
#pragma unroll
        for (int ksp = 0; ksp < 2; ksp++) {
            unsigned af0[4], af1[4];
            ldsm_x4(af0[0], af0[1], af0[2], af0[3],
                    &sA2[buf][(m0 + ar) * 72 + ksp * 32 + ac]);
            ldsm_x4(af1[0], af1[1], af1[2], af1[3],
                    &sA2[buf][(m0 + ar) * 72 + ksp * 32 + 16 + ac]);
#pragma unroll
            for (int nt = 0; nt < 8; nt++) {
                unsigned b0a, b1a, b0b, b1b;
                ldsm_x4(b0a, b1a, b0b, b1b,
                        &sB2[buf][(nt * 8 + l8) * 72 + ksp * 32 + mrow * 8]);
                mma16816(acc[nt], af0, b0a, b1a);
                mma16816(acc[nt], af1, b0b, b1b);
            }
        }
        __syncthreads();
    }

    const int r0 = bm0 + w * 16 + gi;
#pragma unroll
    for (int nt = 0; nt < 8; nt++) {
        int col = bn0 + nt * 8 + tig * 2;
        float b0 = bo[col], b1 = bo[col + 1];
        float2 o0 = make_float2(acc[nt][0] + b0, acc[nt][1] + b1);
        float2 o1 = make_float2(acc[nt][2] + b0, acc[nt][3] + b1);
        *reinterpret_cast<float2*>(out + (size_t)r0 * 256 + col) = o0;
        *reinterpret_cast<float2*>(out + (size_t)(r0 + 8) * 256 + col) = o1;
    }
}

// ---------------------------------------------------------------------------
extern "C" void kernel_launch(void* const* d_in, const int* in_sizes, int n_in,
                              void* d_out, int out_size) {
    const float* x   = (const float*)d_in[0];
    const float* wq1 = (const float*)d_in[1];
    const float* wq2 = (const float*)d_in[2];
    const float* wk1 = (const float*)d_in[3];
    const float* wk2 = (const float*)d_in[4];
    const float* wv1 = (const float*)d_in[5];
    const float* wv2 = (const float*)d_in[6];
    const float* wo  = (const float*)d_in[7];
    const float* bo  = (const float*)d_in[8];
    float* out = (float*)d_out;

    cudaFuncSetAttribute(attn_kernel, cudaFuncAttributeMaxDynamicSharedMemorySize,
                         ATTN_SMEM);

    pre_kernel<<<234, 256>>>(x, wq1, wk1, wv1, wq2, wk2, wv2, wo);
    proj_mma<<<128, 128>>>();
    attn_kernel<<<dim3(64, 4), 256, ATTN_SMEM>>>();
    out_gemm<<<dim3(64, 4), 128>>>(bo, out);
}

// round 12
// speedup vs baseline: 1.6980x; 1.0197x over previous
#include <cuda_runtime.h>
#include <cuda_fp16.h>
#include <cstdint>

#define NN    1024
#define QSZ   256
#define BOT   40

// ------------------------- scratch (no allocs allowed) -----------------------
__device__ __half g_w1th[(size_t)128 * 256];           // w1^T hi [n][k]
__device__ __half g_w1tl[(size_t)128 * 256];           // w1^T lo
__device__ __half g_ahalf[(size_t)4096 * 40];          // a = x@wq1 (fp16)
__device__ __half g_b[(size_t)4096 * 40];              // b = silu(x@wk1)
__device__ __half g_ct[(size_t)4 * 40 * 1024];         // c^T  [b][40][n]
__device__ __half g_gt[(size_t)64 * 1600];             // G^T per (h,hp)
__device__ __half g_wv2t[(size_t)8 * 64 * 40];         // wv2^T per head [h][d][40]
__device__ __half g_attn16[(size_t)4096 * 512];        // attention out (fp16)
__device__ __half g_woT[(size_t)256 * 512];            // wo^T fp16 [n][k]

__device__ __forceinline__ float ex2f(float x) {
    float y;
    asm("ex2.approx.ftz.f32 %0, %1;" : "=f"(y) : "f"(x));
    return y;
}

__device__ __forceinline__ unsigned ex2h2(float a, float b) {
    __half2 h = __floats2half2_rn(a, b);
    unsigned u = *reinterpret_cast<unsigned*>(&h);
    unsigned r;
    asm("ex2.approx.f16x2 %0, %1;" : "=r"(r) : "r"(u));
    return r;
}

__device__ __forceinline__ unsigned packh2(float a, float b) {
    __half2 h = __floats2half2_rn(a, b);
    return *reinterpret_cast<unsigned*>(&h);
}

__device__ __forceinline__ void mma16816(float (&c)[4], const unsigned (&a)[4],
                                         unsigned b0, unsigned b1) {
    asm volatile(
        "mma.sync.aligned.m16n8k16.row.col.f32.f16.f16.f32 "
        "{%0,%1,%2,%3}, {%4,%5,%6,%7}, {%8,%9}, {%0,%1,%2,%3};\n"
        : "+f"(c[0]), "+f"(c[1]), "+f"(c[2]), "+f"(c[3])
        : "r"(a[0]), "r"(a[1]), "r"(a[2]), "r"(a[3]), "r"(b0), "r"(b1));
}

__device__ __forceinline__ void mma16808(float (&c)[4], unsigned a0, unsigned a1,
                                         unsigned b0) {
    asm volatile(
        "mma.sync.aligned.m16n8k8.row.col.f32.f16.f16.f32 "
        "{%0,%1,%2,%3}, {%4,%5}, {%6}, {%0,%1,%2,%3};\n"
        : "+f"(c[0]), "+f"(c[1]), "+f"(c[2]), "+f"(c[3])
        : "r"(a0), "r"(a1), "r"(b0));
}

__device__ __forceinline__ void cp16(void* s, const void* g) {
    unsigned sa = (unsigned)__cvta_generic_to_shared(s);
    asm volatile("cp.async.cg.shared.global [%0], [%1], 16;\n" :: "r"(sa), "l"(g));
}

__device__ __forceinline__ void ldsm_x4(unsigned& r0, unsigned& r1, unsigned& r2,
                                        unsigned& r3, const void* p) {
    unsigned a = (unsigned)__cvta_generic_to_shared(p);
    asm volatile("ldmatrix.sync.aligned.m8n8.x4.shared.b16 {%0,%1,%2,%3}, [%4];"
                 : "=r"(r0), "=r"(r1), "=r"(r2), "=r"(r3) : "r"(a));
}

// split fp32 -> (hi, lo) packed fragments
__device__ __forceinline__ void split2(float a, float b, unsigned& hi, unsigned& lo) {
    __half h0 = __float2half_rn(a), h1 = __float2half_rn(b);
    __half2 hh = __halves2half2(h0, h1);
    hi = *reinterpret_cast<unsigned*>(&hh);
    __half2 ll = __floats2half2_rn(a - __half2float(h0), b - __half2float(h1));
    lo = *reinterpret_cast<unsigned*>(&ll);
}

// ---------------------------------------------------------------------------
// pre_kernel v4: gmat (0..63) + wv2t transpose (64..71) + wo transpose
// (72..103) + w1t hi/lo (104..105). grid 106.
// ---------------------------------------------------------------------------
__global__ __launch_bounds__(256) void pre_kernel(
    const float* __restrict__ wq1, const float* __restrict__ wk1,
    const float* __restrict__ wv1,
    const float* __restrict__ wq2, const float* __restrict__ wk2,
    const float* __restrict__ wv2, const float* __restrict__ wo) {
    __shared__ float sf[5200];

    const int bx = blockIdx.x;
    const int tid = threadIdx.x;

    if (bx < 64) {
        // ---- gmat ----
        float (*sQ)[65] = reinterpret_cast<float (*)[65]>(sf);
        float (*sK)[65] = reinterpret_cast<float (*)[65]>(sf + 2600);
        const int h = bx >> 3, hp = bx & 7;
        for (int idx = tid; idx < 2560; idx += 256) {
            int k = idx >> 6, d = idx & 63;
            sQ[k][d] = wq2[(size_t)k * 512 + h * 64 + d];
            sK[k][d] = wk2[(size_t)k * 512 + hp * 64 + d];
        }
        __syncthreads();
        const float SCALE = 0.125f * 1.4426950408889634f;
        for (int idx = tid; idx < 1600; idx += 256) {
            int c = idx / 40, k = idx % 40;
            float s = 0.f;
#pragma unroll 8
            for (int d = 0; d < 64; d++) s += sQ[k][d] * sK[c][d];
            g_gt[(size_t)bx * 1600 + c * 40 + k] = __float2half_rn(s * SCALE);
        }
    } else if (bx < 72) {
        // ---- wv2t via smem transpose ----
        float (*sT)[65] = reinterpret_cast<float (*)[65]>(sf);
        const int h = bx - 64;
        for (int idx = tid; idx < 2560; idx += 256) {
            int k = idx >> 6, d = idx & 63;
            sT[k][d] = wv2[(size_t)k * 512 + h * 64 + d];
        }
        __syncthreads();
        for (int idx = tid; idx < 2560; idx += 256) {
            int d = idx / 40, k = idx % 40;
            g_wv2t[(size_t)h * 2560 + idx] = __float2half_rn(sT[k][d]);
        }
    } else if (bx < 104) {
        // ---- wo transpose 64x64 tiles ----
        float (*sT)[65] = reinterpret_cast<float (*)[65]>(sf);
        const int blk = bx - 72;
        const int k0 = (blk & 7) * 64, n0 = (blk >> 3) * 64;
#pragma unroll
        for (int i = 0; i < 16; i++) {
            int idx = i * 256 + tid;
            int r = idx >> 6, c = idx & 63;
            sT[r][c] = wo[(size_t)(k0 + r) * 256 + n0 + c];
        }
        __syncthreads();
#pragma unroll
        for (int i = 0; i < 16; i++) {
            int idx = i * 256 + tid;
            int rn = idx >> 6, ck = idx & 63;
            g_woT[(size_t)(n0 + rn) * 512 + k0 + ck] = __float2half_rn(sT[ck][rn]);
        }
    } else {
        // ---- w1t hi/lo ----
        const int base = (bx - 104) * 15360;
        for (int i = tid; i < 15360; i += 256) {
            int e = base + i;
            int n = e >> 8, k = e & 255;
            int proj = n / 40, c = n % 40;
            const float* w1 = (proj == 0) ? wq1 : (proj == 1 ? wk1 : wv1);
            float v = w1[(size_t)k * 40 + c];
            __half hh = __float2half_rn(v);
            g_w1th[(size_t)n * 256 + k] = hh;
            g_w1tl[(size_t)n * 256 + k] = __float2half_rn(v - __half2float(hh));
        }
    }
}

// ---------------------------------------------------------------------------
// proj_mma v2: x read fp32 directly, split to hi/lo fragments in registers.
// ---------------------------------------------------------------------------
__global__ __launch_bounds__(128) void proj_mma(const float* __restrict__ x) {
    const int tid = threadIdx.x;
    const int w = tid >> 5, lane = tid & 31;
    const int gi = lane >> 2, tig = lane & 3;
    const int row0 = blockIdx.x * 32 + (w & 1) * 16;
    const int n0 = (w >> 1) * 64;

    const float* x0 = x + (size_t)(row0 + gi) * 256;
    const float* x8 = x0 + 8 * 256;

    float acc[8][4];
#pragma unroll
    for (int nt = 0; nt < 8; nt++)
#pragma unroll
        for (int q = 0; q < 4; q++) acc[nt][q] = 0.f;

#pragma unroll
    for (int k = 0; k < 16; k++) {
        const int kc = k * 16 + tig * 2;
        unsigned ah[4], al[4];
        float2 v;
        v = *reinterpret_cast<const float2*>(x0 + kc);     split2(v.x, v.y, ah[0], al[0]);
        v = *reinterpret_cast<const float2*>(x8 + kc);     split2(v.x, v.y, ah[1], al[1]);
        v = *reinterpret_cast<const float2*>(x0 + kc + 8); split2(v.x, v.y, ah[2], al[2]);
        v = *reinterpret_cast<const float2*>(x8 + kc + 8); split2(v.x, v.y, ah[3], al[3]);

#pragma unroll
        for (int nt = 0; nt < 8; nt++) {
            const size_t wrow = (size_t)(n0 + nt * 8 + gi) * 256 + k * 16 + tig * 2;
            unsigned b0h = *reinterpret_cast<const unsigned*>(g_w1th + wrow);
            unsigned b1h = *reinterpret_cast<const unsigned*>(g_w1th + wrow + 8);
            unsigned b0l = *reinterpret_cast<const unsigned*>(g_w1tl + wrow);
            unsigned b1l = *reinterpret_cast<const unsigned*>(g_w1tl + wrow + 8);
            mma16816(acc[nt], ah, b0h, b1h);
            mma16816(acc[nt], al, b0h, b1h);
            mma16816(acc[nt], ah, b0l, b1l);
        }
    }

#pragma unroll
    for (int nt = 0; nt < 8; nt++) {
        const int col = n0 + nt * 8 + tig * 2;
        if (col >= 120) continue;
        const int proj = col / 40, c = col % 40;
#pragma unroll
        for (int half = 0; half < 2; half++) {
            const int r = row0 + gi + half * 8;
            float v0 = acc[nt][2 * half], v1 = acc[nt][2 * half + 1];
            if (proj == 0) {
                *reinterpret_cast<unsigned*>(g_ahalf + (size_t)r * 40 + c) =
                    packh2(v0, v1);
            } else if (proj == 1) {
                v0 = v0 / (1.0f + __expf(-v0));
                v1 = v1 / (1.0f + __expf(-v1));
                *reinterpret_cast<unsigned*>(g_b + (size_t)r * 40 + c) =
                    packh2(v0, v1);
            } else {
                const int bb = r >> 10, n = r & 1023;
                g_ct[((size_t)bb * 40 + c) * 1024 + n]     = __float2half_rn(v0);
                g_ct[((size_t)bb * 40 + c + 1) * 1024 + n] = __float2half_rn(v1);
            }
        }
    }
}

// ---------------------------------------------------------------------------
// Flash attention v5 (byte-identical to R11)
// ---------------------------------------------------------------------------
#define CTS   72
#define CT_BUFSZ (41 * CTS)
#define CT_REGION (4 * CT_BUFSZ + 7 * CTS)
#define WVSZ  2560
#define B_HALVES 40960
#define ATTN_SMEM ((B_HALVES + CT_REGION + WVSZ) * 2)

__global__ __launch_bounds__(256, 2) void attn_kernel() {
    extern __shared__ __half sm[];
    __half* b_s  = sm;
    __half* ct_s = sm + B_HALVES;
    __half* wv_s = sm + B_HALVES + CT_REGION;

    const int b = blockIdx.y;
    const int qt = blockIdx.x;
    const int h = qt >> 3;
    const int n0 = (qt & 7) * 128;
    const int tid = threadIdx.x;
    const int w = tid >> 5, lane = tid & 31;
    const int gi = lane >> 2, tig = lane & 3;
    const int l8 = lane & 7, mrow = lane >> 3;
    const int r8 = (lane >> 3) * 8 + (lane & 7);

    const __half* gb = g_b + (size_t)b * 1024 * 40;
    const __half* gct = g_ct + (size_t)b * 40 * 1024;

    for (int idx = tid; idx < 5120; idx += 256)
        cp16(&b_s[idx * 8], gb + idx * 8);
#pragma unroll
    for (int pf = 0; pf < 2; pf++) {
        __half* dc = ct_s + pf * CT_BUFSZ;
        for (int idx = tid; idx < 320; idx += 256) {
            int row = idx >> 3, seg = idx & 7;
            cp16(&dc[row * CTS + seg * 8], gct + (size_t)row * 1024 + pf * 64 + seg * 8);
        }
    }
    for (int idx = tid; idx < 320; idx += 256)
        cp16(&wv_s[idx * 8], g_wv2t + idx * 8);
    asm volatile("cp.async.commit_group;\n");
    asm volatile("cp.async.wait_group 0;\n");
    if (tid < 128) {
        int bufi = tid >> 5, seg = tid & 31;
        *reinterpret_cast<unsigned*>(&ct_s[bufi * CT_BUFSZ + 40 * CTS + seg * 2]) =
            0x3C003C00u;
    }
    __syncthreads();

    float m[2] = {-1e30f, -1e30f}, l[2] = {0.f, 0.f};
    float O[8][4], T[6][4];
#pragma unroll
    for (int dt = 0; dt < 8; dt++)
#pragma unroll
        for (int q = 0; q < 4; q++) O[dt][q] = 0.f;
#pragma unroll
    for (int n = 0; n < 6; n++)
#pragma unroll
        for (int q = 0; q < 4; q++) T[n][q] = 0.f;

    unsigned qf[2][4], qf8[2];
    const __half* ar0 = g_ahalf + (size_t)(((b << 10) | n0) + w * 16 + gi) * 40;
    const __half* ar1 = ar0 + 8 * 40;

    for (int tt = 0; tt < 128; tt += 2) {
        const int hp = tt >> 4;

        asm volatile("cp.async.wait_group 0;\n");
        __syncthreads();

        if (tt + 2 < 128) {
#pragma unroll
            for (int pf = 0; pf < 2; pf++) {
                int ntile = tt + 2 + pf;
                int key0 = (ntile & 15) * 64;
                __half* dc = ct_s + (ntile & 3) * CT_BUFSZ;
                for (int idx = tid; idx < 320; idx += 256) {
                    int row = idx >> 3, seg = idx & 7;
                    cp16(&dc[row * CTS + seg * 8],
                         gct + (size_t)row * 1024 + key0 + seg * 8);
                }
            }
        }
        if ((tt & 15) == 0 && tt > 0) {
            const __half* gw = g_wv2t + (size_t)hp * 2560;
            for (int idx = tid; idx < 320; idx += 256)
                cp16(&wv_s[idx * 8], gw + idx * 8);
        }
        asm volatile("cp.async.commit_group;\n");

        if ((tt & 15) == 0) {
            unsigned af[2][4], af8[2];
#pragma unroll
            for (int kc = 0; kc < 2; kc++) {
                int cc = kc * 16 + tig * 2;
                af[kc][0] = *reinterpret_cast<const unsigned*>(ar0 + cc);
                af[kc][1] = *reinterpret_cast<const unsigned*>(ar1 + cc);
                af[kc][2] = *reinterpret_cast<const unsigned*>(ar0 + cc + 8);
                af[kc][3] = *reinterpret_cast<const unsigned*>(ar1 + cc + 8);
            }
            af8[0] = *reinterpret_cast<const unsigned*>(ar0 + 32 + tig * 2);
            af8[1] = *reinterpret_cast<const unsigned*>(ar1 + 32 + tig * 2);

            const __half* gg = g_gt + (size_t)(h * 8 + hp) * 1600;
            float tq[5][4];
#pragma unroll
            for (int nt = 0; nt < 5; nt++) {
                const __half* gr = gg + (nt * 8 + gi) * 40 + tig * 2;
                unsigned g0 = *reinterpret_cast<const unsigned*>(gr);
                unsigned g1 = *reinterpret_cast<const unsigned*>(gr + 8);
                unsigned g2 = *reinterpret_cast<const unsigned*>(gr + 16);
                unsigned g3 = *reinterpret_cast<const unsigned*>(gr + 24);
                unsigned g4 = *reinterpret_cast<const unsigned*>(gr + 32);
                tq[nt][0] = tq[nt][1] = tq[nt][2] = tq[nt][3] = 0.f;
                mma16816(tq[nt], af[0], g0, g1);
                mma16816(tq[nt], af[1], g2, g3);
                mma16808(tq[nt], af8[0], af8[1], g4);
            }
#pragma unroll
            for (int kc = 0; kc < 2; kc++) {
                qf[kc][0] = packh2(tq[2 * kc][0],     tq[2 * kc][1]);
                qf[kc][1] = packh2(tq[2 * kc][2],     tq[2 * kc][3]);
                qf[kc][2] = packh2(tq[2 * kc + 1][0], tq[2 * kc + 1][1]);
                qf[kc][3] = packh2(tq[2 * kc + 1][2], tq[2 * kc + 1][3]);
            }
            qf8[0] = packh2(tq[4][0], tq[4][1]);
            qf8[1] = packh2(tq[4][2], tq[4][3]);
        }

#pragma unroll
        for (int sub = 0; sub < 2; sub++) {
            const int tile = tt + sub;
            const int t = tile & 15;
            const __half* ct_t = ct_s + (tile & 3) * CT_BUFSZ;

            unsigned kb8v[8];
            ldsm_x4(kb8v[0], kb8v[1], kb8v[2], kb8v[3],
                    &b_s[(t * 64 + r8) * 40 + 32]);
            ldsm_x4(kb8v[4], kb8v[5], kb8v[6], kb8v[7],
                    &b_s[(t * 64 + 32 + r8) * 40 + 32]);

            float S[8][4];
#pragma unroll
            for (int nt = 0; nt < 8; nt++)
#pragma unroll
                for (int q = 0; q < 4; q++) S[nt][q] = 0.f;

#pragma unroll
            for (int nt = 0; nt < 8; nt++) {
                unsigned kb0[2], kb1[2];
                ldsm_x4(kb0[0], kb1[0], kb0[1], kb1[1],
                        &b_s[(t * 64 + nt * 8 + l8) * 40 + mrow * 8]);
                mma16816(S[nt], qf[0], kb0[0], kb1[0]);
                mma16816(S[nt], qf[1], kb0[1], kb1[1]);
                mma16808(S[nt], qf8[0], qf8[1], kb8v[nt]);
            }

#pragma unroll
            for (int h2 = 0; h2 < 2; h2++) {
                float tm = -1e30f;
#pragma unroll
                for (int nt = 0; nt < 8; nt++)
                    tm = fmaxf(tm, fmaxf(S[nt][2 * h2], S[nt][2 * h2 + 1]));
                tm = fmaxf(tm, __shfl_xor_sync(0xffffffffu, tm, 1));
                tm = fmaxf(tm, __shfl_xor_sync(0xffffffffu, tm, 2));
                if (tm > m[h2]) {
                    float al = ex2f(m[h2] - tm);
                    m[h2] = tm;
                    l[h2] *= al;
#pragma unroll
                    for (int dt = 0; dt < 8; dt++) {
                        O[dt][2 * h2] *= al;
                        O[dt][2 * h2 + 1] *= al;
                    }
#pragma unroll
                    for (int n = 0; n < 6; n++) {
                        T[n][2 * h2] *= al;
                        T[n][2 * h2 + 1] *= al;
                    }
                }
            }

            unsigned pa[4][4];
#pragma unroll
            for (int nt = 0; nt < 8; nt++) {
                unsigned p01 = ex2h2(S[nt][0] - m[0], S[nt][1] - m[0]);
                unsigned p23 = ex2h2(S[nt][2] - m[1], S[nt][3] - m[1]);
                pa[nt >> 1][(nt & 1) * 2]     = p01;
                pa[nt >> 1][(nt & 1) * 2 + 1] = p23;
            }

#pragma unroll
            for (int n = 0; n < 6; n++) {
                unsigned vb0[4], vb1[4];
                const __half* va = &ct_t[(n * 8 + l8) * CTS + mrow * 8];
                ldsm_x4(vb0[0], vb1[0], vb0[1], vb1[1], va);
                ldsm_x4(vb0[2], vb1[2], vb0[3], vb1[3], va + 32);
#pragma unroll
                for (int kc = 0; kc < 4; kc++)
                    mma16816(T[n], pa[kc], vb0[kc], vb1[kc]);
            }

            if (t == 15) {
                unsigned at16[2][4], at8a, at8b;
#pragma unroll
                for (int kc = 0; kc < 2; kc++) {
                    at16[kc][0] = packh2(T[2 * kc][0],     T[2 * kc][1]);
                    at16[kc][1] = packh2(T[2 * kc][2],     T[2 * kc][3]);
                    at16[kc][2] = packh2(T[2 * kc + 1][0], T[2 * kc + 1][1]);
                    at16[kc][3] = packh2(T[2 * kc + 1][2], T[2 * kc + 1][3]);
                }
                at8a = packh2(T[4][0], T[4][1]);
                at8b = packh2(T[4][2], T[4][3]);

                unsigned wb8v[8];
                ldsm_x4(wb8v[0], wb8v[1], wb8v[2], wb8v[3],
                        &wv_s[r8 * 40 + 32]);
                ldsm_x4(wb8v[4], wb8v[5], wb8v[6], wb8v[7],
                        &wv_s[(32 + r8) * 40 + 32]);

#pragma unroll
                for (int dt = 0; dt < 8; dt++) {
                    unsigned wb0[2], wb1[2];
                    ldsm_x4(wb0[0], wb1[0], wb0[1], wb1[1],
                            &wv_s[(dt * 8 + l8) * 40 + mrow * 8]);
                    mma16816(O[dt], at16[0], wb0[0], wb1[0]);
                    mma16816(O[dt], at16[1], wb0[1], wb1[1]);
                    mma16808(O[dt], at8a, at8b, wb8v[dt]);
                }
                if (tig == 0) {
                    l[0] += T[5][0];
                    l[1] += T[5][2];
                }
#pragma unroll
                for (int n = 0; n < 6; n++)
#pragma unroll
                    for (int q = 0; q < 4; q++) T[n][q] = 0.f;
            }
        }
    }

#pragma unroll
    for (int h2 = 0; h2 < 2; h2++) {
        float lt = __shfl_sync(0xffffffffu, l[h2], lane & 28);
        float inv = 1.0f / lt;
        int n = n0 + w * 16 + gi + h2 * 8;
        __half* orow = g_attn16 + ((size_t)((b << 10) | n)) * 512 + h * 64;
#pragma unroll
        for (int dt = 0; dt < 8; dt++) {
            *reinterpret_cast<unsigned*>(orow + dt * 8 + tig * 2) =
                packh2(O[dt][2 * h2] * inv, O[dt][2 * h2 + 1] * inv);
        }
    }
}

// ---------------------------------------------------------------------------
// out_gemm v3: 3-buffer cp.async pipeline, one barrier per k-chunk.
// ---------------------------------------------------------------------------
__global__ __launch_bounds__(128) void out_gemm(
    const float* __restrict__ bo, float* __restrict__ out) {
    __shared__ __half sA2[3][64 * 72];
    __shared__ __half sB2[3][64 * 72];

    const int bm0 = blockIdx.x * 64;
    const int bn0 = blockIdx.y * 64;
    const int tid = threadIdx.x;
    const int w = tid >> 5, lane = tid & 31;
    const int gi = lane >> 2, tig = lane & 3;
    const int l8 = lane & 7, mrow = lane >> 3;

    float acc[8][4];
#pragma unroll
    for (int nt = 0; nt < 8; nt++)
#pragma unroll
        for (int q = 0; q < 4; q++) acc[nt][q] = 0.f;

    const int ar = (lane & 15);
    const int ac = (lane >> 4) * 8;

    // prologue: chunk 0 -> buf 0
#pragma unroll
    for (int i = 0; i < 4; i++) {
        int idx = tid + i * 128;
        int r = idx >> 3, s = idx & 7;
        cp16(&sA2[0][r * 72 + s * 8], g_attn16 + (size_t)(bm0 + r) * 512 + s * 8);
        cp16(&sB2[0][r * 72 + s * 8], g_woT + (size_t)(bn0 + r) * 512 + s * 8);
    }
    asm volatile("cp.async.commit_group;\n");

    for (int kc = 0; kc < 8; kc++) {
        const int buf = kc % 3;
        if (kc + 1 < 8) {
            const int nb = (kc + 1) % 3;
#pragma unroll
            for (int i = 0; i < 4; i++) {
                int idx = tid + i * 128;
                int r = idx >> 3, s = idx & 7;
                cp16(&sA2[nb][r * 72 + s * 8],
                     g_attn16 + (size_t)(bm0 + r) * 512 + (kc + 1) * 64 + s * 8);
                cp16(&sB2[nb][r * 72 + s * 8],
                     g_woT + (size_t)(bn0 + r) * 512 + (kc + 1) * 64 + s * 8);
            }
            asm volatile("cp.async.commit_group;\n");
            asm volatile("cp.async.wait_group 1;\n");
        } else {
            asm volatile("cp.async.wait_group 0;\n");
        }
        __syncthreads();

        const int m0 = w * 16;
#pragma unroll
        for (int ksp = 0; ksp < 2; ksp++) {
            unsigned af0[4], af1[4];
            ldsm_x4(af0[0], af0[1], af0[2], af0[3],
                    &sA2[buf][(m0 + ar) * 72 + ksp * 32 + ac]);
            ldsm_x4(af1[0], af1[1], af1[2], af1[3],
                    &sA2[buf][(m0 + ar) * 72 + ksp * 32 + 16 + ac]);
#pragma unroll
            for (int nt = 0; nt < 8; nt++) {
                unsigned b0a, b1a, b0b, b1b;
                ldsm_x4(b0a, b1a, b0b, b1b,
                        &sB2[buf][(nt * 8 + l8) * 72 + ksp * 32 + mrow * 8]);
                mma16816(acc[nt], af0, b0a, b1a);
                mma16816(acc[nt], af1, b0b, b1b);
            }
        }
    }

    const int r0 = bm0 + w * 16 + gi;
#pragma unroll
    for (int nt = 0; nt < 8; nt++) {
        int col = bn0 + nt * 8 + tig * 2;
        float b0 = bo[col], b1 = bo[col + 1];
        float2 o0 = make_float2(acc[nt][0] + b0, acc[nt][1] + b1);
        float2 o1 = make_float2(acc[nt][2] + b0, acc[nt][3] + b1);
        *reinterpret_cast<float2*>(out + (size_t)r0 * 256 + col) = o0;
        *reinterpret_cast<float2*>(out + (size_t)(r0 + 8) * 256 + col) = o1;
    }
}

// ---------------------------------------------------------------------------
extern "C" void kernel_launch(void* const* d_in, const int* in_sizes, int n_in,
                              void* d_out, int out_size) {
    const float* x   = (const float*)d_in[0];
    const float* wq1 = (const float*)d_in[1];
    const float* wq2 = (const float*)d_in[2];
    const float* wk1 = (const float*)d_in[3];
    const float* wk2 = (const float*)d_in[4];
    const float* wv1 = (const float*)d_in[5];
    const float* wv2 = (const float*)d_in[6];
    const float* wo  = (const float*)d_in[7];
    const float* bo  = (const float*)d_in[8];
    float* out = (float*)d_out;

    cudaFuncSetAttribute(attn_kernel, cudaFuncAttributeMaxDynamicSharedMemorySize,
                         ATTN_SMEM);

    pre_kernel<<<106, 256>>>(wq1, wk1, wv1, wq2, wk2, wv2, wo);
    proj_mma<<<128, 128>>>(x);
    attn_kernel<<<dim3(64, 4), 256, ATTN_SMEM>>>();
    out_gemm<<<dim3(64, 4), 128>>>(bo, out);
}